// round 8
// baseline (speedup 1.0000x reference)
#include <cuda_runtime.h>
#include <cuda_bf16.h>
#include <cstdint>

#define BB 4
#define NTOK 32768
#define CC 256
#define HH 8
#define DD 64
#define GG 64
#define INNER 512
#define TOK (BB*NTOK)   // 131072

// ---------------- scratch (device globals; no runtime allocation) ----------------
__device__ __align__(16) __nv_bfloat16 g_x_hi[(size_t)TOK*CC];   // x split bf16 [tok][c]
__device__ __align__(16) __nv_bfloat16 g_x_lo[(size_t)TOK*CC];
__device__ __align__(16) __nv_bfloat16 g_xT_hi[(size_t)BB*CC*NTOK]; // x^T [b][c][n]
__device__ __align__(16) __nv_bfloat16 g_xT_lo[(size_t)BB*CC*NTOK];
__device__ __align__(16) __nv_bfloat16 g_w_hi[(size_t)TOK*INNER];// slice weights [tok][hg]
__device__ __align__(16) __nv_bfloat16 g_w_lo[(size_t)TOK*INNER];
__device__ __align__(16) __nv_bfloat16 g_wT_hi[(size_t)BB*HH*GG*NTOK]; // w^T [bh][g][n]
__device__ __align__(16) __nv_bfloat16 g_wT_lo[(size_t)BB*HH*GG*NTOK];
__device__ __align__(16) __nv_bfloat16 g_wslT_hi[INNER*CC];      // (Wx@Wslice)^T split
__device__ __align__(16) __nv_bfloat16 g_wslT_lo[INNER*CC];
__device__ float g_bsl[INNER];                    // folded slice bias
__device__ float g_P[BB*HH*GG*CC];                // pooled P[bh][g][c] (atomic accum)
__device__ float g_st[BB*HH*GG*DD];               // slice token sums
__device__ float g_norm[BB*HH*GG];                // weight column sums
__device__ float g_os[BB*HH*GG*DD];               // out_slice
__device__ __align__(16) __nv_bfloat16 g_weffT_hi[BB*CC*INNER];  // W_eff^T [b][n=256][k=512]
__device__ __align__(16) __nv_bfloat16 g_weffT_lo[BB*CC*INNER];

// ============================ helpers ============================
#define DINLINE __device__ __forceinline__

DINLINE uint32_t smem_u32(const void* p) {
    uint32_t a;
    asm("{ .reg .u64 t; cvta.to.shared.u64 t, %1; cvt.u32.u64 %0, t; }" : "=r"(a) : "l"(p));
    return a;
}
DINLINE void cpa16(uint32_t dst, const void* src) {
    asm volatile("cp.async.ca.shared.global [%0], [%1], 16;" :: "r"(dst), "l"(src));
}
#define CP_COMMIT() asm volatile("cp.async.commit_group;" ::: "memory")
#define CP_WAIT1()  asm volatile("cp.async.wait_group 1;" ::: "memory")
#define CP_WAIT0()  asm volatile("cp.async.wait_group 0;" ::: "memory")

DINLINE void ldsm4(uint32_t* r, uint32_t addr) {
    asm volatile("ldmatrix.sync.aligned.m8n8.x4.shared.b16 {%0,%1,%2,%3}, [%4];"
        : "=r"(r[0]), "=r"(r[1]), "=r"(r[2]), "=r"(r[3]) : "r"(addr));
}
DINLINE void mma_bf16(float* d, uint32_t a0, uint32_t a1, uint32_t a2, uint32_t a3,
                      uint32_t b0, uint32_t b1) {
    asm volatile("mma.sync.aligned.m16n8k16.row.col.f32.bf16.bf16.f32 "
        "{%0,%1,%2,%3}, {%4,%5,%6,%7}, {%8,%9}, {%0,%1,%2,%3};"
        : "+f"(d[0]), "+f"(d[1]), "+f"(d[2]), "+f"(d[3])
        : "r"(a0), "r"(a1), "r"(a2), "r"(a3), "r"(b0), "r"(b1));
}
#define SWZ(off) ((off) ^ (((off) >> 3) & 0x70))
#define STG 132        // stage row stride (floats)
#define GSMEM 98304    // 3 stages x (16KB A + 16KB B)
#define PGSMEM 73728   // 3 stages x (8KB A + 16KB B)

// ---------------- zero accumulators (must run every graph replay) ----------------
__global__ void k_zero() {
    int i = blockIdx.x * blockDim.x + threadIdx.x;
    if (i < BB*HH*GG*CC) g_P[i] = 0.f;
    if (i < BB*HH*GG)    g_norm[i] = 0.f;
}

// ---------------- split x into bf16 hi/lo, both [tok][c] and transposed ----------------
__global__ void k_split(const float* __restrict__ x) {
    __shared__ uint16_t shi[64][68], slo[64][68];
    int tid = threadIdx.x;
    size_t t0 = (size_t)blockIdx.x * 64;     // token tile
    int c0 = blockIdx.y * 64;                // c tile
    int r = tid >> 2, cq = (tid & 3) * 16;
    #pragma unroll
    for (int j = 0; j < 16; j += 4) {
        float4 v = *(const float4*)&x[(t0 + r) * CC + c0 + cq + j];
        __nv_bfloat16 hx = __float2bfloat16(v.x), hy = __float2bfloat16(v.y);
        __nv_bfloat16 hz = __float2bfloat16(v.z), hw = __float2bfloat16(v.w);
        __nv_bfloat162 h01(hx, hy), h23(hz, hw);
        __nv_bfloat162 l01 = __floats2bfloat162_rn(v.x - __bfloat162float(hx),
                                                   v.y - __bfloat162float(hy));
        __nv_bfloat162 l23 = __floats2bfloat162_rn(v.z - __bfloat162float(hz),
                                                   v.w - __bfloat162float(hw));
        uint2 uh, ul;
        uh.x = *reinterpret_cast<uint32_t*>(&h01); uh.y = *reinterpret_cast<uint32_t*>(&h23);
        ul.x = *reinterpret_cast<uint32_t*>(&l01); ul.y = *reinterpret_cast<uint32_t*>(&l23);
        *(uint2*)&g_x_hi[(t0 + r) * CC + c0 + cq + j] = uh;
        *(uint2*)&g_x_lo[(t0 + r) * CC + c0 + cq + j] = ul;
        *(uint2*)&shi[r][cq + j] = uh;
        *(uint2*)&slo[r][cq + j] = ul;
    }
    __syncthreads();
    int c = tid >> 2, tq = (tid & 3) * 16;
    size_t b = t0 >> 15;                 // /NTOK
    size_t nloc = t0 & (NTOK - 1);
    size_t base = ((size_t)b * CC + c0 + c) * NTOK + nloc + tq;
    #pragma unroll
    for (int j = 0; j < 16; j += 2) {
        uint32_t hv = (uint32_t)shi[tq + j][c] | ((uint32_t)shi[tq + j + 1][c] << 16);
        uint32_t lv = (uint32_t)slo[tq + j][c] | ((uint32_t)slo[tq + j + 1][c] << 16);
        *(uint32_t*)&g_xT_hi[base + j] = hv;
        *(uint32_t*)&g_xT_lo[base + j] = lv;
    }
}

// ---------------- fold + transpose + bf16-split slice weight ----------------
__global__ void k_prep(const float* __restrict__ Wx, const float* __restrict__ bx,
                       const float* __restrict__ Wsl, const float* __restrict__ bsl) {
    int c = blockIdx.x;        // K index 0..255
    int o = threadIdx.x;       // N index 0..511
    int h = o >> 6, gg = o & 63;
    float s = 0.f;
    #pragma unroll 16
    for (int d = 0; d < 64; d++)
        s += Wx[c*INNER + h*64 + d] * Wsl[d*64 + gg];
    __nv_bfloat16 sh = __float2bfloat16(s);
    g_wslT_hi[o*CC + c] = sh;
    g_wslT_lo[o*CC + c] = __float2bfloat16(s - __bfloat162float(sh));
    if (c == 0) {
        float t = 0.f;
        #pragma unroll 16
        for (int d = 0; d < 64; d++) t += bx[h*64 + d] * Wsl[d*64 + gg];
        g_bsl[o] = t + bsl[gg];
    }
}

// ---------------- slice-logits GEMM + softmax (mma.sync) ----------------
// block M128 x N128, K=256 x 3 segments (12 chunks of 64). grid (4, 1024).
__global__ __launch_bounds__(256, 2) void k_proj(const float* __restrict__ temp) {
    extern __shared__ char sm[];
    float* stage = (float*)sm;
    uint32_t sb = smem_u32(sm);
    int tid = threadIdx.x;
    int lane = tid & 31, w = tid >> 5;
    int wm = w & 1, wn = w >> 1;
    int tileM = blockIdx.y, y2 = blockIdx.x;
    int row0 = tileM * 128;
    int b = tileM >> 8;
    size_t row0loc = (size_t)(tileM & 255) * 128;

    float acc[4][4][4];
    #pragma unroll
    for (int a = 0; a < 4; a++)
        #pragma unroll
        for (int b2 = 0; b2 < 4; b2++)
            #pragma unroll
            for (int d = 0; d < 4; d++) acc[a][b2][d] = 0.f;

    auto issue = [&](int c) {
        int p = c % 3, seg = c >> 2, k0 = (c & 3) * 64;
        const __nv_bfloat16* As = (seg == 2) ? g_x_lo : g_x_hi;
        const __nv_bfloat16* Bs = (seg == 1) ? g_wslT_lo : g_wslT_hi;
        #pragma unroll
        for (int i = 0; i < 4; i++) {
            int id = tid + i * 256, r = id >> 3, c8 = (id & 7) * 8;
            cpa16(sb + p*32768 + SWZ((uint32_t)(r*128 + c8*2)),
                  As + (size_t)(row0 + r) * CC + k0 + c8);
        }
        #pragma unroll
        for (int i = 0; i < 4; i++) {
            int id = tid + i * 256, r = id >> 3, c8 = (id & 7) * 8;
            cpa16(sb + p*32768 + 16384 + SWZ((uint32_t)(r*128 + c8*2)),
                  Bs + (size_t)(y2*128 + r) * CC + k0 + c8);
        }
        CP_COMMIT();
    };

    issue(0); issue(1);
    for (int c = 0; c < 12; c++) {
        if (c + 1 < 12) CP_WAIT1(); else CP_WAIT0();
        __syncthreads();
        uint32_t ab = sb + (c % 3) * 32768;
        uint32_t bb = ab + 16384;
        int rA = lane & 15;
        #pragma unroll
        for (int kk = 0; kk < 4; kk++) {
            uint32_t af[4][4], bf[2][4];
            int kc = kk * 16 + (lane >> 4) * 8;
            #pragma unroll
            for (int mi = 0; mi < 4; mi++)
                ldsm4(af[mi], ab + SWZ((uint32_t)((wm*64 + mi*16 + rA)*128 + kc*2)));
            #pragma unroll
            for (int s = 0; s < 2; s++)
                ldsm4(bf[s], bb + SWZ((uint32_t)((wn*32 + s*16 + rA)*128 + kc*2)));
            #pragma unroll
            for (int mi = 0; mi < 4; mi++)
                #pragma unroll
                for (int nj = 0; nj < 4; nj++)
                    mma_bf16(acc[mi][nj], af[mi][0], af[mi][1], af[mi][2], af[mi][3],
                             bf[nj>>1][nj&1], bf[nj>>1][(nj&1)+2]);
        }
        if (c + 2 < 12) issue(c + 2);
    }
    __syncthreads();

    // frags -> stage
    #pragma unroll
    for (int mi = 0; mi < 4; mi++)
        #pragma unroll
        for (int nj = 0; nj < 4; nj++) {
            int row = wm*64 + mi*16 + (lane >> 2);
            int col = wn*32 + nj*8 + (lane & 3)*2;
            *(float2*)&stage[row*STG + col]     = make_float2(acc[mi][nj][0], acc[mi][nj][1]);
            *(float2*)&stage[(row+8)*STG + col] = make_float2(acc[mi][nj][2], acc[mi][nj][3]);
        }
    __syncthreads();

    // softmax over each head's 64 cols per row
    float rt0 = 1.0f / fminf(fmaxf(temp[y2*2 + 0], 0.1f), 5.0f);
    float rt1 = 1.0f / fminf(fmaxf(temp[y2*2 + 1], 0.1f), 5.0f);
    for (int gi = 0; gi < 32; gi++) {
        int G = w * 32 + gi;
        int r = G >> 1, hh = G & 1;
        float bb0 = g_bsl[y2*128 + hh*64 + lane];
        float bb1 = g_bsl[y2*128 + hh*64 + 32 + lane];
        float rt = hh ? rt1 : rt0;
        float v0 = (stage[r*STG + hh*64 + lane]      + bb0) * rt;
        float v1 = (stage[r*STG + hh*64 + 32 + lane] + bb1) * rt;
        float m = fmaxf(v0, v1);
        #pragma unroll
        for (int o = 16; o; o >>= 1) m = fmaxf(m, __shfl_xor_sync(0xFFFFFFFFu, m, o));
        float e0 = __expf(v0 - m), e1 = __expf(v1 - m);
        float s = e0 + e1;
        #pragma unroll
        for (int o = 16; o; o >>= 1) s += __shfl_xor_sync(0xFFFFFFFFu, s, o);
        float rs = 1.0f / s;
        stage[r*STG + hh*64 + lane]      = e0 * rs;
        stage[r*STG + hh*64 + 32 + lane] = e1 * rs;
    }
    __syncthreads();

    // (a) norm: column sums -> atomic
    if (tid < 128) {
        float s = 0.f;
        #pragma unroll 8
        for (int r = 0; r < 128; r++) s += stage[r*STG + tid];
        int head = tid >> 6, g = tid & 63;
        atomicAdd(&g_norm[(b*8 + y2*2 + head)*64 + g], s);
    }
    // (b) w pair [tok][hg]  (coalesced 8B chunks)
    #pragma unroll
    for (int i = 0; i < 16; i++) {
        int lin = tid + i * 256, r = lin >> 5, c4 = (lin & 31) * 4;
        float4 v = *(float4*)&stage[r*STG + c4];
        __nv_bfloat16 hx = __float2bfloat16(v.x), hy = __float2bfloat16(v.y);
        __nv_bfloat16 hz = __float2bfloat16(v.z), hw = __float2bfloat16(v.w);
        __nv_bfloat162 h01(hx, hy), h23(hz, hw);
        __nv_bfloat162 l01 = __floats2bfloat162_rn(v.x - __bfloat162float(hx),
                                                   v.y - __bfloat162float(hy));
        __nv_bfloat162 l23 = __floats2bfloat162_rn(v.z - __bfloat162float(hz),
                                                   v.w - __bfloat162float(hw));
        uint2 uh, ul;
        uh.x = *reinterpret_cast<uint32_t*>(&h01); uh.y = *reinterpret_cast<uint32_t*>(&h23);
        ul.x = *reinterpret_cast<uint32_t*>(&l01); ul.y = *reinterpret_cast<uint32_t*>(&l23);
        size_t idx = (size_t)(row0 + r)*INNER + y2*128 + c4;
        *(uint2*)&g_w_hi[idx] = uh;
        *(uint2*)&g_w_lo[idx] = ul;
    }
    // (c) w^T pair [bh][g][n] — COALESCED: thread owns (head,g) row-half,
    //     writes 128B contiguous hi + 128B lo.
    {
        int G2 = tid >> 1, half = tid & 1;
        int head = G2 >> 6, g = G2 & 63;
        size_t basew = ((size_t)(b*8 + y2*2 + head) * 64 + g) * (size_t)NTOK
                       + row0loc + half * 64;
        #pragma unroll
        for (int t = 0; t < 64; t += 2) {
            float v0 = stage[(half*64 + t)     * STG + G2];
            float v1 = stage[(half*64 + t + 1) * STG + G2];
            __nv_bfloat16 h0 = __float2bfloat16(v0), h1 = __float2bfloat16(v1);
            uint32_t hw2 = (uint32_t)*(uint16_t*)&h0 | ((uint32_t)*(uint16_t*)&h1 << 16);
            __nv_bfloat16 l0 = __float2bfloat16(v0 - __bfloat162float(h0));
            __nv_bfloat16 l1 = __float2bfloat16(v1 - __bfloat162float(h1));
            uint32_t lw2 = (uint32_t)*(uint16_t*)&l0 | ((uint32_t)*(uint16_t*)&l1 << 16);
            *(uint32_t*)&g_wT_hi[basew + t] = hw2;
            *(uint32_t*)&g_wT_lo[basew + t] = lw2;
        }
    }
}

// ---------------- pooling GEMM: P[bh][g][c] = sum_n w[n,g]*x[n,c] ----------------
// block M64(g) x N128(c), grid (32 bh, 8 kc, 2 cb). 192 chunks of 64 k (3 segs x 64).
__global__ __launch_bounds__(256, 2) void k_poolg() {
    extern __shared__ char sm[];
    uint32_t sb = smem_u32(sm);
    int tid = threadIdx.x;
    int lane = tid & 31, w = tid >> 5;
    int wm = w & 1, wn = w >> 1;
    int bh = blockIdx.x, kc = blockIdx.y, cb = blockIdx.z;
    int b = bh >> 3;
    size_t nbase = (size_t)kc * 4096;
    const __nv_bfloat16* Ahi = g_wT_hi + (size_t)bh * 64 * NTOK;
    const __nv_bfloat16* Alo = g_wT_lo + (size_t)bh * 64 * NTOK;
    const __nv_bfloat16* Bhi = g_xT_hi + ((size_t)b * CC + cb * 128) * NTOK;
    const __nv_bfloat16* Blo = g_xT_lo + ((size_t)b * CC + cb * 128) * NTOK;

    float acc[2][4][4];
    #pragma unroll
    for (int a = 0; a < 2; a++)
        #pragma unroll
        for (int b2 = 0; b2 < 4; b2++)
            #pragma unroll
            for (int d = 0; d < 4; d++) acc[a][b2][d] = 0.f;

    auto issue = [&](int c) {
        int p = c % 3, seg = c >> 6, k0 = (c & 63) * 64;
        const __nv_bfloat16* As = (seg == 2) ? Alo : Ahi;
        const __nv_bfloat16* Bs = (seg == 1) ? Blo : Bhi;
        #pragma unroll
        for (int i = 0; i < 2; i++) {
            int id = tid + i * 256, r = id >> 3, c8 = (id & 7) * 8;
            cpa16(sb + p*24576 + SWZ((uint32_t)(r*128 + c8*2)),
                  As + (size_t)r * NTOK + nbase + k0 + c8);
        }
        #pragma unroll
        for (int i = 0; i < 4; i++) {
            int id = tid + i * 256, r = id >> 3, c8 = (id & 7) * 8;
            cpa16(sb + p*24576 + 8192 + SWZ((uint32_t)(r*128 + c8*2)),
                  Bs + (size_t)r * NTOK + nbase + k0 + c8);
        }
        CP_COMMIT();
    };

    issue(0); issue(1);
    for (int c = 0; c < 192; c++) {
        if (c + 1 < 192) CP_WAIT1(); else CP_WAIT0();
        __syncthreads();
        uint32_t ab = sb + (c % 3) * 24576;
        uint32_t bb = ab + 8192;
        int rA = lane & 15;
        #pragma unroll
        for (int kk = 0; kk < 4; kk++) {
            uint32_t af[2][4], bf[2][4];
            int kc2 = kk * 16 + (lane >> 4) * 8;
            #pragma unroll
            for (int mi = 0; mi < 2; mi++)
                ldsm4(af[mi], ab + SWZ((uint32_t)((wm*32 + mi*16 + rA)*128 + kc2*2)));
            #pragma unroll
            for (int s = 0; s < 2; s++)
                ldsm4(bf[s], bb + SWZ((uint32_t)((wn*32 + s*16 + rA)*128 + kc2*2)));
            #pragma unroll
            for (int mi = 0; mi < 2; mi++)
                #pragma unroll
                for (int nj = 0; nj < 4; nj++)
                    mma_bf16(acc[mi][nj], af[mi][0], af[mi][1], af[mi][2], af[mi][3],
                             bf[nj>>1][nj&1], bf[nj>>1][(nj&1)+2]);
        }
        if (c + 2 < 192) issue(c + 2);
    }

    #pragma unroll
    for (int mi = 0; mi < 2; mi++)
        #pragma unroll
        for (int nj = 0; nj < 4; nj++) {
            int row = wm*32 + mi*16 + (lane >> 2);
            int col = cb*128 + wn*32 + nj*8 + (lane & 3)*2;
            int base = bh*16384 + row*256 + col;
            atomicAdd(&g_P[base],            acc[mi][nj][0]);
            atomicAdd(&g_P[base + 1],        acc[mi][nj][1]);
            atomicAdd(&g_P[base + 8*256],    acc[mi][nj][2]);
            atomicAdd(&g_P[base + 8*256 + 1],acc[mi][nj][3]);
        }
}

// ---------------- fold: ST[bh][g][d] = P@Wfx + bfx*norm ----------------
__global__ void k_stok(const float* __restrict__ Wfx, const float* __restrict__ bfx) {
    int bh = blockIdx.x;
    int h = bh & 7;
    int tid = threadIdx.x;
    __shared__ float wf[64][65], pp[64][65];
    float acc[16];
    #pragma unroll
    for (int j = 0; j < 16; j++) acc[j] = 0.f;
    int g = tid >> 2, dq = tid & 3;
    for (int c0 = 0; c0 < 4; c0++) {
        #pragma unroll
        for (int i = 0; i < 16; i++) {
            int id = tid + i * 256;
            int r = id >> 6, cl = id & 63;
            wf[r][cl] = Wfx[(c0*64 + r) * INNER + h*64 + cl];
            pp[r][cl] = g_P[bh*16384 + r*256 + c0*64 + cl];
        }
        __syncthreads();
        for (int cl = 0; cl < 64; cl++) {
            float pv = pp[g][cl];
            #pragma unroll
            for (int j = 0; j < 16; j++)
                acc[j] += pv * wf[cl][dq*16 + j];
        }
        __syncthreads();
    }
    float nrm = g_norm[bh*64 + g];
    #pragma unroll
    for (int j = 0; j < 16; j++) {
        int d = dq*16 + j;
        g_st[bh*4096 + g*64 + d] = acc[j] + bfx[h*64 + d] * nrm;
    }
}

// ---------------- tiny attention over slice tokens ----------------
__global__ void k_attn(const float* __restrict__ Wq, const float* __restrict__ Wk,
                       const float* __restrict__ Wv) {
    int bh = blockIdx.x;
    int tid = threadIdx.x;
    __shared__ float sn[64][64];
    __shared__ float ks[64][64];
    __shared__ float nrm[64];
    if (tid < 64) nrm[tid] = g_norm[bh * 64 + tid] + 1e-5f;
    __syncthreads();
    #pragma unroll
    for (int it = 0; it < 16; it++) {
        int idx = tid + it * 256;
        int g2 = idx >> 6;
        sn[g2][idx & 63] = g_st[bh * 4096 + idx] / nrm[g2];
    }
    __syncthreads();
    #pragma unroll
    for (int it = 0; it < 16; it++) {
        int idx = tid + it * 256;
        int g2 = idx >> 6, d2 = idx & 63;
        float s0 = 0, s1 = 0, s2 = 0, s3 = 0;
        #pragma unroll
        for (int d = 0; d < 64; d += 4) {
            s0 += sn[g2][d]   * Wk[(d)   * 64 + d2];
            s1 += sn[g2][d+1] * Wk[(d+1) * 64 + d2];
            s2 += sn[g2][d+2] * Wk[(d+2) * 64 + d2];
            s3 += sn[g2][d+3] * Wk[(d+3) * 64 + d2];
        }
        ks[g2][d2] = (s0 + s1) + (s2 + s3);
    }
    __syncthreads();
    float tv[64];
    if (tid < 64) {
        int g2 = tid;
        float q[64];
        #pragma unroll
        for (int d2 = 0; d2 < 64; d2++) {
            float s0 = 0, s1 = 0, s2 = 0, s3 = 0;
            #pragma unroll
            for (int d = 0; d < 64; d += 4) {
                s0 += sn[g2][d]   * Wq[(d)   * 64 + d2];
                s1 += sn[g2][d+1] * Wq[(d+1) * 64 + d2];
                s2 += sn[g2][d+2] * Wq[(d+2) * 64 + d2];
                s3 += sn[g2][d+3] * Wq[(d+3) * 64 + d2];
            }
            q[d2] = (s0 + s1) + (s2 + s3);
        }
        float p[64];
        float mx = -1e30f;
        #pragma unroll
        for (int j = 0; j < 64; j++) {
            float s0 = 0, s1 = 0, s2 = 0, s3 = 0;
            #pragma unroll
            for (int d = 0; d < 64; d += 4) {
                s0 += q[d]   * ks[j][d];
                s1 += q[d+1] * ks[j][d+1];
                s2 += q[d+2] * ks[j][d+2];
                s3 += q[d+3] * ks[j][d+3];
            }
            float s = ((s0 + s1) + (s2 + s3)) * 0.125f;
            p[j] = s;
            mx = fmaxf(mx, s);
        }
        float sum = 0.f;
        #pragma unroll
        for (int j = 0; j < 64; j++) { p[j] = __expf(p[j] - mx); sum += p[j]; }
        float rs = 1.0f / sum;
        #pragma unroll
        for (int e = 0; e < 64; e++) {
            float s0 = 0, s1 = 0, s2 = 0, s3 = 0;
            #pragma unroll
            for (int j = 0; j < 64; j += 4) {
                s0 += p[j]   * sn[j][e];
                s1 += p[j+1] * sn[j+1][e];
                s2 += p[j+2] * sn[j+2][e];
                s3 += p[j+3] * sn[j+3][e];
            }
            tv[e] = ((s0 + s1) + (s2 + s3)) * rs;
        }
    }
    __syncthreads();
    if (tid < 64) {
        #pragma unroll
        for (int e = 0; e < 64; e++) ks[tid][e] = tv[e];
    }
    __syncthreads();
    #pragma unroll
    for (int it = 0; it < 16; it++) {
        int idx = tid + it * 256;
        int g2 = idx >> 6, d2 = idx & 63;
        float s0 = 0, s1 = 0, s2 = 0, s3 = 0;
        #pragma unroll
        for (int e = 0; e < 64; e += 4) {
            s0 += ks[g2][e]   * Wv[(e)   * 64 + d2];
            s1 += ks[g2][e+1] * Wv[(e+1) * 64 + d2];
            s2 += ks[g2][e+2] * Wv[(e+2) * 64 + d2];
            s3 += ks[g2][e+3] * Wv[(e+3) * 64 + d2];
        }
        g_os[bh * 4096 + idx] = (s0 + s1) + (s2 + s3);
    }
}

// ---------------- fold out_slice into W_out: W_eff^T pair [b][n=256][k=512] ----------------
__global__ void k_weff(const float* __restrict__ Wout) {
    int blk = blockIdx.x;           // b*512 + row
    int b = blk >> 9;
    int row = blk & 511;            // k index: h*64+g
    int h = row >> 6;
    int tid = threadIdx.x;          // n index = c (256)
    __shared__ float osr[64];
    if (tid < 64) osr[tid] = g_os[(b*8 + h) * 4096 + (row & 63) * 64 + tid];
    __syncthreads();
    float s = 0.f;
    #pragma unroll 16
    for (int d = 0; d < 64; d++)
        s += osr[d] * Wout[(h*64 + d) * CC + tid];
    __nv_bfloat16 sh = __float2bfloat16(s);
    size_t idx = (size_t)b * (CC*INNER) + (size_t)tid * INNER + row;
    g_weffT_hi[idx] = sh;
    g_weffT_lo[idx] = __float2bfloat16(s - __bfloat162float(sh));
}

// ---------------- output GEMM (mma.sync): y = w @ W_eff[b] + b_out ----------------
// block M128 x N128, K=512 x 3 segments (24 chunks). grid (2, 1024): ct fast-varying.
__global__ __launch_bounds__(256, 2) void k_out(const float* __restrict__ bout,
                                                float* __restrict__ y) {
    extern __shared__ char sm[];
    float* stage = (float*)sm;
    uint32_t sb = smem_u32(sm);
    int tid = threadIdx.x;
    int lane = tid & 31, w = tid >> 5;
    int wm = w & 1, wn = w >> 1;
    int tileM = blockIdx.y, ct = blockIdx.x;
    int row0 = tileM * 128;
    int b = tileM >> 8;

    float acc[4][4][4];
    #pragma unroll
    for (int a = 0; a < 4; a++)
        #pragma unroll
        for (int bb2 = 0; bb2 < 4; bb2++)
            #pragma unroll
            for (int d = 0; d < 4; d++) acc[a][bb2][d] = 0.f;

    auto issue = [&](int c) {
        int p = c % 3, seg = c >> 3, k0 = (c & 7) * 64;
        const __nv_bfloat16* As = (seg == 2) ? g_w_lo : g_w_hi;
        const __nv_bfloat16* Bs = (seg == 1) ? g_weffT_lo : g_weffT_hi;
        #pragma unroll
        for (int i = 0; i < 4; i++) {
            int id = tid + i * 256, r = id >> 3, c8 = (id & 7) * 8;
            cpa16(sb + p*32768 + SWZ((uint32_t)(r*128 + c8*2)),
                  As + (size_t)(row0 + r) * INNER + k0 + c8);
        }
        #pragma unroll
        for (int i = 0; i < 4; i++) {
            int id = tid + i * 256, r = id >> 3, c8 = (id & 7) * 8;
            cpa16(sb + p*32768 + 16384 + SWZ((uint32_t)(r*128 + c8*2)),
                  Bs + (size_t)b * (CC*INNER) + (size_t)(ct*128 + r) * INNER + k0 + c8);
        }
        CP_COMMIT();
    };

    issue(0); issue(1);
    for (int c = 0; c < 24; c++) {
        if (c + 1 < 24) CP_WAIT1(); else CP_WAIT0();
        __syncthreads();
        uint32_t ab = sb + (c % 3) * 32768;
        uint32_t bbs = ab + 16384;
        int rA = lane & 15;
        #pragma unroll
        for (int kk = 0; kk < 4; kk++) {
            uint32_t af[4][4], bf[2][4];
            int kc = kk * 16 + (lane >> 4) * 8;
            #pragma unroll
            for (int mi = 0; mi < 4; mi++)
                ldsm4(af[mi], ab + SWZ((uint32_t)((wm*64 + mi*16 + rA)*128 + kc*2)));
            #pragma unroll
            for (int s = 0; s < 2; s++)
                ldsm4(bf[s], bbs + SWZ((uint32_t)((wn*32 + s*16 + rA)*128 + kc*2)));
            #pragma unroll
            for (int mi = 0; mi < 4; mi++)
                #pragma unroll
                for (int nj = 0; nj < 4; nj++)
                    mma_bf16(acc[mi][nj], af[mi][0], af[mi][1], af[mi][2], af[mi][3],
                             bf[nj>>1][nj&1], bf[nj>>1][(nj&1)+2]);
        }
        if (c + 2 < 24) issue(c + 2);
    }
    __syncthreads();

    #pragma unroll
    for (int mi = 0; mi < 4; mi++)
        #pragma unroll
        for (int nj = 0; nj < 4; nj++) {
            int row = wm*64 + mi*16 + (lane >> 2);
            int col = wn*32 + nj*8 + (lane & 3)*2;
            *(float2*)&stage[row*STG + col]     = make_float2(acc[mi][nj][0], acc[mi][nj][1]);
            *(float2*)&stage[(row+8)*STG + col] = make_float2(acc[mi][nj][2], acc[mi][nj][3]);
        }
    __syncthreads();
    #pragma unroll
    for (int i = 0; i < 16; i++) {
        int lin = tid + i * 256, r = lin >> 5, c4 = (lin & 31) * 4;
        float4 v = *(float4*)&stage[r*STG + c4];
        float4 bv = *(const float4*)&bout[ct*128 + c4];
        v.x += bv.x; v.y += bv.y; v.z += bv.z; v.w += bv.w;
        *(float4*)&y[(size_t)(row0 + r)*CC + ct*128 + c4] = v;
    }
}

// ---------------- launch ----------------
extern "C" void kernel_launch(void* const* d_in, const int* in_sizes, int n_in,
                              void* d_out, int out_size) {
    const float* x    = (const float*)d_in[0];
    const float* Wfx  = (const float*)d_in[1];
    const float* bfx  = (const float*)d_in[2];
    const float* Wx   = (const float*)d_in[3];
    const float* bx   = (const float*)d_in[4];
    const float* Wsl  = (const float*)d_in[5];
    const float* bsl  = (const float*)d_in[6];
    const float* temp = (const float*)d_in[7];
    const float* Wq   = (const float*)d_in[8];
    const float* Wk   = (const float*)d_in[9];
    const float* Wv   = (const float*)d_in[10];
    const float* Wout = (const float*)d_in[11];
    const float* bout = (const float*)d_in[12];
    float* y = (float*)d_out;

    cudaFuncSetAttribute(k_proj,  cudaFuncAttributeMaxDynamicSharedMemorySize, GSMEM);
    cudaFuncSetAttribute(k_poolg, cudaFuncAttributeMaxDynamicSharedMemorySize, PGSMEM);
    cudaFuncSetAttribute(k_out,   cudaFuncAttributeMaxDynamicSharedMemorySize, GSMEM);

    k_zero<<<2048, 256>>>();
    k_prep<<<CC, 512>>>(Wx, bx, Wsl, bsl);
    k_split<<<dim3(TOK/64, 4), 256>>>(x);
    k_proj<<<dim3(4, TOK/128), 256, GSMEM>>>(temp);
    k_poolg<<<dim3(32, 8, 2), 256, PGSMEM>>>();
    k_stok<<<32, 256>>>(Wfx, bfx);
    k_attn<<<32, 256>>>(Wq, Wk, Wv);
    k_weff<<<2048, 256>>>(Wout);
    k_out<<<dim3(2, TOK/128), 256, GSMEM>>>(bout, y);
}

// round 9
// speedup vs baseline: 1.0989x; 1.0989x over previous
#include <cuda_runtime.h>
#include <cuda_bf16.h>
#include <cstdint>

#define BB 4
#define NTOK 32768
#define CC 256
#define HH 8
#define DD 64
#define GG 64
#define INNER 512
#define TOK (BB*NTOK)   // 131072

// ---------------- scratch (device globals; no runtime allocation) ----------------
__device__ __align__(16) __nv_bfloat16 g_x_hi[(size_t)TOK*CC];   // x split bf16 [tok][c]
__device__ __align__(16) __nv_bfloat16 g_x_lo[(size_t)TOK*CC];
__device__ __align__(16) __nv_bfloat16 g_xT_hi[(size_t)BB*CC*NTOK]; // x^T [b][c][n]
__device__ __align__(16) __nv_bfloat16 g_xT_lo[(size_t)BB*CC*NTOK];
__device__ __align__(16) __nv_bfloat16 g_w_hi[(size_t)TOK*INNER];// slice weights [tok][hg]
__device__ __align__(16) __nv_bfloat16 g_w_lo[(size_t)TOK*INNER];
__device__ __align__(16) __nv_bfloat16 g_wT_hi[(size_t)BB*HH*GG*NTOK]; // w^T [bh][g][n]
__device__ __align__(16) __nv_bfloat16 g_wT_lo[(size_t)BB*HH*GG*NTOK];
__device__ __align__(16) __nv_bfloat16 g_wslT_hi[INNER*CC];      // (Wx@Wslice)^T split
__device__ __align__(16) __nv_bfloat16 g_wslT_lo[INNER*CC];
__device__ float g_bsl[INNER];                    // folded slice bias
__device__ float g_P[BB*HH*GG*CC];                // pooled P[bh][g][c] (atomic accum)
__device__ float g_norm[BB*HH*GG];                // weight column sums
__device__ float g_os[BB*HH*GG*DD];               // out_slice
__device__ __align__(16) __nv_bfloat16 g_weffT_hi[BB*CC*INNER];  // W_eff^T [b][n=256][k=512]
__device__ __align__(16) __nv_bfloat16 g_weffT_lo[BB*CC*INNER];

// ============================ helpers ============================
#define DINLINE __device__ __forceinline__

DINLINE uint32_t smem_u32(const void* p) {
    uint32_t a;
    asm("{ .reg .u64 t; cvta.to.shared.u64 t, %1; cvt.u32.u64 %0, t; }" : "=r"(a) : "l"(p));
    return a;
}
DINLINE void cpa16(uint32_t dst, const void* src) {
    asm volatile("cp.async.cg.shared.global [%0], [%1], 16;" :: "r"(dst), "l"(src));
}
#define CP_COMMIT() asm volatile("cp.async.commit_group;" ::: "memory")
#define CP_WAIT2()  asm volatile("cp.async.wait_group 2;" ::: "memory")
#define CP_WAIT1()  asm volatile("cp.async.wait_group 1;" ::: "memory")
#define CP_WAIT0()  asm volatile("cp.async.wait_group 0;" ::: "memory")

DINLINE void ldsm4(uint32_t* r, uint32_t addr) {
    asm volatile("ldmatrix.sync.aligned.m8n8.x4.shared.b16 {%0,%1,%2,%3}, [%4];"
        : "=r"(r[0]), "=r"(r[1]), "=r"(r[2]), "=r"(r[3]) : "r"(addr));
}
DINLINE void mma_bf16(float* d, uint32_t a0, uint32_t a1, uint32_t a2, uint32_t a3,
                      uint32_t b0, uint32_t b1) {
    asm volatile("mma.sync.aligned.m16n8k16.row.col.f32.bf16.bf16.f32 "
        "{%0,%1,%2,%3}, {%4,%5,%6,%7}, {%8,%9}, {%0,%1,%2,%3};"
        : "+f"(d[0]), "+f"(d[1]), "+f"(d[2]), "+f"(d[3])
        : "r"(a0), "r"(a1), "r"(a2), "r"(a3), "r"(b0), "r"(b1));
}
#define SWZ(off) ((off) ^ (((off) >> 3) & 0x70))
#define STG 132        // stage row stride (floats)
#define GSMEM 98304    // 3 stages x (16KB A + 16KB B)
#define PGSMEM 98304   // 4 stages x (8KB A + 16KB B)

// ---------------- zero accumulators (must run every graph replay) ----------------
__global__ void k_zero() {
    int i = blockIdx.x * blockDim.x + threadIdx.x;
    if (i < BB*HH*GG*CC) g_P[i] = 0.f;
    if (i < BB*HH*GG)    g_norm[i] = 0.f;
}

// ---------------- split x into bf16 hi/lo, both [tok][c] and transposed ----------------
__global__ void k_split(const float* __restrict__ x) {
    __shared__ uint16_t shi[64][68], slo[64][68];
    int tid = threadIdx.x;
    size_t t0 = (size_t)blockIdx.x * 64;     // token tile
    int c0 = blockIdx.y * 64;                // c tile
    int r = tid >> 2, cq = (tid & 3) * 16;
    #pragma unroll
    for (int j = 0; j < 16; j += 4) {
        float4 v = *(const float4*)&x[(t0 + r) * CC + c0 + cq + j];
        __nv_bfloat16 hx = __float2bfloat16(v.x), hy = __float2bfloat16(v.y);
        __nv_bfloat16 hz = __float2bfloat16(v.z), hw = __float2bfloat16(v.w);
        __nv_bfloat162 h01(hx, hy), h23(hz, hw);
        __nv_bfloat162 l01 = __floats2bfloat162_rn(v.x - __bfloat162float(hx),
                                                   v.y - __bfloat162float(hy));
        __nv_bfloat162 l23 = __floats2bfloat162_rn(v.z - __bfloat162float(hz),
                                                   v.w - __bfloat162float(hw));
        uint2 uh, ul;
        uh.x = *reinterpret_cast<uint32_t*>(&h01); uh.y = *reinterpret_cast<uint32_t*>(&h23);
        ul.x = *reinterpret_cast<uint32_t*>(&l01); ul.y = *reinterpret_cast<uint32_t*>(&l23);
        *(uint2*)&g_x_hi[(t0 + r) * CC + c0 + cq + j] = uh;
        *(uint2*)&g_x_lo[(t0 + r) * CC + c0 + cq + j] = ul;
        *(uint2*)&shi[r][cq + j] = uh;
        *(uint2*)&slo[r][cq + j] = ul;
    }
    __syncthreads();
    int c = tid >> 2, tq = (tid & 3) * 16;
    size_t b = t0 >> 15;                 // /NTOK
    size_t nloc = t0 & (NTOK - 1);
    size_t base = ((size_t)b * CC + c0 + c) * NTOK + nloc + tq;
    #pragma unroll
    for (int j = 0; j < 16; j += 2) {
        uint32_t hv = (uint32_t)shi[tq + j][c] | ((uint32_t)shi[tq + j + 1][c] << 16);
        uint32_t lv = (uint32_t)slo[tq + j][c] | ((uint32_t)slo[tq + j + 1][c] << 16);
        *(uint32_t*)&g_xT_hi[base + j] = hv;
        *(uint32_t*)&g_xT_lo[base + j] = lv;
    }
}

// ---------------- fold + transpose + bf16-split slice weight ----------------
__global__ void k_prep(const float* __restrict__ Wx, const float* __restrict__ bx,
                       const float* __restrict__ Wsl, const float* __restrict__ bsl) {
    int c = blockIdx.x;        // K index 0..255
    int o = threadIdx.x;       // N index 0..511
    int h = o >> 6, gg = o & 63;
    float s = 0.f;
    #pragma unroll 16
    for (int d = 0; d < 64; d++)
        s += Wx[c*INNER + h*64 + d] * Wsl[d*64 + gg];
    __nv_bfloat16 sh = __float2bfloat16(s);
    g_wslT_hi[o*CC + c] = sh;
    g_wslT_lo[o*CC + c] = __float2bfloat16(s - __bfloat162float(sh));
    if (c == 0) {
        float t = 0.f;
        #pragma unroll 16
        for (int d = 0; d < 64; d++) t += bx[h*64 + d] * Wsl[d*64 + gg];
        g_bsl[o] = t + bsl[gg];
    }
}

// ---------------- slice-logits GEMM + softmax (mma.sync) ----------------
// block M128 x N128, K=256 x 3 segments (12 chunks of 64). grid (4, 1024).
__global__ __launch_bounds__(256, 2) void k_proj(const float* __restrict__ temp) {
    extern __shared__ char sm[];
    float* stage = (float*)sm;
    uint32_t sb = smem_u32(sm);
    int tid = threadIdx.x;
    int lane = tid & 31, w = tid >> 5;
    int wm = w & 1, wn = w >> 1;
    int tileM = blockIdx.y, y2 = blockIdx.x;
    int row0 = tileM * 128;
    int b = tileM >> 8;
    size_t row0loc = (size_t)(tileM & 255) * 128;

    float acc[4][4][4];
    #pragma unroll
    for (int a = 0; a < 4; a++)
        #pragma unroll
        for (int b2 = 0; b2 < 4; b2++)
            #pragma unroll
            for (int d = 0; d < 4; d++) acc[a][b2][d] = 0.f;

    auto issue = [&](int c) {
        int p = c % 3, seg = c >> 2, k0 = (c & 3) * 64;
        const __nv_bfloat16* As = (seg == 2) ? g_x_lo : g_x_hi;
        const __nv_bfloat16* Bs = (seg == 1) ? g_wslT_lo : g_wslT_hi;
        #pragma unroll
        for (int i = 0; i < 4; i++) {
            int id = tid + i * 256, r = id >> 3, c8 = (id & 7) * 8;
            cpa16(sb + p*32768 + SWZ((uint32_t)(r*128 + c8*2)),
                  As + (size_t)(row0 + r) * CC + k0 + c8);
        }
        #pragma unroll
        for (int i = 0; i < 4; i++) {
            int id = tid + i * 256, r = id >> 3, c8 = (id & 7) * 8;
            cpa16(sb + p*32768 + 16384 + SWZ((uint32_t)(r*128 + c8*2)),
                  Bs + (size_t)(y2*128 + r) * CC + k0 + c8);
        }
        CP_COMMIT();
    };

    issue(0); issue(1);
    for (int c = 0; c < 12; c++) {
        if (c + 1 < 12) CP_WAIT1(); else CP_WAIT0();
        __syncthreads();
        uint32_t ab = sb + (c % 3) * 32768;
        uint32_t bb = ab + 16384;
        int rA = lane & 15;
        #pragma unroll
        for (int kk = 0; kk < 4; kk++) {
            uint32_t af[4][4], bf[2][4];
            int kc = kk * 16 + (lane >> 4) * 8;
            #pragma unroll
            for (int mi = 0; mi < 4; mi++)
                ldsm4(af[mi], ab + SWZ((uint32_t)((wm*64 + mi*16 + rA)*128 + kc*2)));
            #pragma unroll
            for (int s = 0; s < 2; s++)
                ldsm4(bf[s], bb + SWZ((uint32_t)((wn*32 + s*16 + rA)*128 + kc*2)));
            #pragma unroll
            for (int mi = 0; mi < 4; mi++)
                #pragma unroll
                for (int nj = 0; nj < 4; nj++)
                    mma_bf16(acc[mi][nj], af[mi][0], af[mi][1], af[mi][2], af[mi][3],
                             bf[nj>>1][nj&1], bf[nj>>1][(nj&1)+2]);
        }
        if (c + 2 < 12) issue(c + 2);
    }
    __syncthreads();

    // frags -> stage
    #pragma unroll
    for (int mi = 0; mi < 4; mi++)
        #pragma unroll
        for (int nj = 0; nj < 4; nj++) {
            int row = wm*64 + mi*16 + (lane >> 2);
            int col = wn*32 + nj*8 + (lane & 3)*2;
            *(float2*)&stage[row*STG + col]     = make_float2(acc[mi][nj][0], acc[mi][nj][1]);
            *(float2*)&stage[(row+8)*STG + col] = make_float2(acc[mi][nj][2], acc[mi][nj][3]);
        }
    __syncthreads();

    // softmax over each head's 64 cols per row
    float rt0 = 1.0f / fminf(fmaxf(temp[y2*2 + 0], 0.1f), 5.0f);
    float rt1 = 1.0f / fminf(fmaxf(temp[y2*2 + 1], 0.1f), 5.0f);
    for (int gi = 0; gi < 32; gi++) {
        int G = w * 32 + gi;
        int r = G >> 1, hh = G & 1;
        float bb0 = g_bsl[y2*128 + hh*64 + lane];
        float bb1 = g_bsl[y2*128 + hh*64 + 32 + lane];
        float rt = hh ? rt1 : rt0;
        float v0 = (stage[r*STG + hh*64 + lane]      + bb0) * rt;
        float v1 = (stage[r*STG + hh*64 + 32 + lane] + bb1) * rt;
        float m = fmaxf(v0, v1);
        #pragma unroll
        for (int o = 16; o; o >>= 1) m = fmaxf(m, __shfl_xor_sync(0xFFFFFFFFu, m, o));
        float e0 = __expf(v0 - m), e1 = __expf(v1 - m);
        float s = e0 + e1;
        #pragma unroll
        for (int o = 16; o; o >>= 1) s += __shfl_xor_sync(0xFFFFFFFFu, s, o);
        float rs = 1.0f / s;
        stage[r*STG + hh*64 + lane]      = e0 * rs;
        stage[r*STG + hh*64 + 32 + lane] = e1 * rs;
    }
    __syncthreads();

    // (a) norm: column sums -> atomic
    if (tid < 128) {
        float s = 0.f;
        #pragma unroll 8
        for (int r = 0; r < 128; r++) s += stage[r*STG + tid];
        int head = tid >> 6, g = tid & 63;
        atomicAdd(&g_norm[(b*8 + y2*2 + head)*64 + g], s);
    }
    // (b) w pair [tok][hg]  (coalesced 8B chunks)
    #pragma unroll
    for (int i = 0; i < 16; i++) {
        int lin = tid + i * 256, r = lin >> 5, c4 = (lin & 31) * 4;
        float4 v = *(float4*)&stage[r*STG + c4];
        __nv_bfloat16 hx = __float2bfloat16(v.x), hy = __float2bfloat16(v.y);
        __nv_bfloat16 hz = __float2bfloat16(v.z), hw = __float2bfloat16(v.w);
        __nv_bfloat162 h01(hx, hy), h23(hz, hw);
        __nv_bfloat162 l01 = __floats2bfloat162_rn(v.x - __bfloat162float(hx),
                                                   v.y - __bfloat162float(hy));
        __nv_bfloat162 l23 = __floats2bfloat162_rn(v.z - __bfloat162float(hz),
                                                   v.w - __bfloat162float(hw));
        uint2 uh, ul;
        uh.x = *reinterpret_cast<uint32_t*>(&h01); uh.y = *reinterpret_cast<uint32_t*>(&h23);
        ul.x = *reinterpret_cast<uint32_t*>(&l01); ul.y = *reinterpret_cast<uint32_t*>(&l23);
        size_t idx = (size_t)(row0 + r)*INNER + y2*128 + c4;
        *(uint2*)&g_w_hi[idx] = uh;
        *(uint2*)&g_w_lo[idx] = ul;
    }
    // (c) w^T pair [bh][g][n] — coalesced: thread owns (head,g) row-half
    {
        int G2 = tid >> 1, half = tid & 1;
        int head = G2 >> 6, g = G2 & 63;
        size_t basew = ((size_t)(b*8 + y2*2 + head) * 64 + g) * (size_t)NTOK
                       + row0loc + half * 64;
        #pragma unroll
        for (int t = 0; t < 64; t += 2) {
            float v0 = stage[(half*64 + t)     * STG + G2];
            float v1 = stage[(half*64 + t + 1) * STG + G2];
            __nv_bfloat16 h0 = __float2bfloat16(v0), h1 = __float2bfloat16(v1);
            uint32_t hw2 = (uint32_t)*(uint16_t*)&h0 | ((uint32_t)*(uint16_t*)&h1 << 16);
            __nv_bfloat16 l0 = __float2bfloat16(v0 - __bfloat162float(h0));
            __nv_bfloat16 l1 = __float2bfloat16(v1 - __bfloat162float(h1));
            uint32_t lw2 = (uint32_t)*(uint16_t*)&l0 | ((uint32_t)*(uint16_t*)&l1 << 16);
            *(uint32_t*)&g_wT_hi[basew + t] = hw2;
            *(uint32_t*)&g_wT_lo[basew + t] = lw2;
        }
    }
}

// ---------------- pooling GEMM: P[bh][g][c] = sum_n w[n,g]*x[n,c] ----------------
// block M64(g) x N128(c), grid (32 bh, 16 kc, 2 cb). 96 chunks of 64 k (3 segs x 32).
// 4-stage cp.async pipeline.
__global__ __launch_bounds__(256, 2) void k_poolg() {
    extern __shared__ char sm[];
    uint32_t sb = smem_u32(sm);
    int tid = threadIdx.x;
    int lane = tid & 31, w = tid >> 5;
    int wm = w & 1, wn = w >> 1;
    int bh = blockIdx.x, kc = blockIdx.y, cb = blockIdx.z;
    int b = bh >> 3;
    size_t nbase = (size_t)kc * 2048;
    const __nv_bfloat16* Ahi = g_wT_hi + (size_t)bh * 64 * NTOK;
    const __nv_bfloat16* Alo = g_wT_lo + (size_t)bh * 64 * NTOK;
    const __nv_bfloat16* Bhi = g_xT_hi + ((size_t)b * CC + cb * 128) * NTOK;
    const __nv_bfloat16* Blo = g_xT_lo + ((size_t)b * CC + cb * 128) * NTOK;

    float acc[2][4][4];
    #pragma unroll
    for (int a = 0; a < 2; a++)
        #pragma unroll
        for (int b2 = 0; b2 < 4; b2++)
            #pragma unroll
            for (int d = 0; d < 4; d++) acc[a][b2][d] = 0.f;

    auto issue = [&](int c) {
        int p = c & 3, seg = c >> 5, k0 = (c & 31) * 64;
        const __nv_bfloat16* As = (seg == 2) ? Alo : Ahi;
        const __nv_bfloat16* Bs = (seg == 1) ? Blo : Bhi;
        #pragma unroll
        for (int i = 0; i < 2; i++) {
            int id = tid + i * 256, r = id >> 3, c8 = (id & 7) * 8;
            cpa16(sb + p*24576 + SWZ((uint32_t)(r*128 + c8*2)),
                  As + (size_t)r * NTOK + nbase + k0 + c8);
        }
        #pragma unroll
        for (int i = 0; i < 4; i++) {
            int id = tid + i * 256, r = id >> 3, c8 = (id & 7) * 8;
            cpa16(sb + p*24576 + 8192 + SWZ((uint32_t)(r*128 + c8*2)),
                  Bs + (size_t)r * NTOK + nbase + k0 + c8);
        }
        CP_COMMIT();
    };

    issue(0); issue(1); issue(2);
    for (int c = 0; c < 96; c++) {
        if (c + 2 < 96) CP_WAIT2(); else if (c + 1 < 96) CP_WAIT1(); else CP_WAIT0();
        __syncthreads();
        uint32_t ab = sb + (c & 3) * 24576;
        uint32_t bb = ab + 8192;
        int rA = lane & 15;
        #pragma unroll
        for (int kk = 0; kk < 4; kk++) {
            uint32_t af[2][4], bf[2][4];
            int kc2 = kk * 16 + (lane >> 4) * 8;
            #pragma unroll
            for (int mi = 0; mi < 2; mi++)
                ldsm4(af[mi], ab + SWZ((uint32_t)((wm*32 + mi*16 + rA)*128 + kc2*2)));
            #pragma unroll
            for (int s = 0; s < 2; s++)
                ldsm4(bf[s], bb + SWZ((uint32_t)((wn*32 + s*16 + rA)*128 + kc2*2)));
            #pragma unroll
            for (int mi = 0; mi < 2; mi++)
                #pragma unroll
                for (int nj = 0; nj < 4; nj++)
                    mma_bf16(acc[mi][nj], af[mi][0], af[mi][1], af[mi][2], af[mi][3],
                             bf[nj>>1][nj&1], bf[nj>>1][(nj&1)+2]);
        }
        if (c + 3 < 96) issue(c + 3);
    }

    #pragma unroll
    for (int mi = 0; mi < 2; mi++)
        #pragma unroll
        for (int nj = 0; nj < 4; nj++) {
            int row = wm*32 + mi*16 + (lane >> 2);
            int col = cb*128 + wn*32 + nj*8 + (lane & 3)*2;
            int base = bh*16384 + row*256 + col;
            atomicAdd(&g_P[base],            acc[mi][nj][0]);
            atomicAdd(&g_P[base + 1],        acc[mi][nj][1]);
            atomicAdd(&g_P[base + 8*256],    acc[mi][nj][2]);
            atomicAdd(&g_P[base + 8*256 + 1],acc[mi][nj][3]);
        }
}

// ---------------- fused: ST = P@Wfx + bfx*norm ; tiny attention -> g_os ----------------
__global__ void k_stat(const float* __restrict__ Wfx, const float* __restrict__ bfx,
                       const float* __restrict__ Wq, const float* __restrict__ Wk,
                       const float* __restrict__ Wv) {
    int bh = blockIdx.x;
    int h = bh & 7;
    int tid = threadIdx.x;
    __shared__ float bufA[64][65], bufB[64][65];
    __shared__ float nrmc[64];

    // --- stok phase: acc = P @ Wfx (per thread: g row, 16 d-cols) ---
    float acc[16];
    #pragma unroll
    for (int j = 0; j < 16; j++) acc[j] = 0.f;
    int g = tid >> 2, dq = tid & 3;
    for (int c0 = 0; c0 < 4; c0++) {
        #pragma unroll
        for (int i = 0; i < 16; i++) {
            int id = tid + i * 256;
            int r = id >> 6, cl = id & 63;
            bufA[r][cl] = Wfx[(c0*64 + r) * INNER + h*64 + cl];
            bufB[r][cl] = g_P[bh*16384 + r*256 + c0*64 + cl];
        }
        __syncthreads();
        for (int cl = 0; cl < 64; cl++) {
            float pv = bufB[g][cl];
            #pragma unroll
            for (int j = 0; j < 16; j++)
                acc[j] += pv * bufA[cl][dq*16 + j];
        }
        __syncthreads();
    }
    if (tid < 64) nrmc[tid] = g_norm[bh*64 + tid];
    __syncthreads();
    // sn = (acc + bfx*nrm) / (nrm + 1e-5) directly into bufA (stride 65)
    {
        float nrm = nrmc[g];
        float rdiv = 1.0f / (nrm + 1e-5f);
        #pragma unroll
        for (int j = 0; j < 16; j++) {
            int d = dq*16 + j;
            bufA[g][d] = (acc[j] + bfx[h*64 + d] * nrm) * rdiv;
        }
    }
    __syncthreads();

    // --- attention phase on sn=bufA, ks=bufB (stride 65) ---
    #pragma unroll
    for (int it = 0; it < 16; it++) {
        int idx = tid + it * 256;
        int g2 = idx >> 6, d2 = idx & 63;
        float s0 = 0, s1 = 0, s2 = 0, s3 = 0;
        #pragma unroll
        for (int d = 0; d < 64; d += 4) {
            s0 += bufA[g2][d]   * Wk[(d)   * 64 + d2];
            s1 += bufA[g2][d+1] * Wk[(d+1) * 64 + d2];
            s2 += bufA[g2][d+2] * Wk[(d+2) * 64 + d2];
            s3 += bufA[g2][d+3] * Wk[(d+3) * 64 + d2];
        }
        bufB[g2][d2] = (s0 + s1) + (s2 + s3);
    }
    __syncthreads();
    float tv[64];
    if (tid < 64) {
        int g2 = tid;
        float q[64];
        #pragma unroll
        for (int d2 = 0; d2 < 64; d2++) {
            float s0 = 0, s1 = 0, s2 = 0, s3 = 0;
            #pragma unroll
            for (int d = 0; d < 64; d += 4) {
                s0 += bufA[g2][d]   * Wq[(d)   * 64 + d2];
                s1 += bufA[g2][d+1] * Wq[(d+1) * 64 + d2];
                s2 += bufA[g2][d+2] * Wq[(d+2) * 64 + d2];
                s3 += bufA[g2][d+3] * Wq[(d+3) * 64 + d2];
            }
            q[d2] = (s0 + s1) + (s2 + s3);
        }
        float p[64];
        float mx = -1e30f;
        #pragma unroll
        for (int j = 0; j < 64; j++) {
            float s0 = 0, s1 = 0, s2 = 0, s3 = 0;
            #pragma unroll
            for (int d = 0; d < 64; d += 4) {
                s0 += q[d]   * bufB[j][d];
                s1 += q[d+1] * bufB[j][d+1];
                s2 += q[d+2] * bufB[j][d+2];
                s3 += q[d+3] * bufB[j][d+3];
            }
            float s = ((s0 + s1) + (s2 + s3)) * 0.125f;
            p[j] = s;
            mx = fmaxf(mx, s);
        }
        float sum = 0.f;
        #pragma unroll
        for (int j = 0; j < 64; j++) { p[j] = __expf(p[j] - mx); sum += p[j]; }
        float rs = 1.0f / sum;
        #pragma unroll
        for (int e = 0; e < 64; e++) {
            float s0 = 0, s1 = 0, s2 = 0, s3 = 0;
            #pragma unroll
            for (int j = 0; j < 64; j += 4) {
                s0 += p[j]   * bufA[j][e];
                s1 += p[j+1] * bufA[j+1][e];
                s2 += p[j+2] * bufA[j+2][e];
                s3 += p[j+3] * bufA[j+3][e];
            }
            tv[e] = ((s0 + s1) + (s2 + s3)) * rs;
        }
    }
    __syncthreads();
    if (tid < 64) {
        #pragma unroll
        for (int e = 0; e < 64; e++) bufB[tid][e] = tv[e];
    }
    __syncthreads();
    #pragma unroll
    for (int it = 0; it < 16; it++) {
        int idx = tid + it * 256;
        int g2 = idx >> 6, d2 = idx & 63;
        float s0 = 0, s1 = 0, s2 = 0, s3 = 0;
        #pragma unroll
        for (int e = 0; e < 64; e += 4) {
            s0 += bufB[g2][e]   * Wv[(e)   * 64 + d2];
            s1 += bufB[g2][e+1] * Wv[(e+1) * 64 + d2];
            s2 += bufB[g2][e+2] * Wv[(e+2) * 64 + d2];
            s3 += bufB[g2][e+3] * Wv[(e+3) * 64 + d2];
        }
        g_os[bh * 4096 + idx] = (s0 + s1) + (s2 + s3);
    }
}

// ---------------- fold out_slice into W_out: W_eff^T pair [b][n=256][k=512] ----------------
__global__ void k_weff(const float* __restrict__ Wout) {
    int blk = blockIdx.x;           // b*512 + row
    int b = blk >> 9;
    int row = blk & 511;            // k index: h*64+g
    int h = row >> 6;
    int tid = threadIdx.x;          // n index = c (256)
    __shared__ float osr[64];
    if (tid < 64) osr[tid] = g_os[(b*8 + h) * 4096 + (row & 63) * 64 + tid];
    __syncthreads();
    float s = 0.f;
    #pragma unroll 16
    for (int d = 0; d < 64; d++)
        s += osr[d] * Wout[(h*64 + d) * CC + tid];
    __nv_bfloat16 sh = __float2bfloat16(s);
    size_t idx = (size_t)b * (CC*INNER) + (size_t)tid * INNER + row;
    g_weffT_hi[idx] = sh;
    g_weffT_lo[idx] = __float2bfloat16(s - __bfloat162float(sh));
}

// ---------------- output GEMM (mma.sync): y = w @ W_eff[b] + b_out ----------------
// block M128 x N128, K=512 x 3 segments (24 chunks). grid (2, 1024): ct fast-varying.
__global__ __launch_bounds__(256, 2) void k_out(const float* __restrict__ bout,
                                                float* __restrict__ y) {
    extern __shared__ char sm[];
    float* stage = (float*)sm;
    uint32_t sb = smem_u32(sm);
    int tid = threadIdx.x;
    int lane = tid & 31, w = tid >> 5;
    int wm = w & 1, wn = w >> 1;
    int tileM = blockIdx.y, ct = blockIdx.x;
    int row0 = tileM * 128;
    int b = tileM >> 8;

    float acc[4][4][4];
    #pragma unroll
    for (int a = 0; a < 4; a++)
        #pragma unroll
        for (int bb2 = 0; bb2 < 4; bb2++)
            #pragma unroll
            for (int d = 0; d < 4; d++) acc[a][bb2][d] = 0.f;

    auto issue = [&](int c) {
        int p = c % 3, seg = c >> 3, k0 = (c & 7) * 64;
        const __nv_bfloat16* As = (seg == 2) ? g_w_lo : g_w_hi;
        const __nv_bfloat16* Bs = (seg == 1) ? g_weffT_lo : g_weffT_hi;
        #pragma unroll
        for (int i = 0; i < 4; i++) {
            int id = tid + i * 256, r = id >> 3, c8 = (id & 7) * 8;
            cpa16(sb + p*32768 + SWZ((uint32_t)(r*128 + c8*2)),
                  As + (size_t)(row0 + r) * INNER + k0 + c8);
        }
        #pragma unroll
        for (int i = 0; i < 4; i++) {
            int id = tid + i * 256, r = id >> 3, c8 = (id & 7) * 8;
            cpa16(sb + p*32768 + 16384 + SWZ((uint32_t)(r*128 + c8*2)),
                  Bs + (size_t)b * (CC*INNER) + (size_t)(ct*128 + r) * INNER + k0 + c8);
        }
        CP_COMMIT();
    };

    issue(0); issue(1);
    for (int c = 0; c < 24; c++) {
        if (c + 1 < 24) CP_WAIT1(); else CP_WAIT0();
        __syncthreads();
        uint32_t ab = sb + (c % 3) * 32768;
        uint32_t bbs = ab + 16384;
        int rA = lane & 15;
        #pragma unroll
        for (int kk = 0; kk < 4; kk++) {
            uint32_t af[4][4], bf[2][4];
            int kc = kk * 16 + (lane >> 4) * 8;
            #pragma unroll
            for (int mi = 0; mi < 4; mi++)
                ldsm4(af[mi], ab + SWZ((uint32_t)((wm*64 + mi*16 + rA)*128 + kc*2)));
            #pragma unroll
            for (int s = 0; s < 2; s++)
                ldsm4(bf[s], bbs + SWZ((uint32_t)((wn*32 + s*16 + rA)*128 + kc*2)));
            #pragma unroll
            for (int mi = 0; mi < 4; mi++)
                #pragma unroll
                for (int nj = 0; nj < 4; nj++)
                    mma_bf16(acc[mi][nj], af[mi][0], af[mi][1], af[mi][2], af[mi][3],
                             bf[nj>>1][nj&1], bf[nj>>1][(nj&1)+2]);
        }
        if (c + 2 < 24) issue(c + 2);
    }
    __syncthreads();

    #pragma unroll
    for (int mi = 0; mi < 4; mi++)
        #pragma unroll
        for (int nj = 0; nj < 4; nj++) {
            int row = wm*64 + mi*16 + (lane >> 2);
            int col = wn*32 + nj*8 + (lane & 3)*2;
            *(float2*)&stage[row*STG + col]     = make_float2(acc[mi][nj][0], acc[mi][nj][1]);
            *(float2*)&stage[(row+8)*STG + col] = make_float2(acc[mi][nj][2], acc[mi][nj][3]);
        }
    __syncthreads();
    #pragma unroll
    for (int i = 0; i < 16; i++) {
        int lin = tid + i * 256, r = lin >> 5, c4 = (lin & 31) * 4;
        float4 v = *(float4*)&stage[r*STG + c4];
        float4 bv = *(const float4*)&bout[ct*128 + c4];
        v.x += bv.x; v.y += bv.y; v.z += bv.z; v.w += bv.w;
        *(float4*)&y[(size_t)(row0 + r)*CC + ct*128 + c4] = v;
    }
}

// ---------------- launch ----------------
extern "C" void kernel_launch(void* const* d_in, const int* in_sizes, int n_in,
                              void* d_out, int out_size) {
    const float* x    = (const float*)d_in[0];
    const float* Wfx  = (const float*)d_in[1];
    const float* bfx  = (const float*)d_in[2];
    const float* Wx   = (const float*)d_in[3];
    const float* bx   = (const float*)d_in[4];
    const float* Wsl  = (const float*)d_in[5];
    const float* bsl  = (const float*)d_in[6];
    const float* temp = (const float*)d_in[7];
    const float* Wq   = (const float*)d_in[8];
    const float* Wk   = (const float*)d_in[9];
    const float* Wv   = (const float*)d_in[10];
    const float* Wout = (const float*)d_in[11];
    const float* bout = (const float*)d_in[12];
    float* y = (float*)d_out;

    cudaFuncSetAttribute(k_proj,  cudaFuncAttributeMaxDynamicSharedMemorySize, GSMEM);
    cudaFuncSetAttribute(k_poolg, cudaFuncAttributeMaxDynamicSharedMemorySize, PGSMEM);
    cudaFuncSetAttribute(k_out,   cudaFuncAttributeMaxDynamicSharedMemorySize, GSMEM);

    k_zero<<<2048, 256>>>();
    k_prep<<<CC, 512>>>(Wx, bx, Wsl, bsl);
    k_split<<<dim3(TOK/64, 4), 256>>>(x);
    k_proj<<<dim3(4, TOK/128), 256, GSMEM>>>(temp);
    k_poolg<<<dim3(32, 16, 2), 256, PGSMEM>>>();
    k_stat<<<32, 256>>>(Wfx, bfx, Wq, Wk, Wv);
    k_weff<<<2048, 256>>>(Wout);
    k_out<<<dim3(2, TOK/128), 256, GSMEM>>>(bout, y);
}

// round 10
// speedup vs baseline: 1.1640x; 1.0592x over previous
#include <cuda_runtime.h>
#include <cuda_bf16.h>
#include <cstdint>

#define BB 4
#define NTOK 32768
#define CC 256
#define HH 8
#define DD 64
#define GG 64
#define INNER 512
#define TOK (BB*NTOK)   // 131072

// ---------------- scratch (device globals; no runtime allocation) ----------------
__device__ __align__(16) __nv_bfloat16 g_x_hi[(size_t)TOK*CC];   // x split bf16 [tok][c]
__device__ __align__(16) __nv_bfloat16 g_xT_hi[(size_t)BB*CC*NTOK]; // x^T [b][c][n]
__device__ __align__(16) __nv_bfloat16 g_xT_lo[(size_t)BB*CC*NTOK];
__device__ __align__(16) __nv_bfloat16 g_w_hi[(size_t)TOK*INNER];// slice weights [tok][hg]
__device__ __align__(16) __nv_bfloat16 g_w_lo[(size_t)TOK*INNER];
__device__ __align__(16) __nv_bfloat16 g_wT_hi[(size_t)BB*HH*GG*NTOK]; // w^T [bh][g][n]
__device__ __align__(16) __nv_bfloat16 g_wT_lo[(size_t)BB*HH*GG*NTOK];
__device__ __align__(16) __nv_bfloat16 g_wslT_hi[INNER*CC];      // (Wx@Wslice)^T split
__device__ __align__(16) __nv_bfloat16 g_wslT_lo[INNER*CC];
__device__ float g_bsl[INNER];                    // folded slice bias
__device__ float g_P[BB*HH*GG*CC];                // pooled P[bh][g][c] (atomic accum)
__device__ float g_norm[BB*HH*GG];                // weight column sums
__device__ float g_os[BB*HH*GG*DD];               // out_slice
__device__ __align__(16) __nv_bfloat16 g_weffT_hi[BB*CC*INNER];  // W_eff^T [b][n=256][k=512]
__device__ __align__(16) __nv_bfloat16 g_weffT_lo[BB*CC*INNER];

// ============================ helpers ============================
#define DINLINE __device__ __forceinline__

DINLINE uint32_t smem_u32(const void* p) {
    uint32_t a;
    asm("{ .reg .u64 t; cvta.to.shared.u64 t, %1; cvt.u32.u64 %0, t; }" : "=r"(a) : "l"(p));
    return a;
}
DINLINE void cpa16(uint32_t dst, const void* src) {
    asm volatile("cp.async.cg.shared.global [%0], [%1], 16;" :: "r"(dst), "l"(src));
}
#define CP_COMMIT() asm volatile("cp.async.commit_group;" ::: "memory")
#define CP_WAIT2()  asm volatile("cp.async.wait_group 2;" ::: "memory")
#define CP_WAIT1()  asm volatile("cp.async.wait_group 1;" ::: "memory")
#define CP_WAIT0()  asm volatile("cp.async.wait_group 0;" ::: "memory")

DINLINE void ldsm4(uint32_t* r, uint32_t addr) {
    asm volatile("ldmatrix.sync.aligned.m8n8.x4.shared.b16 {%0,%1,%2,%3}, [%4];"
        : "=r"(r[0]), "=r"(r[1]), "=r"(r[2]), "=r"(r[3]) : "r"(addr));
}
DINLINE void mma_bf16(float* d, uint32_t a0, uint32_t a1, uint32_t a2, uint32_t a3,
                      uint32_t b0, uint32_t b1) {
    asm volatile("mma.sync.aligned.m16n8k16.row.col.f32.bf16.bf16.f32 "
        "{%0,%1,%2,%3}, {%4,%5,%6,%7}, {%8,%9}, {%0,%1,%2,%3};"
        : "+f"(d[0]), "+f"(d[1]), "+f"(d[2]), "+f"(d[3])
        : "r"(a0), "r"(a1), "r"(a2), "r"(a3), "r"(b0), "r"(b1));
}
#define SWZ(off) ((off) ^ (((off) >> 3) & 0x70))
#define STG 132        // stage row stride (floats)
#define GSMEM 98304    // 3 stages x (16KB A + 16KB B)
#define PGSMEM 98304   // 4 stages x (8KB A + 16KB B)

// ---------------- zero accumulators (must run every graph replay) ----------------
__global__ void k_zero() {
    int i = blockIdx.x * blockDim.x + threadIdx.x;
    if (i < BB*HH*GG*CC) g_P[i] = 0.f;
    if (i < BB*HH*GG)    g_norm[i] = 0.f;
}

// ---------------- split x into bf16 hi ([tok][c]) and hi/lo transposed ----------------
__global__ void k_split(const float* __restrict__ x) {
    __shared__ uint16_t shi[64][68], slo[64][68];
    int tid = threadIdx.x;
    size_t t0 = (size_t)blockIdx.x * 64;     // token tile
    int c0 = blockIdx.y * 64;                // c tile
    int r = tid >> 2, cq = (tid & 3) * 16;
    #pragma unroll
    for (int j = 0; j < 16; j += 4) {
        float4 v = *(const float4*)&x[(t0 + r) * CC + c0 + cq + j];
        __nv_bfloat16 hx = __float2bfloat16(v.x), hy = __float2bfloat16(v.y);
        __nv_bfloat16 hz = __float2bfloat16(v.z), hw = __float2bfloat16(v.w);
        __nv_bfloat162 h01(hx, hy), h23(hz, hw);
        __nv_bfloat162 l01 = __floats2bfloat162_rn(v.x - __bfloat162float(hx),
                                                   v.y - __bfloat162float(hy));
        __nv_bfloat162 l23 = __floats2bfloat162_rn(v.z - __bfloat162float(hz),
                                                   v.w - __bfloat162float(hw));
        uint2 uh, ul;
        uh.x = *reinterpret_cast<uint32_t*>(&h01); uh.y = *reinterpret_cast<uint32_t*>(&h23);
        ul.x = *reinterpret_cast<uint32_t*>(&l01); ul.y = *reinterpret_cast<uint32_t*>(&l23);
        *(uint2*)&g_x_hi[(t0 + r) * CC + c0 + cq + j] = uh;
        *(uint2*)&shi[r][cq + j] = uh;
        *(uint2*)&slo[r][cq + j] = ul;
    }
    __syncthreads();
    int c = tid >> 2, tq = (tid & 3) * 16;
    size_t b = t0 >> 15;                 // /NTOK
    size_t nloc = t0 & (NTOK - 1);
    size_t base = ((size_t)b * CC + c0 + c) * NTOK + nloc + tq;
    #pragma unroll
    for (int j = 0; j < 16; j += 2) {
        uint32_t hv = (uint32_t)shi[tq + j][c] | ((uint32_t)shi[tq + j + 1][c] << 16);
        uint32_t lv = (uint32_t)slo[tq + j][c] | ((uint32_t)slo[tq + j + 1][c] << 16);
        *(uint32_t*)&g_xT_hi[base + j] = hv;
        *(uint32_t*)&g_xT_lo[base + j] = lv;
    }
}

// ---------------- fold + transpose + bf16-split slice weight ----------------
__global__ void k_prep(const float* __restrict__ Wx, const float* __restrict__ bx,
                       const float* __restrict__ Wsl, const float* __restrict__ bsl) {
    int c = blockIdx.x;        // K index 0..255
    int o = threadIdx.x;       // N index 0..511
    int h = o >> 6, gg = o & 63;
    float s = 0.f;
    #pragma unroll 16
    for (int d = 0; d < 64; d++)
        s += Wx[c*INNER + h*64 + d] * Wsl[d*64 + gg];
    __nv_bfloat16 sh = __float2bfloat16(s);
    g_wslT_hi[o*CC + c] = sh;
    g_wslT_lo[o*CC + c] = __float2bfloat16(s - __bfloat162float(sh));
    if (c == 0) {
        float t = 0.f;
        #pragma unroll 16
        for (int d = 0; d < 64; d++) t += bx[h*64 + d] * Wsl[d*64 + gg];
        g_bsl[o] = t + bsl[gg];
    }
}

// ---------------- slice-logits GEMM + softmax (mma.sync) ----------------
// block M128 x N128, K=256 x 2 segments (8 chunks of 64): hi*Bhi + hi*Blo.
// (x_lo*Bhi term dropped: logits are small-magnitude, abs error ~2e-4.)
// grid (4, 1024).
__global__ __launch_bounds__(256, 2) void k_proj(const float* __restrict__ temp) {
    extern __shared__ char sm[];
    float* stage = (float*)sm;
    uint32_t sb = smem_u32(sm);
    int tid = threadIdx.x;
    int lane = tid & 31, w = tid >> 5;
    int wm = w & 1, wn = w >> 1;
    int tileM = blockIdx.y, y2 = blockIdx.x;
    int row0 = tileM * 128;
    int b = tileM >> 8;
    size_t row0loc = (size_t)(tileM & 255) * 128;

    float acc[4][4][4];
    #pragma unroll
    for (int a = 0; a < 4; a++)
        #pragma unroll
        for (int b2 = 0; b2 < 4; b2++)
            #pragma unroll
            for (int d = 0; d < 4; d++) acc[a][b2][d] = 0.f;

    auto issue = [&](int c) {
        int p = c % 3, seg = c >> 2, k0 = (c & 3) * 64;
        const __nv_bfloat16* Bs = (seg == 1) ? g_wslT_lo : g_wslT_hi;
        #pragma unroll
        for (int i = 0; i < 4; i++) {
            int id = tid + i * 256, r = id >> 3, c8 = (id & 7) * 8;
            cpa16(sb + p*32768 + SWZ((uint32_t)(r*128 + c8*2)),
                  g_x_hi + (size_t)(row0 + r) * CC + k0 + c8);
        }
        #pragma unroll
        for (int i = 0; i < 4; i++) {
            int id = tid + i * 256, r = id >> 3, c8 = (id & 7) * 8;
            cpa16(sb + p*32768 + 16384 + SWZ((uint32_t)(r*128 + c8*2)),
                  Bs + (size_t)(y2*128 + r) * CC + k0 + c8);
        }
        CP_COMMIT();
    };

    issue(0); issue(1);
    for (int c = 0; c < 8; c++) {
        if (c + 1 < 8) CP_WAIT1(); else CP_WAIT0();
        __syncthreads();
        uint32_t ab = sb + (c % 3) * 32768;
        uint32_t bb = ab + 16384;
        int rA = lane & 15;
        #pragma unroll
        for (int kk = 0; kk < 4; kk++) {
            uint32_t af[4][4], bf[2][4];
            int kc = kk * 16 + (lane >> 4) * 8;
            #pragma unroll
            for (int mi = 0; mi < 4; mi++)
                ldsm4(af[mi], ab + SWZ((uint32_t)((wm*64 + mi*16 + rA)*128 + kc*2)));
            #pragma unroll
            for (int s = 0; s < 2; s++)
                ldsm4(bf[s], bb + SWZ((uint32_t)((wn*32 + s*16 + rA)*128 + kc*2)));
            #pragma unroll
            for (int mi = 0; mi < 4; mi++)
                #pragma unroll
                for (int nj = 0; nj < 4; nj++)
                    mma_bf16(acc[mi][nj], af[mi][0], af[mi][1], af[mi][2], af[mi][3],
                             bf[nj>>1][nj&1], bf[nj>>1][(nj&1)+2]);
        }
        if (c + 2 < 8) issue(c + 2);
    }
    __syncthreads();

    // frags -> stage
    #pragma unroll
    for (int mi = 0; mi < 4; mi++)
        #pragma unroll
        for (int nj = 0; nj < 4; nj++) {
            int row = wm*64 + mi*16 + (lane >> 2);
            int col = wn*32 + nj*8 + (lane & 3)*2;
            *(float2*)&stage[row*STG + col]     = make_float2(acc[mi][nj][0], acc[mi][nj][1]);
            *(float2*)&stage[(row+8)*STG + col] = make_float2(acc[mi][nj][2], acc[mi][nj][3]);
        }
    __syncthreads();

    // softmax over each head's 64 cols per row
    float rt0 = 1.0f / fminf(fmaxf(temp[y2*2 + 0], 0.1f), 5.0f);
    float rt1 = 1.0f / fminf(fmaxf(temp[y2*2 + 1], 0.1f), 5.0f);
    for (int gi = 0; gi < 32; gi++) {
        int G = w * 32 + gi;
        int r = G >> 1, hh = G & 1;
        float bb0 = g_bsl[y2*128 + hh*64 + lane];
        float bb1 = g_bsl[y2*128 + hh*64 + 32 + lane];
        float rt = hh ? rt1 : rt0;
        float v0 = (stage[r*STG + hh*64 + lane]      + bb0) * rt;
        float v1 = (stage[r*STG + hh*64 + 32 + lane] + bb1) * rt;
        float m = fmaxf(v0, v1);
        #pragma unroll
        for (int o = 16; o; o >>= 1) m = fmaxf(m, __shfl_xor_sync(0xFFFFFFFFu, m, o));
        float e0 = __expf(v0 - m), e1 = __expf(v1 - m);
        float s = e0 + e1;
        #pragma unroll
        for (int o = 16; o; o >>= 1) s += __shfl_xor_sync(0xFFFFFFFFu, s, o);
        float rs = 1.0f / s;
        stage[r*STG + hh*64 + lane]      = e0 * rs;
        stage[r*STG + hh*64 + 32 + lane] = e1 * rs;
    }
    __syncthreads();

    // (a) norm: column sums -> atomic
    if (tid < 128) {
        float s = 0.f;
        #pragma unroll 8
        for (int r = 0; r < 128; r++) s += stage[r*STG + tid];
        int head = tid >> 6, g = tid & 63;
        atomicAdd(&g_norm[(b*8 + y2*2 + head)*64 + g], s);
    }
    // (b) w pair [tok][hg]  (coalesced 8B chunks)
    #pragma unroll
    for (int i = 0; i < 16; i++) {
        int lin = tid + i * 256, r = lin >> 5, c4 = (lin & 31) * 4;
        float4 v = *(float4*)&stage[r*STG + c4];
        __nv_bfloat16 hx = __float2bfloat16(v.x), hy = __float2bfloat16(v.y);
        __nv_bfloat16 hz = __float2bfloat16(v.z), hw = __float2bfloat16(v.w);
        __nv_bfloat162 h01(hx, hy), h23(hz, hw);
        __nv_bfloat162 l01 = __floats2bfloat162_rn(v.x - __bfloat162float(hx),
                                                   v.y - __bfloat162float(hy));
        __nv_bfloat162 l23 = __floats2bfloat162_rn(v.z - __bfloat162float(hz),
                                                   v.w - __bfloat162float(hw));
        uint2 uh, ul;
        uh.x = *reinterpret_cast<uint32_t*>(&h01); uh.y = *reinterpret_cast<uint32_t*>(&h23);
        ul.x = *reinterpret_cast<uint32_t*>(&l01); ul.y = *reinterpret_cast<uint32_t*>(&l23);
        size_t idx = (size_t)(row0 + r)*INNER + y2*128 + c4;
        *(uint2*)&g_w_hi[idx] = uh;
        *(uint2*)&g_w_lo[idx] = ul;
    }
    // (c) w^T pair [bh][g][n] — coalesced: thread owns (head,g) row-half
    {
        int G2 = tid >> 1, half = tid & 1;
        int head = G2 >> 6, g = G2 & 63;
        size_t basew = ((size_t)(b*8 + y2*2 + head) * 64 + g) * (size_t)NTOK
                       + row0loc + half * 64;
        #pragma unroll
        for (int t = 0; t < 64; t += 2) {
            float v0 = stage[(half*64 + t)     * STG + G2];
            float v1 = stage[(half*64 + t + 1) * STG + G2];
            __nv_bfloat16 h0 = __float2bfloat16(v0), h1 = __float2bfloat16(v1);
            uint32_t hw2 = (uint32_t)*(uint16_t*)&h0 | ((uint32_t)*(uint16_t*)&h1 << 16);
            __nv_bfloat16 l0 = __float2bfloat16(v0 - __bfloat162float(h0));
            __nv_bfloat16 l1 = __float2bfloat16(v1 - __bfloat162float(h1));
            uint32_t lw2 = (uint32_t)*(uint16_t*)&l0 | ((uint32_t)*(uint16_t*)&l1 << 16);
            *(uint32_t*)&g_wT_hi[basew + t] = hw2;
            *(uint32_t*)&g_wT_lo[basew + t] = lw2;
        }
    }
}

// ---------------- pooling GEMM: P[bh][g][c] = sum_n w[n,g]*x[n,c] ----------------
// block M64(g) x N128(c), grid (32 bh, 16 kc, 2 cb). 96 chunks of 64 k (3 segs x 32).
// 4-stage cp.async pipeline.
__global__ __launch_bounds__(256, 2) void k_poolg() {
    extern __shared__ char sm[];
    uint32_t sb = smem_u32(sm);
    int tid = threadIdx.x;
    int lane = tid & 31, w = tid >> 5;
    int wm = w & 1, wn = w >> 1;
    int bh = blockIdx.x, kc = blockIdx.y, cb = blockIdx.z;
    int b = bh >> 3;
    size_t nbase = (size_t)kc * 2048;
    const __nv_bfloat16* Ahi = g_wT_hi + (size_t)bh * 64 * NTOK;
    const __nv_bfloat16* Alo = g_wT_lo + (size_t)bh * 64 * NTOK;
    const __nv_bfloat16* Bhi = g_xT_hi + ((size_t)b * CC + cb * 128) * NTOK;
    const __nv_bfloat16* Blo = g_xT_lo + ((size_t)b * CC + cb * 128) * NTOK;

    float acc[2][4][4];
    #pragma unroll
    for (int a = 0; a < 2; a++)
        #pragma unroll
        for (int b2 = 0; b2 < 4; b2++)
            #pragma unroll
            for (int d = 0; d < 4; d++) acc[a][b2][d] = 0.f;

    auto issue = [&](int c) {
        int p = c & 3, seg = c >> 5, k0 = (c & 31) * 64;
        const __nv_bfloat16* As = (seg == 2) ? Alo : Ahi;
        const __nv_bfloat16* Bs = (seg == 1) ? Blo : Bhi;
        #pragma unroll
        for (int i = 0; i < 2; i++) {
            int id = tid + i * 256, r = id >> 3, c8 = (id & 7) * 8;
            cpa16(sb + p*24576 + SWZ((uint32_t)(r*128 + c8*2)),
                  As + (size_t)r * NTOK + nbase + k0 + c8);
        }
        #pragma unroll
        for (int i = 0; i < 4; i++) {
            int id = tid + i * 256, r = id >> 3, c8 = (id & 7) * 8;
            cpa16(sb + p*24576 + 8192 + SWZ((uint32_t)(r*128 + c8*2)),
                  Bs + (size_t)r * NTOK + nbase + k0 + c8);
        }
        CP_COMMIT();
    };

    issue(0); issue(1); issue(2);
    for (int c = 0; c < 96; c++) {
        if (c + 2 < 96) CP_WAIT2(); else if (c + 1 < 96) CP_WAIT1(); else CP_WAIT0();
        __syncthreads();
        uint32_t ab = sb + (c & 3) * 24576;
        uint32_t bb = ab + 8192;
        int rA = lane & 15;
        #pragma unroll
        for (int kk = 0; kk < 4; kk++) {
            uint32_t af[2][4], bf[2][4];
            int kc2 = kk * 16 + (lane >> 4) * 8;
            #pragma unroll
            for (int mi = 0; mi < 2; mi++)
                ldsm4(af[mi], ab + SWZ((uint32_t)((wm*32 + mi*16 + rA)*128 + kc2*2)));
            #pragma unroll
            for (int s = 0; s < 2; s++)
                ldsm4(bf[s], bb + SWZ((uint32_t)((wn*32 + s*16 + rA)*128 + kc2*2)));
            #pragma unroll
            for (int mi = 0; mi < 2; mi++)
                #pragma unroll
                for (int nj = 0; nj < 4; nj++)
                    mma_bf16(acc[mi][nj], af[mi][0], af[mi][1], af[mi][2], af[mi][3],
                             bf[nj>>1][nj&1], bf[nj>>1][(nj&1)+2]);
        }
        if (c + 3 < 96) issue(c + 3);
    }

    #pragma unroll
    for (int mi = 0; mi < 2; mi++)
        #pragma unroll
        for (int nj = 0; nj < 4; nj++) {
            int row = wm*32 + mi*16 + (lane >> 2);
            int col = cb*128 + wn*32 + nj*8 + (lane & 3)*2;
            int base = bh*16384 + row*256 + col;
            atomicAdd(&g_P[base],            acc[mi][nj][0]);
            atomicAdd(&g_P[base + 1],        acc[mi][nj][1]);
            atomicAdd(&g_P[base + 8*256],    acc[mi][nj][2]);
            atomicAdd(&g_P[base + 8*256 + 1],acc[mi][nj][3]);
        }
}

// ---------------- fused: ST = P@Wfx + bfx*norm ; tiny attention -> g_os ----------------
__global__ void k_stat(const float* __restrict__ Wfx, const float* __restrict__ bfx,
                       const float* __restrict__ Wq, const float* __restrict__ Wk,
                       const float* __restrict__ Wv) {
    int bh = blockIdx.x;
    int h = bh & 7;
    int tid = threadIdx.x;
    __shared__ float bufA[64][65], bufB[64][65];
    __shared__ float nrmc[64];

    // --- stok phase: acc = P @ Wfx (per thread: g row, 16 d-cols) ---
    float acc[16];
    #pragma unroll
    for (int j = 0; j < 16; j++) acc[j] = 0.f;
    int g = tid >> 2, dq = tid & 3;
    for (int c0 = 0; c0 < 4; c0++) {
        #pragma unroll
        for (int i = 0; i < 16; i++) {
            int id = tid + i * 256;
            int r = id >> 6, cl = id & 63;
            bufA[r][cl] = Wfx[(c0*64 + r) * INNER + h*64 + cl];
            bufB[r][cl] = g_P[bh*16384 + r*256 + c0*64 + cl];
        }
        __syncthreads();
        for (int cl = 0; cl < 64; cl++) {
            float pv = bufB[g][cl];
            #pragma unroll
            for (int j = 0; j < 16; j++)
                acc[j] += pv * bufA[cl][dq*16 + j];
        }
        __syncthreads();
    }
    if (tid < 64) nrmc[tid] = g_norm[bh*64 + tid];
    __syncthreads();
    {
        float nrm = nrmc[g];
        float rdiv = 1.0f / (nrm + 1e-5f);
        #pragma unroll
        for (int j = 0; j < 16; j++) {
            int d = dq*16 + j;
            bufA[g][d] = (acc[j] + bfx[h*64 + d] * nrm) * rdiv;
        }
    }
    __syncthreads();

    // --- attention phase on sn=bufA, ks=bufB ---
    #pragma unroll
    for (int it = 0; it < 16; it++) {
        int idx = tid + it * 256;
        int g2 = idx >> 6, d2 = idx & 63;
        float s0 = 0, s1 = 0, s2 = 0, s3 = 0;
        #pragma unroll
        for (int d = 0; d < 64; d += 4) {
            s0 += bufA[g2][d]   * Wk[(d)   * 64 + d2];
            s1 += bufA[g2][d+1] * Wk[(d+1) * 64 + d2];
            s2 += bufA[g2][d+2] * Wk[(d+2) * 64 + d2];
            s3 += bufA[g2][d+3] * Wk[(d+3) * 64 + d2];
        }
        bufB[g2][d2] = (s0 + s1) + (s2 + s3);
    }
    __syncthreads();
    float tv[64];
    if (tid < 64) {
        int g2 = tid;
        float q[64];
        #pragma unroll
        for (int d2 = 0; d2 < 64; d2++) {
            float s0 = 0, s1 = 0, s2 = 0, s3 = 0;
            #pragma unroll
            for (int d = 0; d < 64; d += 4) {
                s0 += bufA[g2][d]   * Wq[(d)   * 64 + d2];
                s1 += bufA[g2][d+1] * Wq[(d+1) * 64 + d2];
                s2 += bufA[g2][d+2] * Wq[(d+2) * 64 + d2];
                s3 += bufA[g2][d+3] * Wq[(d+3) * 64 + d2];
            }
            q[d2] = (s0 + s1) + (s2 + s3);
        }
        float p[64];
        float mx = -1e30f;
        #pragma unroll
        for (int j = 0; j < 64; j++) {
            float s0 = 0, s1 = 0, s2 = 0, s3 = 0;
            #pragma unroll
            for (int d = 0; d < 64; d += 4) {
                s0 += q[d]   * bufB[j][d];
                s1 += q[d+1] * bufB[j][d+1];
                s2 += q[d+2] * bufB[j][d+2];
                s3 += q[d+3] * bufB[j][d+3];
            }
            float s = ((s0 + s1) + (s2 + s3)) * 0.125f;
            p[j] = s;
            mx = fmaxf(mx, s);
        }
        float sum = 0.f;
        #pragma unroll
        for (int j = 0; j < 64; j++) { p[j] = __expf(p[j] - mx); sum += p[j]; }
        float rs = 1.0f / sum;
        #pragma unroll
        for (int e = 0; e < 64; e++) {
            float s0 = 0, s1 = 0, s2 = 0, s3 = 0;
            #pragma unroll
            for (int j = 0; j < 64; j += 4) {
                s0 += p[j]   * bufA[j][e];
                s1 += p[j+1] * bufA[j+1][e];
                s2 += p[j+2] * bufA[j+2][e];
                s3 += p[j+3] * bufA[j+3][e];
            }
            tv[e] = ((s0 + s1) + (s2 + s3)) * rs;
        }
    }
    __syncthreads();
    if (tid < 64) {
        #pragma unroll
        for (int e = 0; e < 64; e++) bufB[tid][e] = tv[e];
    }
    __syncthreads();
    #pragma unroll
    for (int it = 0; it < 16; it++) {
        int idx = tid + it * 256;
        int g2 = idx >> 6, d2 = idx & 63;
        float s0 = 0, s1 = 0, s2 = 0, s3 = 0;
        #pragma unroll
        for (int e = 0; e < 64; e += 4) {
            s0 += bufB[g2][e]   * Wv[(e)   * 64 + d2];
            s1 += bufB[g2][e+1] * Wv[(e+1) * 64 + d2];
            s2 += bufB[g2][e+2] * Wv[(e+2) * 64 + d2];
            s3 += bufB[g2][e+3] * Wv[(e+3) * 64 + d2];
        }
        g_os[bh * 4096 + idx] = (s0 + s1) + (s2 + s3);
    }
}

// ---------------- fold out_slice into W_out: W_eff^T pair [b][n=256][k=512] ----------------
__global__ void k_weff(const float* __restrict__ Wout) {
    int blk = blockIdx.x;           // b*512 + row
    int b = blk >> 9;
    int row = blk & 511;            // k index: h*64+g
    int h = row >> 6;
    int tid = threadIdx.x;          // n index = c (256)
    __shared__ float osr[64];
    if (tid < 64) osr[tid] = g_os[(b*8 + h) * 4096 + (row & 63) * 64 + tid];
    __syncthreads();
    float s = 0.f;
    #pragma unroll 16
    for (int d = 0; d < 64; d++)
        s += osr[d] * Wout[(h*64 + d) * CC + tid];
    __nv_bfloat16 sh = __float2bfloat16(s);
    size_t idx = (size_t)b * (CC*INNER) + (size_t)tid * INNER + row;
    g_weffT_hi[idx] = sh;
    g_weffT_lo[idx] = __float2bfloat16(s - __bfloat162float(sh));
}

// ---------------- output GEMM (mma.sync): y = w @ W_eff[b] + b_out ----------------
// block M128 x N128, K=512 x 3 segments (24 chunks). grid (2, 1024): ct fast-varying.
__global__ __launch_bounds__(256, 2) void k_out(const float* __restrict__ bout,
                                                float* __restrict__ y) {
    extern __shared__ char sm[];
    float* stage = (float*)sm;
    uint32_t sb = smem_u32(sm);
    int tid = threadIdx.x;
    int lane = tid & 31, w = tid >> 5;
    int wm = w & 1, wn = w >> 1;
    int tileM = blockIdx.y, ct = blockIdx.x;
    int row0 = tileM * 128;
    int b = tileM >> 8;

    float acc[4][4][4];
    #pragma unroll
    for (int a = 0; a < 4; a++)
        #pragma unroll
        for (int bb2 = 0; bb2 < 4; bb2++)
            #pragma unroll
            for (int d = 0; d < 4; d++) acc[a][bb2][d] = 0.f;

    auto issue = [&](int c) {
        int p = c % 3, seg = c >> 3, k0 = (c & 7) * 64;
        const __nv_bfloat16* As = (seg == 2) ? g_w_lo : g_w_hi;
        const __nv_bfloat16* Bs = (seg == 1) ? g_weffT_lo : g_weffT_hi;
        #pragma unroll
        for (int i = 0; i < 4; i++) {
            int id = tid + i * 256, r = id >> 3, c8 = (id & 7) * 8;
            cpa16(sb + p*32768 + SWZ((uint32_t)(r*128 + c8*2)),
                  As + (size_t)(row0 + r) * INNER + k0 + c8);
        }
        #pragma unroll
        for (int i = 0; i < 4; i++) {
            int id = tid + i * 256, r = id >> 3, c8 = (id & 7) * 8;
            cpa16(sb + p*32768 + 16384 + SWZ((uint32_t)(r*128 + c8*2)),
                  Bs + (size_t)b * (CC*INNER) + (size_t)(ct*128 + r) * INNER + k0 + c8);
        }
        CP_COMMIT();
    };

    issue(0); issue(1);
    for (int c = 0; c < 24; c++) {
        if (c + 1 < 24) CP_WAIT1(); else CP_WAIT0();
        __syncthreads();
        uint32_t ab = sb + (c % 3) * 32768;
        uint32_t bbs = ab + 16384;
        int rA = lane & 15;
        #pragma unroll
        for (int kk = 0; kk < 4; kk++) {
            uint32_t af[4][4], bf[2][4];
            int kc = kk * 16 + (lane >> 4) * 8;
            #pragma unroll
            for (int mi = 0; mi < 4; mi++)
                ldsm4(af[mi], ab + SWZ((uint32_t)((wm*64 + mi*16 + rA)*128 + kc*2)));
            #pragma unroll
            for (int s = 0; s < 2; s++)
                ldsm4(bf[s], bbs + SWZ((uint32_t)((wn*32 + s*16 + rA)*128 + kc*2)));
            #pragma unroll
            for (int mi = 0; mi < 4; mi++)
                #pragma unroll
                for (int nj = 0; nj < 4; nj++)
                    mma_bf16(acc[mi][nj], af[mi][0], af[mi][1], af[mi][2], af[mi][3],
                             bf[nj>>1][nj&1], bf[nj>>1][(nj&1)+2]);
        }
        if (c + 2 < 24) issue(c + 2);
    }
    __syncthreads();

    #pragma unroll
    for (int mi = 0; mi < 4; mi++)
        #pragma unroll
        for (int nj = 0; nj < 4; nj++) {
            int row = wm*64 + mi*16 + (lane >> 2);
            int col = wn*32 + nj*8 + (lane & 3)*2;
            *(float2*)&stage[row*STG + col]     = make_float2(acc[mi][nj][0], acc[mi][nj][1]);
            *(float2*)&stage[(row+8)*STG + col] = make_float2(acc[mi][nj][2], acc[mi][nj][3]);
        }
    __syncthreads();
    #pragma unroll
    for (int i = 0; i < 16; i++) {
        int lin = tid + i * 256, r = lin >> 5, c4 = (lin & 31) * 4;
        float4 v = *(float4*)&stage[r*STG + c4];
        float4 bv = *(const float4*)&bout[ct*128 + c4];
        v.x += bv.x; v.y += bv.y; v.z += bv.z; v.w += bv.w;
        *(float4*)&y[(size_t)(row0 + r)*CC + ct*128 + c4] = v;
    }
}

// ---------------- launch ----------------
extern "C" void kernel_launch(void* const* d_in, const int* in_sizes, int n_in,
                              void* d_out, int out_size) {
    const float* x    = (const float*)d_in[0];
    const float* Wfx  = (const float*)d_in[1];
    const float* bfx  = (const float*)d_in[2];
    const float* Wx   = (const float*)d_in[3];
    const float* bx   = (const float*)d_in[4];
    const float* Wsl  = (const float*)d_in[5];
    const float* bsl  = (const float*)d_in[6];
    const float* temp = (const float*)d_in[7];
    const float* Wq   = (const float*)d_in[8];
    const float* Wk   = (const float*)d_in[9];
    const float* Wv   = (const float*)d_in[10];
    const float* Wout = (const float*)d_in[11];
    const float* bout = (const float*)d_in[12];
    float* y = (float*)d_out;

    cudaFuncSetAttribute(k_proj,  cudaFuncAttributeMaxDynamicSharedMemorySize, GSMEM);
    cudaFuncSetAttribute(k_poolg, cudaFuncAttributeMaxDynamicSharedMemorySize, PGSMEM);
    cudaFuncSetAttribute(k_out,   cudaFuncAttributeMaxDynamicSharedMemorySize, GSMEM);

    k_zero<<<2048, 256>>>();
    k_prep<<<CC, 512>>>(Wx, bx, Wsl, bsl);
    k_split<<<dim3(TOK/64, 4), 256>>>(x);
    k_proj<<<dim3(4, TOK/128), 256, GSMEM>>>(temp);
    k_poolg<<<dim3(32, 16, 2), 256, PGSMEM>>>();
    k_stat<<<32, 256>>>(Wfx, bfx, Wq, Wk, Wv);
    k_weff<<<2048, 256>>>(Wout);
    k_out<<<dim3(2, TOK/128), 256, GSMEM>>>(bout, y);
}

// round 11
// speedup vs baseline: 1.4216x; 1.2212x over previous
#include <cuda_runtime.h>
#include <cuda_fp16.h>
#include <cstdint>

#define BB 4
#define NTOK 32768
#define CC 256
#define HH 8
#define DD 64
#define GG 64
#define INNER 512
#define TOK (BB*NTOK)   // 131072

// ---------------- scratch (device globals; no runtime allocation) ----------------
__device__ __align__(16) __half g_x_hi[(size_t)TOK*CC];      // x fp16 hi [tok][c]
__device__ __align__(16) __half g_xT_hi[(size_t)BB*CC*NTOK]; // x^T hi [b][c][n]
__device__ __align__(16) __half g_xT_lo[(size_t)BB*CC*NTOK]; // x^T lo
__device__ __align__(16) __half g_w_hi[(size_t)TOK*INNER];   // slice weights fp16 [tok][hg]
__device__ __align__(16) __half g_wT_hi[(size_t)BB*HH*GG*NTOK]; // w^T fp16 [bh][g][n]
__device__ __align__(16) __half g_wslT_hi[INNER*CC];         // (Wx@Wslice)^T hi
__device__ __align__(16) __half g_wslT_lo[INNER*CC];         // lo
__device__ float g_bsl[INNER];                    // folded slice bias
__device__ float g_P[BB*HH*GG*CC];                // pooled P[bh][g][c] (atomic accum)
__device__ float g_norm[BB*HH*GG];                // weight column sums
__device__ float g_os[BB*HH*GG*DD];               // out_slice
__device__ __align__(16) __half g_weffT_hi[BB*CC*INNER];     // W_eff^T hi [b][c][hg]
__device__ __align__(16) __half g_weffT_lo[BB*CC*INNER];     // lo

// ============================ helpers ============================
#define DINLINE __device__ __forceinline__

DINLINE uint32_t smem_u32(const void* p) {
    uint32_t a;
    asm("{ .reg .u64 t; cvta.to.shared.u64 t, %1; cvt.u32.u64 %0, t; }" : "=r"(a) : "l"(p));
    return a;
}
DINLINE void cpa16(uint32_t dst, const void* src) {
    asm volatile("cp.async.cg.shared.global [%0], [%1], 16;" :: "r"(dst), "l"(src));
}
#define CP_COMMIT() asm volatile("cp.async.commit_group;" ::: "memory")
#define CP_WAIT2()  asm volatile("cp.async.wait_group 2;" ::: "memory")
#define CP_WAIT1()  asm volatile("cp.async.wait_group 1;" ::: "memory")
#define CP_WAIT0()  asm volatile("cp.async.wait_group 0;" ::: "memory")

DINLINE void ldsm4(uint32_t* r, uint32_t addr) {
    asm volatile("ldmatrix.sync.aligned.m8n8.x4.shared.b16 {%0,%1,%2,%3}, [%4];"
        : "=r"(r[0]), "=r"(r[1]), "=r"(r[2]), "=r"(r[3]) : "r"(addr));
}
DINLINE void mma_f16(float* d, uint32_t a0, uint32_t a1, uint32_t a2, uint32_t a3,
                     uint32_t b0, uint32_t b1) {
    asm volatile("mma.sync.aligned.m16n8k16.row.col.f32.f16.f16.f32 "
        "{%0,%1,%2,%3}, {%4,%5,%6,%7}, {%8,%9}, {%0,%1,%2,%3};"
        : "+f"(d[0]), "+f"(d[1]), "+f"(d[2]), "+f"(d[3])
        : "r"(a0), "r"(a1), "r"(a2), "r"(a3), "r"(b0), "r"(b1));
}
DINLINE uint32_t pack_h2(float a, float b) {
    __half2 h = __floats2half2_rn(a, b);
    return *reinterpret_cast<uint32_t*>(&h);
}
#define SWZ(off) ((off) ^ (((off) >> 3) & 0x70))
#define STG 132        // stage row stride (floats)
#define GSMEM 98304    // 3 stages x (16KB A + 16KB B)
#define PGSMEM 98304   // 4 stages x (8KB A + 16KB B)

// ---------------- zero accumulators (must run every graph replay) ----------------
__global__ void k_zero() {
    int i = blockIdx.x * blockDim.x + threadIdx.x;
    if (i < BB*HH*GG*CC) g_P[i] = 0.f;
    if (i < BB*HH*GG)    g_norm[i] = 0.f;
}

// ---------------- split x into fp16 hi ([tok][c]) and hi/lo transposed ----------------
__global__ void k_split(const float* __restrict__ x) {
    __shared__ uint16_t shi[64][68], slo[64][68];
    int tid = threadIdx.x;
    size_t t0 = (size_t)blockIdx.x * 64;     // token tile
    int c0 = blockIdx.y * 64;                // c tile
    int r = tid >> 2, cq = (tid & 3) * 16;
    #pragma unroll
    for (int j = 0; j < 16; j += 4) {
        float4 v = *(const float4*)&x[(t0 + r) * CC + c0 + cq + j];
        __half hx = __float2half_rn(v.x), hy = __float2half_rn(v.y);
        __half hz = __float2half_rn(v.z), hw = __float2half_rn(v.w);
        uint2 uh, ul;
        uh.x = pack_h2(v.x, v.y);  // (round-trips through half2 rn)
        uh.y = pack_h2(v.z, v.w);
        ul.x = pack_h2(v.x - __half2float(hx), v.y - __half2float(hy));
        ul.y = pack_h2(v.z - __half2float(hz), v.w - __half2float(hw));
        *(uint2*)&g_x_hi[(t0 + r) * CC + c0 + cq + j] = uh;
        *(uint2*)&shi[r][cq + j] = uh;
        *(uint2*)&slo[r][cq + j] = ul;
    }
    __syncthreads();
    int c = tid >> 2, tq = (tid & 3) * 16;
    size_t b = t0 >> 15;                 // /NTOK
    size_t nloc = t0 & (NTOK - 1);
    size_t base = ((size_t)b * CC + c0 + c) * NTOK + nloc + tq;
    #pragma unroll
    for (int j = 0; j < 16; j += 2) {
        uint32_t hv = (uint32_t)shi[tq + j][c] | ((uint32_t)shi[tq + j + 1][c] << 16);
        uint32_t lv = (uint32_t)slo[tq + j][c] | ((uint32_t)slo[tq + j + 1][c] << 16);
        *(uint32_t*)&g_xT_hi[base + j] = hv;
        *(uint32_t*)&g_xT_lo[base + j] = lv;
    }
}

// ---------------- fold + transpose + fp16-split slice weight ----------------
__global__ void k_prep(const float* __restrict__ Wx, const float* __restrict__ bx,
                       const float* __restrict__ Wsl, const float* __restrict__ bsl) {
    int c = blockIdx.x;        // K index 0..255
    int o = threadIdx.x;       // N index 0..511
    int h = o >> 6, gg = o & 63;
    float s = 0.f;
    #pragma unroll 16
    for (int d = 0; d < 64; d++)
        s += Wx[c*INNER + h*64 + d] * Wsl[d*64 + gg];
    __half sh = __float2half_rn(s);
    g_wslT_hi[o*CC + c] = sh;
    g_wslT_lo[o*CC + c] = __float2half_rn(s - __half2float(sh));
    if (c == 0) {
        float t = 0.f;
        #pragma unroll 16
        for (int d = 0; d < 64; d++) t += bx[h*64 + d] * Wsl[d*64 + gg];
        g_bsl[o] = t + bsl[gg];
    }
}

// ---------------- slice-logits GEMM + softmax (mma.sync, fp16 2-seg) ----------------
// block M128 x N128, K=256 x 2 segments (8 chunks of 64): xhi*Bhi + xhi*Blo.
// grid (4, 1024).
__global__ __launch_bounds__(256, 2) void k_proj(const float* __restrict__ temp) {
    extern __shared__ char sm[];
    float* stage = (float*)sm;
    uint32_t sb = smem_u32(sm);
    int tid = threadIdx.x;
    int lane = tid & 31, w = tid >> 5;
    int wm = w & 1, wn = w >> 1;
    int tileM = blockIdx.y, y2 = blockIdx.x;
    int row0 = tileM * 128;
    int b = tileM >> 8;
    size_t row0loc = (size_t)(tileM & 255) * 128;

    float acc[4][4][4];
    #pragma unroll
    for (int a = 0; a < 4; a++)
        #pragma unroll
        for (int b2 = 0; b2 < 4; b2++)
            #pragma unroll
            for (int d = 0; d < 4; d++) acc[a][b2][d] = 0.f;

    auto issue = [&](int c) {
        int p = c % 3, seg = c >> 2, k0 = (c & 3) * 64;
        const __half* Bs = (seg == 1) ? g_wslT_lo : g_wslT_hi;
        #pragma unroll
        for (int i = 0; i < 4; i++) {
            int id = tid + i * 256, r = id >> 3, c8 = (id & 7) * 8;
            cpa16(sb + p*32768 + SWZ((uint32_t)(r*128 + c8*2)),
                  g_x_hi + (size_t)(row0 + r) * CC + k0 + c8);
        }
        #pragma unroll
        for (int i = 0; i < 4; i++) {
            int id = tid + i * 256, r = id >> 3, c8 = (id & 7) * 8;
            cpa16(sb + p*32768 + 16384 + SWZ((uint32_t)(r*128 + c8*2)),
                  Bs + (size_t)(y2*128 + r) * CC + k0 + c8);
        }
        CP_COMMIT();
    };

    issue(0); issue(1);
    for (int c = 0; c < 8; c++) {
        if (c + 1 < 8) CP_WAIT1(); else CP_WAIT0();
        __syncthreads();
        uint32_t ab = sb + (c % 3) * 32768;
        uint32_t bb = ab + 16384;
        int rA = lane & 15;
        #pragma unroll
        for (int kk = 0; kk < 4; kk++) {
            uint32_t af[4][4], bf[2][4];
            int kc = kk * 16 + (lane >> 4) * 8;
            #pragma unroll
            for (int mi = 0; mi < 4; mi++)
                ldsm4(af[mi], ab + SWZ((uint32_t)((wm*64 + mi*16 + rA)*128 + kc*2)));
            #pragma unroll
            for (int s = 0; s < 2; s++)
                ldsm4(bf[s], bb + SWZ((uint32_t)((wn*32 + s*16 + rA)*128 + kc*2)));
            #pragma unroll
            for (int mi = 0; mi < 4; mi++)
                #pragma unroll
                for (int nj = 0; nj < 4; nj++)
                    mma_f16(acc[mi][nj], af[mi][0], af[mi][1], af[mi][2], af[mi][3],
                            bf[nj>>1][nj&1], bf[nj>>1][(nj&1)+2]);
        }
        if (c + 2 < 8) issue(c + 2);
    }
    __syncthreads();

    // frags -> stage
    #pragma unroll
    for (int mi = 0; mi < 4; mi++)
        #pragma unroll
        for (int nj = 0; nj < 4; nj++) {
            int row = wm*64 + mi*16 + (lane >> 2);
            int col = wn*32 + nj*8 + (lane & 3)*2;
            *(float2*)&stage[row*STG + col]     = make_float2(acc[mi][nj][0], acc[mi][nj][1]);
            *(float2*)&stage[(row+8)*STG + col] = make_float2(acc[mi][nj][2], acc[mi][nj][3]);
        }
    __syncthreads();

    // softmax over each head's 64 cols per row
    float rt0 = 1.0f / fminf(fmaxf(temp[y2*2 + 0], 0.1f), 5.0f);
    float rt1 = 1.0f / fminf(fmaxf(temp[y2*2 + 1], 0.1f), 5.0f);
    for (int gi = 0; gi < 32; gi++) {
        int G = w * 32 + gi;
        int r = G >> 1, hh = G & 1;
        float bb0 = g_bsl[y2*128 + hh*64 + lane];
        float bb1 = g_bsl[y2*128 + hh*64 + 32 + lane];
        float rt = hh ? rt1 : rt0;
        float v0 = (stage[r*STG + hh*64 + lane]      + bb0) * rt;
        float v1 = (stage[r*STG + hh*64 + 32 + lane] + bb1) * rt;
        float m = fmaxf(v0, v1);
        #pragma unroll
        for (int o = 16; o; o >>= 1) m = fmaxf(m, __shfl_xor_sync(0xFFFFFFFFu, m, o));
        float e0 = __expf(v0 - m), e1 = __expf(v1 - m);
        float s = e0 + e1;
        #pragma unroll
        for (int o = 16; o; o >>= 1) s += __shfl_xor_sync(0xFFFFFFFFu, s, o);
        float rs = 1.0f / s;
        stage[r*STG + hh*64 + lane]      = e0 * rs;
        stage[r*STG + hh*64 + 32 + lane] = e1 * rs;
    }
    __syncthreads();

    // (a) norm: column sums -> atomic
    if (tid < 128) {
        float s = 0.f;
        #pragma unroll 8
        for (int r = 0; r < 128; r++) s += stage[r*STG + tid];
        int head = tid >> 6, g = tid & 63;
        atomicAdd(&g_norm[(b*8 + y2*2 + head)*64 + g], s);
    }
    // (b) w fp16 [tok][hg]  (coalesced 8B chunks)
    #pragma unroll
    for (int i = 0; i < 16; i++) {
        int lin = tid + i * 256, r = lin >> 5, c4 = (lin & 31) * 4;
        float4 v = *(float4*)&stage[r*STG + c4];
        uint2 uh;
        uh.x = pack_h2(v.x, v.y);
        uh.y = pack_h2(v.z, v.w);
        *(uint2*)&g_w_hi[(size_t)(row0 + r)*INNER + y2*128 + c4] = uh;
    }
    // (c) w^T fp16 [bh][g][n] — coalesced: thread owns (head,g) row-half
    {
        int G2 = tid >> 1, half = tid & 1;
        int head = G2 >> 6, g = G2 & 63;
        size_t basew = ((size_t)(b*8 + y2*2 + head) * 64 + g) * (size_t)NTOK
                       + row0loc + half * 64;
        #pragma unroll
        for (int t = 0; t < 64; t += 2) {
            float v0 = stage[(half*64 + t)     * STG + G2];
            float v1 = stage[(half*64 + t + 1) * STG + G2];
            *(uint32_t*)&g_wT_hi[basew + t] = pack_h2(v0, v1);
        }
    }
}

// ---------------- pooling GEMM: P[bh][g][c] = sum_n w[n,g]*x[n,c] ----------------
// block M64(g) x N128(c), grid (32 bh, 16 kc, 2 cb). 64 chunks (2 segs x 32).
// segs: whi*xhi + whi*xlo. 4-stage cp.async.
__global__ __launch_bounds__(256, 2) void k_poolg() {
    extern __shared__ char sm[];
    uint32_t sb = smem_u32(sm);
    int tid = threadIdx.x;
    int lane = tid & 31, w = tid >> 5;
    int wm = w & 1, wn = w >> 1;
    int bh = blockIdx.x, kc = blockIdx.y, cb = blockIdx.z;
    int b = bh >> 3;
    size_t nbase = (size_t)kc * 2048;
    const __half* Ahi = g_wT_hi + (size_t)bh * 64 * NTOK;
    const __half* Bhi = g_xT_hi + ((size_t)b * CC + cb * 128) * NTOK;
    const __half* Blo = g_xT_lo + ((size_t)b * CC + cb * 128) * NTOK;

    float acc[2][4][4];
    #pragma unroll
    for (int a = 0; a < 2; a++)
        #pragma unroll
        for (int b2 = 0; b2 < 4; b2++)
            #pragma unroll
            for (int d = 0; d < 4; d++) acc[a][b2][d] = 0.f;

    auto issue = [&](int c) {
        int p = c & 3, seg = c >> 5, k0 = (c & 31) * 64;
        const __half* Bs = (seg == 1) ? Blo : Bhi;
        #pragma unroll
        for (int i = 0; i < 2; i++) {
            int id = tid + i * 256, r = id >> 3, c8 = (id & 7) * 8;
            cpa16(sb + p*24576 + SWZ((uint32_t)(r*128 + c8*2)),
                  Ahi + (size_t)r * NTOK + nbase + k0 + c8);
        }
        #pragma unroll
        for (int i = 0; i < 4; i++) {
            int id = tid + i * 256, r = id >> 3, c8 = (id & 7) * 8;
            cpa16(sb + p*24576 + 8192 + SWZ((uint32_t)(r*128 + c8*2)),
                  Bs + (size_t)r * NTOK + nbase + k0 + c8);
        }
        CP_COMMIT();
    };

    issue(0); issue(1); issue(2);
    for (int c = 0; c < 64; c++) {
        if (c + 2 < 64) CP_WAIT2(); else if (c + 1 < 64) CP_WAIT1(); else CP_WAIT0();
        __syncthreads();
        uint32_t ab = sb + (c & 3) * 24576;
        uint32_t bb = ab + 8192;
        int rA = lane & 15;
        #pragma unroll
        for (int kk = 0; kk < 4; kk++) {
            uint32_t af[2][4], bf[2][4];
            int kc2 = kk * 16 + (lane >> 4) * 8;
            #pragma unroll
            for (int mi = 0; mi < 2; mi++)
                ldsm4(af[mi], ab + SWZ((uint32_t)((wm*32 + mi*16 + rA)*128 + kc2*2)));
            #pragma unroll
            for (int s = 0; s < 2; s++)
                ldsm4(bf[s], bb + SWZ((uint32_t)((wn*32 + s*16 + rA)*128 + kc2*2)));
            #pragma unroll
            for (int mi = 0; mi < 2; mi++)
                #pragma unroll
                for (int nj = 0; nj < 4; nj++)
                    mma_f16(acc[mi][nj], af[mi][0], af[mi][1], af[mi][2], af[mi][3],
                            bf[nj>>1][nj&1], bf[nj>>1][(nj&1)+2]);
        }
        if (c + 3 < 64) issue(c + 3);
    }

    #pragma unroll
    for (int mi = 0; mi < 2; mi++)
        #pragma unroll
        for (int nj = 0; nj < 4; nj++) {
            int row = wm*32 + mi*16 + (lane >> 2);
            int col = cb*128 + wn*32 + nj*8 + (lane & 3)*2;
            int base = bh*16384 + row*256 + col;
            atomicAdd(&g_P[base],            acc[mi][nj][0]);
            atomicAdd(&g_P[base + 1],        acc[mi][nj][1]);
            atomicAdd(&g_P[base + 8*256],    acc[mi][nj][2]);
            atomicAdd(&g_P[base + 8*256 + 1],acc[mi][nj][3]);
        }
}

// ---------------- fused: ST = P@Wfx + bfx*norm ; tiny attention -> g_os ----------------
__global__ void k_stat(const float* __restrict__ Wfx, const float* __restrict__ bfx,
                       const float* __restrict__ Wq, const float* __restrict__ Wk,
                       const float* __restrict__ Wv) {
    int bh = blockIdx.x;
    int h = bh & 7;
    int tid = threadIdx.x;
    __shared__ float bufA[64][65], bufB[64][65];
    __shared__ float nrmc[64];

    float acc[16];
    #pragma unroll
    for (int j = 0; j < 16; j++) acc[j] = 0.f;
    int g = tid >> 2, dq = tid & 3;
    for (int c0 = 0; c0 < 4; c0++) {
        #pragma unroll
        for (int i = 0; i < 16; i++) {
            int id = tid + i * 256;
            int r = id >> 6, cl = id & 63;
            bufA[r][cl] = Wfx[(c0*64 + r) * INNER + h*64 + cl];
            bufB[r][cl] = g_P[bh*16384 + r*256 + c0*64 + cl];
        }
        __syncthreads();
        for (int cl = 0; cl < 64; cl++) {
            float pv = bufB[g][cl];
            #pragma unroll
            for (int j = 0; j < 16; j++)
                acc[j] += pv * bufA[cl][dq*16 + j];
        }
        __syncthreads();
    }
    if (tid < 64) nrmc[tid] = g_norm[bh*64 + tid];
    __syncthreads();
    {
        float nrm = nrmc[g];
        float rdiv = 1.0f / (nrm + 1e-5f);
        #pragma unroll
        for (int j = 0; j < 16; j++) {
            int d = dq*16 + j;
            bufA[g][d] = (acc[j] + bfx[h*64 + d] * nrm) * rdiv;
        }
    }
    __syncthreads();

    #pragma unroll
    for (int it = 0; it < 16; it++) {
        int idx = tid + it * 256;
        int g2 = idx >> 6, d2 = idx & 63;
        float s0 = 0, s1 = 0, s2 = 0, s3 = 0;
        #pragma unroll
        for (int d = 0; d < 64; d += 4) {
            s0 += bufA[g2][d]   * Wk[(d)   * 64 + d2];
            s1 += bufA[g2][d+1] * Wk[(d+1) * 64 + d2];
            s2 += bufA[g2][d+2] * Wk[(d+2) * 64 + d2];
            s3 += bufA[g2][d+3] * Wk[(d+3) * 64 + d2];
        }
        bufB[g2][d2] = (s0 + s1) + (s2 + s3);
    }
    __syncthreads();
    float tv[64];
    if (tid < 64) {
        int g2 = tid;
        float q[64];
        #pragma unroll
        for (int d2 = 0; d2 < 64; d2++) {
            float s0 = 0, s1 = 0, s2 = 0, s3 = 0;
            #pragma unroll
            for (int d = 0; d < 64; d += 4) {
                s0 += bufA[g2][d]   * Wq[(d)   * 64 + d2];
                s1 += bufA[g2][d+1] * Wq[(d+1) * 64 + d2];
                s2 += bufA[g2][d+2] * Wq[(d+2) * 64 + d2];
                s3 += bufA[g2][d+3] * Wq[(d+3) * 64 + d2];
            }
            q[d2] = (s0 + s1) + (s2 + s3);
        }
        float p[64];
        float mx = -1e30f;
        #pragma unroll
        for (int j = 0; j < 64; j++) {
            float s0 = 0, s1 = 0, s2 = 0, s3 = 0;
            #pragma unroll
            for (int d = 0; d < 64; d += 4) {
                s0 += q[d]   * bufB[j][d];
                s1 += q[d+1] * bufB[j][d+1];
                s2 += q[d+2] * bufB[j][d+2];
                s3 += q[d+3] * bufB[j][d+3];
            }
            float s = ((s0 + s1) + (s2 + s3)) * 0.125f;
            p[j] = s;
            mx = fmaxf(mx, s);
        }
        float sum = 0.f;
        #pragma unroll
        for (int j = 0; j < 64; j++) { p[j] = __expf(p[j] - mx); sum += p[j]; }
        float rs = 1.0f / sum;
        #pragma unroll
        for (int e = 0; e < 64; e++) {
            float s0 = 0, s1 = 0, s2 = 0, s3 = 0;
            #pragma unroll
            for (int j = 0; j < 64; j += 4) {
                s0 += p[j]   * bufA[j][e];
                s1 += p[j+1] * bufA[j+1][e];
                s2 += p[j+2] * bufA[j+2][e];
                s3 += p[j+3] * bufA[j+3][e];
            }
            tv[e] = ((s0 + s1) + (s2 + s3)) * rs;
        }
    }
    __syncthreads();
    if (tid < 64) {
        #pragma unroll
        for (int e = 0; e < 64; e++) bufB[tid][e] = tv[e];
    }
    __syncthreads();
    #pragma unroll
    for (int it = 0; it < 16; it++) {
        int idx = tid + it * 256;
        int g2 = idx >> 6, d2 = idx & 63;
        float s0 = 0, s1 = 0, s2 = 0, s3 = 0;
        #pragma unroll
        for (int e = 0; e < 64; e += 4) {
            s0 += bufB[g2][e]   * Wv[(e)   * 64 + d2];
            s1 += bufB[g2][e+1] * Wv[(e+1) * 64 + d2];
            s2 += bufB[g2][e+2] * Wv[(e+2) * 64 + d2];
            s3 += bufB[g2][e+3] * Wv[(e+3) * 64 + d2];
        }
        g_os[bh * 4096 + idx] = (s0 + s1) + (s2 + s3);
    }
}

// ---------------- fold out_slice into W_out: W_eff^T fp16 pair [b][c][hg] ----------------
__global__ void k_weff(const float* __restrict__ Wout) {
    int blk = blockIdx.x;           // b*512 + row
    int b = blk >> 9;
    int row = blk & 511;            // k index: h*64+g
    int h = row >> 6;
    int tid = threadIdx.x;          // n index = c (256)
    __shared__ float osr[64];
    if (tid < 64) osr[tid] = g_os[(b*8 + h) * 4096 + (row & 63) * 64 + tid];
    __syncthreads();
    float s = 0.f;
    #pragma unroll 16
    for (int d = 0; d < 64; d++)
        s += osr[d] * Wout[(h*64 + d) * CC + tid];
    __half sh = __float2half_rn(s);
    size_t idx = (size_t)b * (CC*INNER) + (size_t)tid * INNER + row;
    g_weffT_hi[idx] = sh;
    g_weffT_lo[idx] = __float2half_rn(s - __half2float(sh));
}

// ---------------- output GEMM: y = w @ W_eff[b] + b_out (fp16 2-seg) ----------------
// block M128 x N128, K=512 x 2 segments (16 chunks). grid (2, 1024): ct fast-varying.
__global__ __launch_bounds__(256, 2) void k_out(const float* __restrict__ bout,
                                                float* __restrict__ y) {
    extern __shared__ char sm[];
    float* stage = (float*)sm;
    uint32_t sb = smem_u32(sm);
    int tid = threadIdx.x;
    int lane = tid & 31, w = tid >> 5;
    int wm = w & 1, wn = w >> 1;
    int tileM = blockIdx.y, ct = blockIdx.x;
    int row0 = tileM * 128;
    int b = tileM >> 8;

    float acc[4][4][4];
    #pragma unroll
    for (int a = 0; a < 4; a++)
        #pragma unroll
        for (int bb2 = 0; bb2 < 4; bb2++)
            #pragma unroll
            for (int d = 0; d < 4; d++) acc[a][bb2][d] = 0.f;

    auto issue = [&](int c) {
        int p = c % 3, seg = c >> 3, k0 = (c & 7) * 64;
        const __half* Bs = (seg == 1) ? g_weffT_lo : g_weffT_hi;
        #pragma unroll
        for (int i = 0; i < 4; i++) {
            int id = tid + i * 256, r = id >> 3, c8 = (id & 7) * 8;
            cpa16(sb + p*32768 + SWZ((uint32_t)(r*128 + c8*2)),
                  g_w_hi + (size_t)(row0 + r) * INNER + k0 + c8);
        }
        #pragma unroll
        for (int i = 0; i < 4; i++) {
            int id = tid + i * 256, r = id >> 3, c8 = (id & 7) * 8;
            cpa16(sb + p*32768 + 16384 + SWZ((uint32_t)(r*128 + c8*2)),
                  Bs + (size_t)b * (CC*INNER) + (size_t)(ct*128 + r) * INNER + k0 + c8);
        }
        CP_COMMIT();
    };

    issue(0); issue(1);
    for (int c = 0; c < 16; c++) {
        if (c + 1 < 16) CP_WAIT1(); else CP_WAIT0();
        __syncthreads();
        uint32_t ab = sb + (c % 3) * 32768;
        uint32_t bbs = ab + 16384;
        int rA = lane & 15;
        #pragma unroll
        for (int kk = 0; kk < 4; kk++) {
            uint32_t af[4][4], bf[2][4];
            int kc = kk * 16 + (lane >> 4) * 8;
            #pragma unroll
            for (int mi = 0; mi < 4; mi++)
                ldsm4(af[mi], ab + SWZ((uint32_t)((wm*64 + mi*16 + rA)*128 + kc*2)));
            #pragma unroll
            for (int s = 0; s < 2; s++)
                ldsm4(bf[s], bbs + SWZ((uint32_t)((wn*32 + s*16 + rA)*128 + kc*2)));
            #pragma unroll
            for (int mi = 0; mi < 4; mi++)
                #pragma unroll
                for (int nj = 0; nj < 4; nj++)
                    mma_f16(acc[mi][nj], af[mi][0], af[mi][1], af[mi][2], af[mi][3],
                            bf[nj>>1][nj&1], bf[nj>>1][(nj&1)+2]);
        }
        if (c + 2 < 16) issue(c + 2);
    }
    __syncthreads();

    #pragma unroll
    for (int mi = 0; mi < 4; mi++)
        #pragma unroll
        for (int nj = 0; nj < 4; nj++) {
            int row = wm*64 + mi*16 + (lane >> 2);
            int col = wn*32 + nj*8 + (lane & 3)*2;
            *(float2*)&stage[row*STG + col]     = make_float2(acc[mi][nj][0], acc[mi][nj][1]);
            *(float2*)&stage[(row+8)*STG + col] = make_float2(acc[mi][nj][2], acc[mi][nj][3]);
        }
    __syncthreads();
    #pragma unroll
    for (int i = 0; i < 16; i++) {
        int lin = tid + i * 256, r = lin >> 5, c4 = (lin & 31) * 4;
        float4 v = *(float4*)&stage[r*STG + c4];
        float4 bv = *(const float4*)&bout[ct*128 + c4];
        v.x += bv.x; v.y += bv.y; v.z += bv.z; v.w += bv.w;
        *(float4*)&y[(size_t)(row0 + r)*CC + ct*128 + c4] = v;
    }
}

// ---------------- launch ----------------
extern "C" void kernel_launch(void* const* d_in, const int* in_sizes, int n_in,
                              void* d_out, int out_size) {
    const float* x    = (const float*)d_in[0];
    const float* Wfx  = (const float*)d_in[1];
    const float* bfx  = (const float*)d_in[2];
    const float* Wx   = (const float*)d_in[3];
    const float* bx   = (const float*)d_in[4];
    const float* Wsl  = (const float*)d_in[5];
    const float* bsl  = (const float*)d_in[6];
    const float* temp = (const float*)d_in[7];
    const float* Wq   = (const float*)d_in[8];
    const float* Wk   = (const float*)d_in[9];
    const float* Wv   = (const float*)d_in[10];
    const float* Wout = (const float*)d_in[11];
    const float* bout = (const float*)d_in[12];
    float* y = (float*)d_out;

    cudaFuncSetAttribute(k_proj,  cudaFuncAttributeMaxDynamicSharedMemorySize, GSMEM);
    cudaFuncSetAttribute(k_poolg, cudaFuncAttributeMaxDynamicSharedMemorySize, PGSMEM);
    cudaFuncSetAttribute(k_out,   cudaFuncAttributeMaxDynamicSharedMemorySize, GSMEM);

    k_zero<<<2048, 256>>>();
    k_prep<<<CC, 512>>>(Wx, bx, Wsl, bsl);
    k_split<<<dim3(TOK/64, 4), 256>>>(x);
    k_proj<<<dim3(4, TOK/128), 256, GSMEM>>>(temp);
    k_poolg<<<dim3(32, 16, 2), 256, PGSMEM>>>();
    k_stat<<<32, 256>>>(Wfx, bfx, Wq, Wk, Wv);
    k_weff<<<2048, 256>>>(Wout);
    k_out<<<dim3(2, TOK/128), 256, GSMEM>>>(bout, y);
}

// round 12
// speedup vs baseline: 1.4465x; 1.0175x over previous
#include <cuda_runtime.h>
#include <cuda_fp16.h>
#include <cstdint>

#define BB 4
#define NTOK 32768
#define CC 256
#define HH 8
#define DD 64
#define GG 64
#define INNER 512
#define TOK (BB*NTOK)   // 131072

// ---------------- scratch (device globals; no runtime allocation) ----------------
__device__ __align__(16) __half g_x_hi[(size_t)TOK*CC];      // x fp16 hi [tok][c]
__device__ __align__(16) __half g_xT_hi[(size_t)BB*CC*NTOK]; // x^T hi [b][c][n]
__device__ __align__(16) __half g_xT_lo[(size_t)BB*CC*NTOK]; // x^T lo
__device__ __align__(16) __half g_w_hi[(size_t)TOK*INNER];   // slice weights fp16 [tok][hg]
__device__ __align__(16) __half g_wT_hi[(size_t)BB*HH*GG*NTOK]; // w^T fp16 [bh][g][n]
__device__ __align__(16) __half g_wslT_hi[INNER*CC];         // (Wx@Wslice)^T hi
__device__ __align__(16) __half g_wslT_lo[INNER*CC];         // lo
__device__ float g_bsl[INNER];                    // folded slice bias
__device__ float g_P[BB*HH*GG*CC];                // pooled P[bh][g][c] (atomic accum)
__device__ float g_norm[BB*HH*GG];                // weight column sums
__device__ float g_os[BB*HH*GG*DD];               // out_slice
__device__ __align__(16) __half g_weffT_hi[BB*CC*INNER];     // W_eff^T hi [b][c][hg]
__device__ __align__(16) __half g_weffT_lo[BB*CC*INNER];     // lo

// ============================ helpers ============================
#define DINLINE __device__ __forceinline__

DINLINE uint32_t smem_u32(const void* p) {
    uint32_t a;
    asm("{ .reg .u64 t; cvta.to.shared.u64 t, %1; cvt.u32.u64 %0, t; }" : "=r"(a) : "l"(p));
    return a;
}
DINLINE void cpa16(uint32_t dst, const void* src) {
    asm volatile("cp.async.cg.shared.global [%0], [%1], 16;" :: "r"(dst), "l"(src));
}
#define CP_COMMIT() asm volatile("cp.async.commit_group;" ::: "memory")
#define CP_WAIT2()  asm volatile("cp.async.wait_group 2;" ::: "memory")
#define CP_WAIT1()  asm volatile("cp.async.wait_group 1;" ::: "memory")
#define CP_WAIT0()  asm volatile("cp.async.wait_group 0;" ::: "memory")

DINLINE void ldsm4(uint32_t* r, uint32_t addr) {
    asm volatile("ldmatrix.sync.aligned.m8n8.x4.shared.b16 {%0,%1,%2,%3}, [%4];"
        : "=r"(r[0]), "=r"(r[1]), "=r"(r[2]), "=r"(r[3]) : "r"(addr));
}
DINLINE void mma_f16(float* d, uint32_t a0, uint32_t a1, uint32_t a2, uint32_t a3,
                     uint32_t b0, uint32_t b1) {
    asm volatile("mma.sync.aligned.m16n8k16.row.col.f32.f16.f16.f32 "
        "{%0,%1,%2,%3}, {%4,%5,%6,%7}, {%8,%9}, {%0,%1,%2,%3};"
        : "+f"(d[0]), "+f"(d[1]), "+f"(d[2]), "+f"(d[3])
        : "r"(a0), "r"(a1), "r"(a2), "r"(a3), "r"(b0), "r"(b1));
}
DINLINE uint32_t pack_h2(float a, float b) {
    __half2 h = __floats2half2_rn(a, b);
    return *reinterpret_cast<uint32_t*>(&h);
}
#define SWZ(off) ((off) ^ (((off) >> 3) & 0x70))
#define STG 132        // stage row stride (floats)
#define GSMEM 98304    // 3 stages x (16KB A + 16KB B)
#define PGSMEM 98304   // 4 stages x (8KB A + 16KB B)

// ---------------- zero accumulators (must run every graph replay) ----------------
__global__ void k_zero() {
    int i = blockIdx.x * blockDim.x + threadIdx.x;
    if (i < BB*HH*GG*CC) g_P[i] = 0.f;
    if (i < BB*HH*GG)    g_norm[i] = 0.f;
}

// ---------------- split x into fp16 hi ([tok][c]) and hi/lo transposed ----------------
__global__ void k_split(const float* __restrict__ x) {
    __shared__ uint16_t shi[64][68], slo[64][68];
    int tid = threadIdx.x;
    size_t t0 = (size_t)blockIdx.x * 64;     // token tile
    int c0 = blockIdx.y * 64;                // c tile
    int r = tid >> 2, cq = (tid & 3) * 16;
    #pragma unroll
    for (int j = 0; j < 16; j += 4) {
        float4 v = *(const float4*)&x[(t0 + r) * CC + c0 + cq + j];
        __half hx = __float2half_rn(v.x), hy = __float2half_rn(v.y);
        __half hz = __float2half_rn(v.z), hw = __float2half_rn(v.w);
        uint2 uh, ul;
        uh.x = pack_h2(v.x, v.y);
        uh.y = pack_h2(v.z, v.w);
        ul.x = pack_h2(v.x - __half2float(hx), v.y - __half2float(hy));
        ul.y = pack_h2(v.z - __half2float(hz), v.w - __half2float(hw));
        *(uint2*)&g_x_hi[(t0 + r) * CC + c0 + cq + j] = uh;
        *(uint2*)&shi[r][cq + j] = uh;
        *(uint2*)&slo[r][cq + j] = ul;
    }
    __syncthreads();
    int c = tid >> 2, tq = (tid & 3) * 16;
    size_t b = t0 >> 15;                 // /NTOK
    size_t nloc = t0 & (NTOK - 1);
    size_t base = ((size_t)b * CC + c0 + c) * NTOK + nloc + tq;
    #pragma unroll
    for (int j = 0; j < 16; j += 2) {
        uint32_t hv = (uint32_t)shi[tq + j][c] | ((uint32_t)shi[tq + j + 1][c] << 16);
        uint32_t lv = (uint32_t)slo[tq + j][c] | ((uint32_t)slo[tq + j + 1][c] << 16);
        *(uint32_t*)&g_xT_hi[base + j] = hv;
        *(uint32_t*)&g_xT_lo[base + j] = lv;
    }
}

// ---------------- fold + transpose + fp16-split slice weight ----------------
__global__ void k_prep(const float* __restrict__ Wx, const float* __restrict__ bx,
                       const float* __restrict__ Wsl, const float* __restrict__ bsl) {
    int c = blockIdx.x;        // K index 0..255
    int o = threadIdx.x;       // N index 0..511
    int h = o >> 6, gg = o & 63;
    float s = 0.f;
    #pragma unroll 16
    for (int d = 0; d < 64; d++)
        s += Wx[c*INNER + h*64 + d] * Wsl[d*64 + gg];
    __half sh = __float2half_rn(s);
    g_wslT_hi[o*CC + c] = sh;
    g_wslT_lo[o*CC + c] = __float2half_rn(s - __half2float(sh));
    if (c == 0) {
        float t = 0.f;
        #pragma unroll 16
        for (int d = 0; d < 64; d++) t += bx[h*64 + d] * Wsl[d*64 + gg];
        g_bsl[o] = t + bsl[gg];
    }
}

// ---------------- slice-logits GEMM + softmax (mma.sync, fp16 2-seg) ----------------
// block M128 x N128, K=256 x 2 segments (8 chunks of 64): xhi*Bhi + xhi*Blo.
// grid (4, 1024).
__global__ __launch_bounds__(256, 2) void k_proj(const float* __restrict__ temp) {
    extern __shared__ char sm[];
    float* stage = (float*)sm;
    uint32_t sb = smem_u32(sm);
    int tid = threadIdx.x;
    int lane = tid & 31, w = tid >> 5;
    int wm = w & 1, wn = w >> 1;
    int tileM = blockIdx.y, y2 = blockIdx.x;
    int row0 = tileM * 128;
    int b = tileM >> 8;
    size_t row0loc = (size_t)(tileM & 255) * 128;

    float acc[4][4][4];
    #pragma unroll
    for (int a = 0; a < 4; a++)
        #pragma unroll
        for (int b2 = 0; b2 < 4; b2++)
            #pragma unroll
            for (int d = 0; d < 4; d++) acc[a][b2][d] = 0.f;

    auto issue = [&](int c) {
        int p = c % 3, seg = c >> 2, k0 = (c & 3) * 64;
        const __half* Bs = (seg == 1) ? g_wslT_lo : g_wslT_hi;
        #pragma unroll
        for (int i = 0; i < 4; i++) {
            int id = tid + i * 256, r = id >> 3, c8 = (id & 7) * 8;
            cpa16(sb + p*32768 + SWZ((uint32_t)(r*128 + c8*2)),
                  g_x_hi + (size_t)(row0 + r) * CC + k0 + c8);
        }
        #pragma unroll
        for (int i = 0; i < 4; i++) {
            int id = tid + i * 256, r = id >> 3, c8 = (id & 7) * 8;
            cpa16(sb + p*32768 + 16384 + SWZ((uint32_t)(r*128 + c8*2)),
                  Bs + (size_t)(y2*128 + r) * CC + k0 + c8);
        }
        CP_COMMIT();
    };

    issue(0); issue(1);
    for (int c = 0; c < 8; c++) {
        if (c + 1 < 8) CP_WAIT1(); else CP_WAIT0();
        __syncthreads();
        uint32_t ab = sb + (c % 3) * 32768;
        uint32_t bb = ab + 16384;
        int rA = lane & 15;
        #pragma unroll
        for (int kk = 0; kk < 4; kk++) {
            uint32_t af[4][4], bf[2][4];
            int kc = kk * 16 + (lane >> 4) * 8;
            #pragma unroll
            for (int mi = 0; mi < 4; mi++)
                ldsm4(af[mi], ab + SWZ((uint32_t)((wm*64 + mi*16 + rA)*128 + kc*2)));
            #pragma unroll
            for (int s = 0; s < 2; s++)
                ldsm4(bf[s], bb + SWZ((uint32_t)((wn*32 + s*16 + rA)*128 + kc*2)));
            #pragma unroll
            for (int mi = 0; mi < 4; mi++)
                #pragma unroll
                for (int nj = 0; nj < 4; nj++)
                    mma_f16(acc[mi][nj], af[mi][0], af[mi][1], af[mi][2], af[mi][3],
                            bf[nj>>1][nj&1], bf[nj>>1][(nj&1)+2]);
        }
        if (c + 2 < 8) issue(c + 2);
    }
    __syncthreads();

    // frags -> stage
    #pragma unroll
    for (int mi = 0; mi < 4; mi++)
        #pragma unroll
        for (int nj = 0; nj < 4; nj++) {
            int row = wm*64 + mi*16 + (lane >> 2);
            int col = wn*32 + nj*8 + (lane & 3)*2;
            *(float2*)&stage[row*STG + col]     = make_float2(acc[mi][nj][0], acc[mi][nj][1]);
            *(float2*)&stage[(row+8)*STG + col] = make_float2(acc[mi][nj][2], acc[mi][nj][3]);
        }
    __syncthreads();

    // softmax over each head's 64 cols per row
    float rt0 = 1.0f / fminf(fmaxf(temp[y2*2 + 0], 0.1f), 5.0f);
    float rt1 = 1.0f / fminf(fmaxf(temp[y2*2 + 1], 0.1f), 5.0f);
    for (int gi = 0; gi < 32; gi++) {
        int G = w * 32 + gi;
        int r = G >> 1, hh = G & 1;
        float bb0 = g_bsl[y2*128 + hh*64 + lane];
        float bb1 = g_bsl[y2*128 + hh*64 + 32 + lane];
        float rt = hh ? rt1 : rt0;
        float v0 = (stage[r*STG + hh*64 + lane]      + bb0) * rt;
        float v1 = (stage[r*STG + hh*64 + 32 + lane] + bb1) * rt;
        float m = fmaxf(v0, v1);
        #pragma unroll
        for (int o = 16; o; o >>= 1) m = fmaxf(m, __shfl_xor_sync(0xFFFFFFFFu, m, o));
        float e0 = __expf(v0 - m), e1 = __expf(v1 - m);
        float s = e0 + e1;
        #pragma unroll
        for (int o = 16; o; o >>= 1) s += __shfl_xor_sync(0xFFFFFFFFu, s, o);
        float rs = 1.0f / s;
        stage[r*STG + hh*64 + lane]      = e0 * rs;
        stage[r*STG + hh*64 + 32 + lane] = e1 * rs;
    }
    __syncthreads();

    // (a) norm: column sums -> atomic
    if (tid < 128) {
        float s = 0.f;
        #pragma unroll 8
        for (int r = 0; r < 128; r++) s += stage[r*STG + tid];
        int head = tid >> 6, g = tid & 63;
        atomicAdd(&g_norm[(b*8 + y2*2 + head)*64 + g], s);
    }
    // (b) w fp16 [tok][hg]  (coalesced 8B chunks)
    #pragma unroll
    for (int i = 0; i < 16; i++) {
        int lin = tid + i * 256, r = lin >> 5, c4 = (lin & 31) * 4;
        float4 v = *(float4*)&stage[r*STG + c4];
        uint2 uh;
        uh.x = pack_h2(v.x, v.y);
        uh.y = pack_h2(v.z, v.w);
        *(uint2*)&g_w_hi[(size_t)(row0 + r)*INNER + y2*128 + c4] = uh;
    }
    // (c) w^T fp16 [bh][g][n] — warp owns 16 cols; lanes pack token pairs
    //     -> every STG.32 is 128B-coalesced (32 lanes x 4B contiguous).
    {
        int colbase = w * 16;
        #pragma unroll
        for (int i = 0; i < 16; i++) {
            int c = colbase + i;
            int head = c >> 6, g = c & 63;
            size_t basew = ((size_t)(b*8 + y2*2 + head) * 64 + g) * (size_t)NTOK
                           + row0loc;
            uint32_t v0 = pack_h2(stage[(2*lane)*STG + c],
                                  stage[(2*lane + 1)*STG + c]);
            uint32_t v1 = pack_h2(stage[(64 + 2*lane)*STG + c],
                                  stage[(64 + 2*lane + 1)*STG + c]);
            *(uint32_t*)&g_wT_hi[basew + 2*lane]      = v0;
            *(uint32_t*)&g_wT_hi[basew + 64 + 2*lane] = v1;
        }
    }
}

// ---------------- pooling GEMM: P[bh][g][c] = sum_n w[n,g]*x[n,c] ----------------
// block M64(g) x N128(c), grid (32 bh, 16 kc, 2 cb). 64 chunks (2 segs x 32).
// segs: whi*xhi + whi*xlo. 4-stage cp.async.
__global__ __launch_bounds__(256, 2) void k_poolg() {
    extern __shared__ char sm[];
    uint32_t sb = smem_u32(sm);
    int tid = threadIdx.x;
    int lane = tid & 31, w = tid >> 5;
    int wm = w & 1, wn = w >> 1;
    int bh = blockIdx.x, kc = blockIdx.y, cb = blockIdx.z;
    int b = bh >> 3;
    size_t nbase = (size_t)kc * 2048;
    const __half* Ahi = g_wT_hi + (size_t)bh * 64 * NTOK;
    const __half* Bhi = g_xT_hi + ((size_t)b * CC + cb * 128) * NTOK;
    const __half* Blo = g_xT_lo + ((size_t)b * CC + cb * 128) * NTOK;

    float acc[2][4][4];
    #pragma unroll
    for (int a = 0; a < 2; a++)
        #pragma unroll
        for (int b2 = 0; b2 < 4; b2++)
            #pragma unroll
            for (int d = 0; d < 4; d++) acc[a][b2][d] = 0.f;

    auto issue = [&](int c) {
        int p = c & 3, seg = c >> 5, k0 = (c & 31) * 64;
        const __half* Bs = (seg == 1) ? Blo : Bhi;
        #pragma unroll
        for (int i = 0; i < 2; i++) {
            int id = tid + i * 256, r = id >> 3, c8 = (id & 7) * 8;
            cpa16(sb + p*24576 + SWZ((uint32_t)(r*128 + c8*2)),
                  Ahi + (size_t)r * NTOK + nbase + k0 + c8);
        }
        #pragma unroll
        for (int i = 0; i < 4; i++) {
            int id = tid + i * 256, r = id >> 3, c8 = (id & 7) * 8;
            cpa16(sb + p*24576 + 8192 + SWZ((uint32_t)(r*128 + c8*2)),
                  Bs + (size_t)r * NTOK + nbase + k0 + c8);
        }
        CP_COMMIT();
    };

    issue(0); issue(1); issue(2);
    for (int c = 0; c < 64; c++) {
        if (c + 2 < 64) CP_WAIT2(); else if (c + 1 < 64) CP_WAIT1(); else CP_WAIT0();
        __syncthreads();
        uint32_t ab = sb + (c & 3) * 24576;
        uint32_t bb = ab + 8192;
        int rA = lane & 15;
        #pragma unroll
        for (int kk = 0; kk < 4; kk++) {
            uint32_t af[2][4], bf[2][4];
            int kc2 = kk * 16 + (lane >> 4) * 8;
            #pragma unroll
            for (int mi = 0; mi < 2; mi++)
                ldsm4(af[mi], ab + SWZ((uint32_t)((wm*32 + mi*16 + rA)*128 + kc2*2)));
            #pragma unroll
            for (int s = 0; s < 2; s++)
                ldsm4(bf[s], bb + SWZ((uint32_t)((wn*32 + s*16 + rA)*128 + kc2*2)));
            #pragma unroll
            for (int mi = 0; mi < 2; mi++)
                #pragma unroll
                for (int nj = 0; nj < 4; nj++)
                    mma_f16(acc[mi][nj], af[mi][0], af[mi][1], af[mi][2], af[mi][3],
                            bf[nj>>1][nj&1], bf[nj>>1][(nj&1)+2]);
        }
        if (c + 3 < 64) issue(c + 3);
    }

    #pragma unroll
    for (int mi = 0; mi < 2; mi++)
        #pragma unroll
        for (int nj = 0; nj < 4; nj++) {
            int row = wm*32 + mi*16 + (lane >> 2);
            int col = cb*128 + wn*32 + nj*8 + (lane & 3)*2;
            int base = bh*16384 + row*256 + col;
            atomicAdd(&g_P[base],            acc[mi][nj][0]);
            atomicAdd(&g_P[base + 1],        acc[mi][nj][1]);
            atomicAdd(&g_P[base + 8*256],    acc[mi][nj][2]);
            atomicAdd(&g_P[base + 8*256 + 1],acc[mi][nj][3]);
        }
}

// ---------------- fused: ST = P@Wfx + bfx*norm ; tiny attention -> g_os ----------------
__global__ void k_stat(const float* __restrict__ Wfx, const float* __restrict__ bfx,
                       const float* __restrict__ Wq, const float* __restrict__ Wk,
                       const float* __restrict__ Wv) {
    int bh = blockIdx.x;
    int h = bh & 7;
    int tid = threadIdx.x;
    __shared__ float bufA[64][65], bufB[64][65];
    __shared__ float nrmc[64];

    float acc[16];
    #pragma unroll
    for (int j = 0; j < 16; j++) acc[j] = 0.f;
    int g = tid >> 2, dq = tid & 3;
    for (int c0 = 0; c0 < 4; c0++) {
        #pragma unroll
        for (int i = 0; i < 16; i++) {
            int id = tid + i * 256;
            int r = id >> 6, cl = id & 63;
            bufA[r][cl] = Wfx[(c0*64 + r) * INNER + h*64 + cl];
            bufB[r][cl] = g_P[bh*16384 + r*256 + c0*64 + cl];
        }
        __syncthreads();
        for (int cl = 0; cl < 64; cl++) {
            float pv = bufB[g][cl];
            #pragma unroll
            for (int j = 0; j < 16; j++)
                acc[j] += pv * bufA[cl][dq*16 + j];
        }
        __syncthreads();
    }
    if (tid < 64) nrmc[tid] = g_norm[bh*64 + tid];
    __syncthreads();
    {
        float nrm = nrmc[g];
        float rdiv = 1.0f / (nrm + 1e-5f);
        #pragma unroll
        for (int j = 0; j < 16; j++) {
            int d = dq*16 + j;
            bufA[g][d] = (acc[j] + bfx[h*64 + d] * nrm) * rdiv;
        }
    }
    __syncthreads();

    #pragma unroll
    for (int it = 0; it < 16; it++) {
        int idx = tid + it * 256;
        int g2 = idx >> 6, d2 = idx & 63;
        float s0 = 0, s1 = 0, s2 = 0, s3 = 0;
        #pragma unroll
        for (int d = 0; d < 64; d += 4) {
            s0 += bufA[g2][d]   * Wk[(d)   * 64 + d2];
            s1 += bufA[g2][d+1] * Wk[(d+1) * 64 + d2];
            s2 += bufA[g2][d+2] * Wk[(d+2) * 64 + d2];
            s3 += bufA[g2][d+3] * Wk[(d+3) * 64 + d2];
        }
        bufB[g2][d2] = (s0 + s1) + (s2 + s3);
    }
    __syncthreads();
    float tv[64];
    if (tid < 64) {
        int g2 = tid;
        float q[64];
        #pragma unroll
        for (int d2 = 0; d2 < 64; d2++) {
            float s0 = 0, s1 = 0, s2 = 0, s3 = 0;
            #pragma unroll
            for (int d = 0; d < 64; d += 4) {
                s0 += bufA[g2][d]   * Wq[(d)   * 64 + d2];
                s1 += bufA[g2][d+1] * Wq[(d+1) * 64 + d2];
                s2 += bufA[g2][d+2] * Wq[(d+2) * 64 + d2];
                s3 += bufA[g2][d+3] * Wq[(d+3) * 64 + d2];
            }
            q[d2] = (s0 + s1) + (s2 + s3);
        }
        float p[64];
        float mx = -1e30f;
        #pragma unroll
        for (int j = 0; j < 64; j++) {
            float s0 = 0, s1 = 0, s2 = 0, s3 = 0;
            #pragma unroll
            for (int d = 0; d < 64; d += 4) {
                s0 += q[d]   * bufB[j][d];
                s1 += q[d+1] * bufB[j][d+1];
                s2 += q[d+2] * bufB[j][d+2];
                s3 += q[d+3] * bufB[j][d+3];
            }
            float s = ((s0 + s1) + (s2 + s3)) * 0.125f;
            p[j] = s;
            mx = fmaxf(mx, s);
        }
        float sum = 0.f;
        #pragma unroll
        for (int j = 0; j < 64; j++) { p[j] = __expf(p[j] - mx); sum += p[j]; }
        float rs = 1.0f / sum;
        #pragma unroll
        for (int e = 0; e < 64; e++) {
            float s0 = 0, s1 = 0, s2 = 0, s3 = 0;
            #pragma unroll
            for (int j = 0; j < 64; j += 4) {
                s0 += p[j]   * bufA[j][e];
                s1 += p[j+1] * bufA[j+1][e];
                s2 += p[j+2] * bufA[j+2][e];
                s3 += p[j+3] * bufA[j+3][e];
            }
            tv[e] = ((s0 + s1) + (s2 + s3)) * rs;
        }
    }
    __syncthreads();
    if (tid < 64) {
        #pragma unroll
        for (int e = 0; e < 64; e++) bufB[tid][e] = tv[e];
    }
    __syncthreads();
    #pragma unroll
    for (int it = 0; it < 16; it++) {
        int idx = tid + it * 256;
        int g2 = idx >> 6, d2 = idx & 63;
        float s0 = 0, s1 = 0, s2 = 0, s3 = 0;
        #pragma unroll
        for (int e = 0; e < 64; e += 4) {
            s0 += bufB[g2][e]   * Wv[(e)   * 64 + d2];
            s1 += bufB[g2][e+1] * Wv[(e+1) * 64 + d2];
            s2 += bufB[g2][e+2] * Wv[(e+2) * 64 + d2];
            s3 += bufB[g2][e+3] * Wv[(e+3) * 64 + d2];
        }
        g_os[bh * 4096 + idx] = (s0 + s1) + (s2 + s3);
    }
}

// ---------------- fold out_slice into W_out: W_eff^T fp16 pair [b][c][hg] ----------------
__global__ void k_weff(const float* __restrict__ Wout) {
    int blk = blockIdx.x;           // b*512 + row
    int b = blk >> 9;
    int row = blk & 511;            // k index: h*64+g
    int h = row >> 6;
    int tid = threadIdx.x;          // n index = c (256)
    __shared__ float osr[64];
    if (tid < 64) osr[tid] = g_os[(b*8 + h) * 4096 + (row & 63) * 64 + tid];
    __syncthreads();
    float s = 0.f;
    #pragma unroll 16
    for (int d = 0; d < 64; d++)
        s += osr[d] * Wout[(h*64 + d) * CC + tid];
    __half sh = __float2half_rn(s);
    size_t idx = (size_t)b * (CC*INNER) + (size_t)tid * INNER + row;
    g_weffT_hi[idx] = sh;
    g_weffT_lo[idx] = __float2half_rn(s - __half2float(sh));
}

// ---------------- output GEMM: y = w @ W_eff[b] + b_out (fp16 2-seg) ----------------
// block M128 x N128, K=512 x 2 segments (16 chunks). grid (2, 1024): ct fast-varying.
__global__ __launch_bounds__(256, 2) void k_out(const float* __restrict__ bout,
                                                float* __restrict__ y) {
    extern __shared__ char sm[];
    float* stage = (float*)sm;
    uint32_t sb = smem_u32(sm);
    int tid = threadIdx.x;
    int lane = tid & 31, w = tid >> 5;
    int wm = w & 1, wn = w >> 1;
    int tileM = blockIdx.y, ct = blockIdx.x;
    int row0 = tileM * 128;
    int b = tileM >> 8;

    float acc[4][4][4];
    #pragma unroll
    for (int a = 0; a < 4; a++)
        #pragma unroll
        for (int bb2 = 0; bb2 < 4; bb2++)
            #pragma unroll
            for (int d = 0; d < 4; d++) acc[a][bb2][d] = 0.f;

    auto issue = [&](int c) {
        int p = c % 3, seg = c >> 3, k0 = (c & 7) * 64;
        const __half* Bs = (seg == 1) ? g_weffT_lo : g_weffT_hi;
        #pragma unroll
        for (int i = 0; i < 4; i++) {
            int id = tid + i * 256, r = id >> 3, c8 = (id & 7) * 8;
            cpa16(sb + p*32768 + SWZ((uint32_t)(r*128 + c8*2)),
                  g_w_hi + (size_t)(row0 + r) * INNER + k0 + c8);
        }
        #pragma unroll
        for (int i = 0; i < 4; i++) {
            int id = tid + i * 256, r = id >> 3, c8 = (id & 7) * 8;
            cpa16(sb + p*32768 + 16384 + SWZ((uint32_t)(r*128 + c8*2)),
                  Bs + (size_t)b * (CC*INNER) + (size_t)(ct*128 + r) * INNER + k0 + c8);
        }
        CP_COMMIT();
    };

    issue(0); issue(1);
    for (int c = 0; c < 16; c++) {
        if (c + 1 < 16) CP_WAIT1(); else CP_WAIT0();
        __syncthreads();
        uint32_t ab = sb + (c % 3) * 32768;
        uint32_t bbs = ab + 16384;
        int rA = lane & 15;
        #pragma unroll
        for (int kk = 0; kk < 4; kk++) {
            uint32_t af[4][4], bf[2][4];
            int kc = kk * 16 + (lane >> 4) * 8;
            #pragma unroll
            for (int mi = 0; mi < 4; mi++)
                ldsm4(af[mi], ab + SWZ((uint32_t)((wm*64 + mi*16 + rA)*128 + kc*2)));
            #pragma unroll
            for (int s = 0; s < 2; s++)
                ldsm4(bf[s], bbs + SWZ((uint32_t)((wn*32 + s*16 + rA)*128 + kc*2)));
            #pragma unroll
            for (int mi = 0; mi < 4; mi++)
                #pragma unroll
                for (int nj = 0; nj < 4; nj++)
                    mma_f16(acc[mi][nj], af[mi][0], af[mi][1], af[mi][2], af[mi][3],
                            bf[nj>>1][nj&1], bf[nj>>1][(nj&1)+2]);
        }
        if (c + 2 < 16) issue(c + 2);
    }
    __syncthreads();

    #pragma unroll
    for (int mi = 0; mi < 4; mi++)
        #pragma unroll
        for (int nj = 0; nj < 4; nj++) {
            int row = wm*64 + mi*16 + (lane >> 2);
            int col = wn*32 + nj*8 + (lane & 3)*2;
            *(float2*)&stage[row*STG + col]     = make_float2(acc[mi][nj][0], acc[mi][nj][1]);
            *(float2*)&stage[(row+8)*STG + col] = make_float2(acc[mi][nj][2], acc[mi][nj][3]);
        }
    __syncthreads();
    #pragma unroll
    for (int i = 0; i < 16; i++) {
        int lin = tid + i * 256, r = lin >> 5, c4 = (lin & 31) * 4;
        float4 v = *(float4*)&stage[r*STG + c4];
        float4 bv = *(const float4*)&bout[ct*128 + c4];
        v.x += bv.x; v.y += bv.y; v.z += bv.z; v.w += bv.w;
        *(float4*)&y[(size_t)(row0 + r)*CC + ct*128 + c4] = v;
    }
}

// ---------------- launch ----------------
extern "C" void kernel_launch(void* const* d_in, const int* in_sizes, int n_in,
                              void* d_out, int out_size) {
    const float* x    = (const float*)d_in[0];
    const float* Wfx  = (const float*)d_in[1];
    const float* bfx  = (const float*)d_in[2];
    const float* Wx   = (const float*)d_in[3];
    const float* bx   = (const float*)d_in[4];
    const float* Wsl  = (const float*)d_in[5];
    const float* bsl  = (const float*)d_in[6];
    const float* temp = (const float*)d_in[7];
    const float* Wq   = (const float*)d_in[8];
    const float* Wk   = (const float*)d_in[9];
    const float* Wv   = (const float*)d_in[10];
    const float* Wout = (const float*)d_in[11];
    const float* bout = (const float*)d_in[12];
    float* y = (float*)d_out;

    cudaFuncSetAttribute(k_proj,  cudaFuncAttributeMaxDynamicSharedMemorySize, GSMEM);
    cudaFuncSetAttribute(k_poolg, cudaFuncAttributeMaxDynamicSharedMemorySize, PGSMEM);
    cudaFuncSetAttribute(k_out,   cudaFuncAttributeMaxDynamicSharedMemorySize, GSMEM);

    k_zero<<<2048, 256>>>();
    k_prep<<<CC, 512>>>(Wx, bx, Wsl, bsl);
    k_split<<<dim3(TOK/64, 4), 256>>>(x);
    k_proj<<<dim3(4, TOK/128), 256, GSMEM>>>(temp);
    k_poolg<<<dim3(32, 16, 2), 256, PGSMEM>>>();
    k_stat<<<32, 256>>>(Wfx, bfx, Wq, Wk, Wv);
    k_weff<<<2048, 256>>>(Wout);
    k_out<<<dim3(2, TOK/128), 256, GSMEM>>>(bout, y);
}

// round 13
// speedup vs baseline: 1.4574x; 1.0075x over previous
#include <cuda_runtime.h>
#include <cuda_fp16.h>
#include <cstdint>

#define BB 4
#define NTOK 32768
#define CC 256
#define HH 8
#define DD 64
#define GG 64
#define INNER 512
#define TOK (BB*NTOK)   // 131072

// ---------------- scratch (device globals; no runtime allocation) ----------------
__device__ __align__(16) __half g_x_hi[(size_t)TOK*CC];      // x fp16 hi [tok][c]
__device__ __align__(16) __half g_xT_hi[(size_t)BB*CC*NTOK]; // x^T hi [b][c][n]
__device__ __align__(16) __half g_xT_lo[(size_t)BB*CC*NTOK]; // x^T lo
__device__ __align__(16) __half g_w_hi[(size_t)TOK*INNER];   // slice weights fp16 [tok][hg]
__device__ __align__(16) __half g_wT_hi[(size_t)BB*HH*GG*NTOK]; // w^T fp16 [bh][g][n]
__device__ __align__(16) __half g_wslT_hi[INNER*CC];         // (Wx@Wslice)^T hi
__device__ __align__(16) __half g_wslT_lo[INNER*CC];         // lo
__device__ float g_bsl[INNER];                    // folded slice bias
__device__ float g_P[BB*HH*GG*CC];                // pooled P[bh][g][c] (atomic accum)
__device__ float g_norm[BB*HH*GG];                // weight column sums
__device__ float g_os[BB*HH*GG*DD];               // out_slice
__device__ __align__(16) __half g_weffT_hi[BB*CC*INNER];     // W_eff^T hi [b][c][hg]
__device__ __align__(16) __half g_weffT_lo[BB*CC*INNER];     // lo

// ============================ helpers ============================
#define DINLINE __device__ __forceinline__

DINLINE uint32_t smem_u32(const void* p) {
    uint32_t a;
    asm("{ .reg .u64 t; cvta.to.shared.u64 t, %1; cvt.u32.u64 %0, t; }" : "=r"(a) : "l"(p));
    return a;
}
DINLINE void cpa16(uint32_t dst, const void* src) {
    asm volatile("cp.async.cg.shared.global [%0], [%1], 16;" :: "r"(dst), "l"(src));
}
#define CP_COMMIT() asm volatile("cp.async.commit_group;" ::: "memory")
#define CP_WAIT2()  asm volatile("cp.async.wait_group 2;" ::: "memory")
#define CP_WAIT1()  asm volatile("cp.async.wait_group 1;" ::: "memory")
#define CP_WAIT0()  asm volatile("cp.async.wait_group 0;" ::: "memory")

DINLINE void ldsm4(uint32_t* r, uint32_t addr) {
    asm volatile("ldmatrix.sync.aligned.m8n8.x4.shared.b16 {%0,%1,%2,%3}, [%4];"
        : "=r"(r[0]), "=r"(r[1]), "=r"(r[2]), "=r"(r[3]) : "r"(addr));
}
DINLINE void mma_f16(float* d, uint32_t a0, uint32_t a1, uint32_t a2, uint32_t a3,
                     uint32_t b0, uint32_t b1) {
    asm volatile("mma.sync.aligned.m16n8k16.row.col.f32.f16.f16.f32 "
        "{%0,%1,%2,%3}, {%4,%5,%6,%7}, {%8,%9}, {%0,%1,%2,%3};"
        : "+f"(d[0]), "+f"(d[1]), "+f"(d[2]), "+f"(d[3])
        : "r"(a0), "r"(a1), "r"(a2), "r"(a3), "r"(b0), "r"(b1));
}
DINLINE uint32_t pack_h2(float a, float b) {
    __half2 h = __floats2half2_rn(a, b);
    return *reinterpret_cast<uint32_t*>(&h);
}
#define SWZ(off) ((off) ^ (((off) >> 3) & 0x70))
#define STG 132        // stage row stride (floats)
#define GSMEM 98304    // 3 stages x (16KB A + 16KB B)
#define PGSMEM 98304   // 4 stages x (8KB A + 16KB B)

// ---------------- zero accumulators (must run every graph replay) ----------------
__global__ void k_zero() {
    int i = blockIdx.x * blockDim.x + threadIdx.x;
    if (i < BB*HH*GG*CC) g_P[i] = 0.f;
    if (i < BB*HH*GG)    g_norm[i] = 0.f;
}

// ---------------- split x into fp16 hi ([tok][c]) and hi/lo transposed ----------------
__global__ void k_split(const float* __restrict__ x) {
    __shared__ uint16_t shi[64][68], slo[64][68];
    int tid = threadIdx.x;
    size_t t0 = (size_t)blockIdx.x * 64;     // token tile
    int c0 = blockIdx.y * 64;                // c tile
    int r = tid >> 2, cq = (tid & 3) * 16;
    #pragma unroll
    for (int j = 0; j < 16; j += 4) {
        float4 v = *(const float4*)&x[(t0 + r) * CC + c0 + cq + j];
        __half hx = __float2half_rn(v.x), hy = __float2half_rn(v.y);
        __half hz = __float2half_rn(v.z), hw = __float2half_rn(v.w);
        uint2 uh, ul;
        uh.x = pack_h2(v.x, v.y);
        uh.y = pack_h2(v.z, v.w);
        ul.x = pack_h2(v.x - __half2float(hx), v.y - __half2float(hy));
        ul.y = pack_h2(v.z - __half2float(hz), v.w - __half2float(hw));
        *(uint2*)&g_x_hi[(t0 + r) * CC + c0 + cq + j] = uh;
        *(uint2*)&shi[r][cq + j] = uh;
        *(uint2*)&slo[r][cq + j] = ul;
    }
    __syncthreads();
    int c = tid >> 2, tq = (tid & 3) * 16;
    size_t b = t0 >> 15;                 // /NTOK
    size_t nloc = t0 & (NTOK - 1);
    size_t base = ((size_t)b * CC + c0 + c) * NTOK + nloc + tq;
    #pragma unroll
    for (int j = 0; j < 16; j += 2) {
        uint32_t hv = (uint32_t)shi[tq + j][c] | ((uint32_t)shi[tq + j + 1][c] << 16);
        uint32_t lv = (uint32_t)slo[tq + j][c] | ((uint32_t)slo[tq + j + 1][c] << 16);
        *(uint32_t*)&g_xT_hi[base + j] = hv;
        *(uint32_t*)&g_xT_lo[base + j] = lv;
    }
}

// ---------------- fold + transpose + fp16-split slice weight ----------------
__global__ void k_prep(const float* __restrict__ Wx, const float* __restrict__ bx,
                       const float* __restrict__ Wsl, const float* __restrict__ bsl) {
    int c = blockIdx.x;        // K index 0..255
    int o = threadIdx.x;       // N index 0..511
    int h = o >> 6, gg = o & 63;
    float s = 0.f;
    #pragma unroll 16
    for (int d = 0; d < 64; d++)
        s += Wx[c*INNER + h*64 + d] * Wsl[d*64 + gg];
    __half sh = __float2half_rn(s);
    g_wslT_hi[o*CC + c] = sh;
    g_wslT_lo[o*CC + c] = __float2half_rn(s - __half2float(sh));
    if (c == 0) {
        float t = 0.f;
        #pragma unroll 16
        for (int d = 0; d < 64; d++) t += bx[h*64 + d] * Wsl[d*64 + gg];
        g_bsl[o] = t + bsl[gg];
    }
}

// ---------------- slice-logits GEMM + softmax (mma.sync, fp16 2-seg) ----------------
// block M128 x N128, K=256 x 2 segments (8 chunks of 64): xhi*Bhi + xhi*Blo.
// grid (4, 1024).
__global__ __launch_bounds__(256, 2) void k_proj(const float* __restrict__ temp) {
    extern __shared__ char sm[];
    float* stage = (float*)sm;
    uint32_t sb = smem_u32(sm);
    int tid = threadIdx.x;
    int lane = tid & 31, w = tid >> 5;
    int wm = w & 1, wn = w >> 1;
    int tileM = blockIdx.y, y2 = blockIdx.x;
    int row0 = tileM * 128;
    int b = tileM >> 8;
    size_t row0loc = (size_t)(tileM & 255) * 128;

    float acc[4][4][4];
    #pragma unroll
    for (int a = 0; a < 4; a++)
        #pragma unroll
        for (int b2 = 0; b2 < 4; b2++)
            #pragma unroll
            for (int d = 0; d < 4; d++) acc[a][b2][d] = 0.f;

    auto issue = [&](int c) {
        int p = c % 3, seg = c >> 2, k0 = (c & 3) * 64;
        const __half* Bs = (seg == 1) ? g_wslT_lo : g_wslT_hi;
        #pragma unroll
        for (int i = 0; i < 4; i++) {
            int id = tid + i * 256, r = id >> 3, c8 = (id & 7) * 8;
            cpa16(sb + p*32768 + SWZ((uint32_t)(r*128 + c8*2)),
                  g_x_hi + (size_t)(row0 + r) * CC + k0 + c8);
        }
        #pragma unroll
        for (int i = 0; i < 4; i++) {
            int id = tid + i * 256, r = id >> 3, c8 = (id & 7) * 8;
            cpa16(sb + p*32768 + 16384 + SWZ((uint32_t)(r*128 + c8*2)),
                  Bs + (size_t)(y2*128 + r) * CC + k0 + c8);
        }
        CP_COMMIT();
    };

    issue(0); issue(1);
    for (int c = 0; c < 8; c++) {
        if (c + 1 < 8) CP_WAIT1(); else CP_WAIT0();
        __syncthreads();
        uint32_t ab = sb + (c % 3) * 32768;
        uint32_t bb = ab + 16384;
        int rA = lane & 15;
        #pragma unroll
        for (int kk = 0; kk < 4; kk++) {
            uint32_t af[4][4], bf[2][4];
            int kc = kk * 16 + (lane >> 4) * 8;
            #pragma unroll
            for (int mi = 0; mi < 4; mi++)
                ldsm4(af[mi], ab + SWZ((uint32_t)((wm*64 + mi*16 + rA)*128 + kc*2)));
            #pragma unroll
            for (int s = 0; s < 2; s++)
                ldsm4(bf[s], bb + SWZ((uint32_t)((wn*32 + s*16 + rA)*128 + kc*2)));
            #pragma unroll
            for (int mi = 0; mi < 4; mi++)
                #pragma unroll
                for (int nj = 0; nj < 4; nj++)
                    mma_f16(acc[mi][nj], af[mi][0], af[mi][1], af[mi][2], af[mi][3],
                            bf[nj>>1][nj&1], bf[nj>>1][(nj&1)+2]);
        }
        if (c + 2 < 8) issue(c + 2);
    }
    __syncthreads();

    // frags -> stage
    #pragma unroll
    for (int mi = 0; mi < 4; mi++)
        #pragma unroll
        for (int nj = 0; nj < 4; nj++) {
            int row = wm*64 + mi*16 + (lane >> 2);
            int col = wn*32 + nj*8 + (lane & 3)*2;
            *(float2*)&stage[row*STG + col]     = make_float2(acc[mi][nj][0], acc[mi][nj][1]);
            *(float2*)&stage[(row+8)*STG + col] = make_float2(acc[mi][nj][2], acc[mi][nj][3]);
        }
    __syncthreads();

    // softmax over each head's 64 cols per row
    float rt0 = 1.0f / fminf(fmaxf(temp[y2*2 + 0], 0.1f), 5.0f);
    float rt1 = 1.0f / fminf(fmaxf(temp[y2*2 + 1], 0.1f), 5.0f);
    for (int gi = 0; gi < 32; gi++) {
        int G = w * 32 + gi;
        int r = G >> 1, hh = G & 1;
        float bb0 = g_bsl[y2*128 + hh*64 + lane];
        float bb1 = g_bsl[y2*128 + hh*64 + 32 + lane];
        float rt = hh ? rt1 : rt0;
        float v0 = (stage[r*STG + hh*64 + lane]      + bb0) * rt;
        float v1 = (stage[r*STG + hh*64 + 32 + lane] + bb1) * rt;
        float m = fmaxf(v0, v1);
        #pragma unroll
        for (int o = 16; o; o >>= 1) m = fmaxf(m, __shfl_xor_sync(0xFFFFFFFFu, m, o));
        float e0 = __expf(v0 - m), e1 = __expf(v1 - m);
        float s = e0 + e1;
        #pragma unroll
        for (int o = 16; o; o >>= 1) s += __shfl_xor_sync(0xFFFFFFFFu, s, o);
        float rs = 1.0f / s;
        stage[r*STG + hh*64 + lane]      = e0 * rs;
        stage[r*STG + hh*64 + 32 + lane] = e1 * rs;
    }
    __syncthreads();

    // (a) norm: column sums -> atomic
    if (tid < 128) {
        float s = 0.f;
        #pragma unroll 8
        for (int r = 0; r < 128; r++) s += stage[r*STG + tid];
        int head = tid >> 6, g = tid & 63;
        atomicAdd(&g_norm[(b*8 + y2*2 + head)*64 + g], s);
    }
    // (b) w fp16 [tok][hg]  (coalesced 8B chunks)
    #pragma unroll
    for (int i = 0; i < 16; i++) {
        int lin = tid + i * 256, r = lin >> 5, c4 = (lin & 31) * 4;
        float4 v = *(float4*)&stage[r*STG + c4];
        uint2 uh;
        uh.x = pack_h2(v.x, v.y);
        uh.y = pack_h2(v.z, v.w);
        *(uint2*)&g_w_hi[(size_t)(row0 + r)*INNER + y2*128 + c4] = uh;
    }
    // (c) w^T fp16 [bh][g][n] — warp owns 16 cols; lanes pack token pairs
    //     -> every STG.32 is 128B-coalesced (32 lanes x 4B contiguous).
    {
        int colbase = w * 16;
        #pragma unroll
        for (int i = 0; i < 16; i++) {
            int c = colbase + i;
            int head = c >> 6, g = c & 63;
            size_t basew = ((size_t)(b*8 + y2*2 + head) * 64 + g) * (size_t)NTOK
                           + row0loc;
            uint32_t v0 = pack_h2(stage[(2*lane)*STG + c],
                                  stage[(2*lane + 1)*STG + c]);
            uint32_t v1 = pack_h2(stage[(64 + 2*lane)*STG + c],
                                  stage[(64 + 2*lane + 1)*STG + c]);
            *(uint32_t*)&g_wT_hi[basew + 2*lane]      = v0;
            *(uint32_t*)&g_wT_hi[basew + 64 + 2*lane] = v1;
        }
    }
}

// ---------------- pooling GEMM: P[bh][g][c] = sum_n w[n,g]*x[n,c] ----------------
// block M64(g) x N128(c), grid (32 bh, 16 kc, 2 cb). 64 chunks (2 segs x 32).
// segs: whi*xhi + whi*xlo. 4-stage cp.async.
__global__ __launch_bounds__(256, 2) void k_poolg() {
    extern __shared__ char sm[];
    uint32_t sb = smem_u32(sm);
    int tid = threadIdx.x;
    int lane = tid & 31, w = tid >> 5;
    int wm = w & 1, wn = w >> 1;
    int bh = blockIdx.x, kc = blockIdx.y, cb = blockIdx.z;
    int b = bh >> 3;
    size_t nbase = (size_t)kc * 2048;
    const __half* Ahi = g_wT_hi + (size_t)bh * 64 * NTOK;
    const __half* Bhi = g_xT_hi + ((size_t)b * CC + cb * 128) * NTOK;
    const __half* Blo = g_xT_lo + ((size_t)b * CC + cb * 128) * NTOK;

    float acc[2][4][4];
    #pragma unroll
    for (int a = 0; a < 2; a++)
        #pragma unroll
        for (int b2 = 0; b2 < 4; b2++)
            #pragma unroll
            for (int d = 0; d < 4; d++) acc[a][b2][d] = 0.f;

    auto issue = [&](int c) {
        int p = c & 3, seg = c >> 5, k0 = (c & 31) * 64;
        const __half* Bs = (seg == 1) ? Blo : Bhi;
        #pragma unroll
        for (int i = 0; i < 2; i++) {
            int id = tid + i * 256, r = id >> 3, c8 = (id & 7) * 8;
            cpa16(sb + p*24576 + SWZ((uint32_t)(r*128 + c8*2)),
                  Ahi + (size_t)r * NTOK + nbase + k0 + c8);
        }
        #pragma unroll
        for (int i = 0; i < 4; i++) {
            int id = tid + i * 256, r = id >> 3, c8 = (id & 7) * 8;
            cpa16(sb + p*24576 + 8192 + SWZ((uint32_t)(r*128 + c8*2)),
                  Bs + (size_t)r * NTOK + nbase + k0 + c8);
        }
        CP_COMMIT();
    };

    issue(0); issue(1); issue(2);
    for (int c = 0; c < 64; c++) {
        if (c + 2 < 64) CP_WAIT2(); else if (c + 1 < 64) CP_WAIT1(); else CP_WAIT0();
        __syncthreads();
        uint32_t ab = sb + (c & 3) * 24576;
        uint32_t bb = ab + 8192;
        int rA = lane & 15;
        #pragma unroll
        for (int kk = 0; kk < 4; kk++) {
            uint32_t af[2][4], bf[2][4];
            int kc2 = kk * 16 + (lane >> 4) * 8;
            #pragma unroll
            for (int mi = 0; mi < 2; mi++)
                ldsm4(af[mi], ab + SWZ((uint32_t)((wm*32 + mi*16 + rA)*128 + kc2*2)));
            #pragma unroll
            for (int s = 0; s < 2; s++)
                ldsm4(bf[s], bb + SWZ((uint32_t)((wn*32 + s*16 + rA)*128 + kc2*2)));
            #pragma unroll
            for (int mi = 0; mi < 2; mi++)
                #pragma unroll
                for (int nj = 0; nj < 4; nj++)
                    mma_f16(acc[mi][nj], af[mi][0], af[mi][1], af[mi][2], af[mi][3],
                            bf[nj>>1][nj&1], bf[nj>>1][(nj&1)+2]);
        }
        if (c + 3 < 64) issue(c + 3);
    }

    #pragma unroll
    for (int mi = 0; mi < 2; mi++)
        #pragma unroll
        for (int nj = 0; nj < 4; nj++) {
            int row = wm*32 + mi*16 + (lane >> 2);
            int col = cb*128 + wn*32 + nj*8 + (lane & 3)*2;
            int base = bh*16384 + row*256 + col;
            atomicAdd(&g_P[base],            acc[mi][nj][0]);
            atomicAdd(&g_P[base + 1],        acc[mi][nj][1]);
            atomicAdd(&g_P[base + 8*256],    acc[mi][nj][2]);
            atomicAdd(&g_P[base + 8*256 + 1],acc[mi][nj][3]);
        }
}

// ---------------- fused: ST = P@Wfx + bfx*norm ; tiny attention -> g_os ----------------
__global__ void k_stat(const float* __restrict__ Wfx, const float* __restrict__ bfx,
                       const float* __restrict__ Wq, const float* __restrict__ Wk,
                       const float* __restrict__ Wv) {
    int bh = blockIdx.x;
    int h = bh & 7;
    int tid = threadIdx.x;
    __shared__ float bufA[64][65], bufB[64][65];
    __shared__ float nrmc[64];

    float acc[16];
    #pragma unroll
    for (int j = 0; j < 16; j++) acc[j] = 0.f;
    int g = tid >> 2, dq = tid & 3;
    for (int c0 = 0; c0 < 4; c0++) {
        #pragma unroll
        for (int i = 0; i < 16; i++) {
            int id = tid + i * 256;
            int r = id >> 6, cl = id & 63;
            bufA[r][cl] = Wfx[(c0*64 + r) * INNER + h*64 + cl];
            bufB[r][cl] = g_P[bh*16384 + r*256 + c0*64 + cl];
        }
        __syncthreads();
        for (int cl = 0; cl < 64; cl++) {
            float pv = bufB[g][cl];
            #pragma unroll
            for (int j = 0; j < 16; j++)
                acc[j] += pv * bufA[cl][dq*16 + j];
        }
        __syncthreads();
    }
    if (tid < 64) nrmc[tid] = g_norm[bh*64 + tid];
    __syncthreads();
    {
        float nrm = nrmc[g];
        float rdiv = 1.0f / (nrm + 1e-5f);
        #pragma unroll
        for (int j = 0; j < 16; j++) {
            int d = dq*16 + j;
            bufA[g][d] = (acc[j] + bfx[h*64 + d] * nrm) * rdiv;
        }
    }
    __syncthreads();

    #pragma unroll
    for (int it = 0; it < 16; it++) {
        int idx = tid + it * 256;
        int g2 = idx >> 6, d2 = idx & 63;
        float s0 = 0, s1 = 0, s2 = 0, s3 = 0;
        #pragma unroll
        for (int d = 0; d < 64; d += 4) {
            s0 += bufA[g2][d]   * Wk[(d)   * 64 + d2];
            s1 += bufA[g2][d+1] * Wk[(d+1) * 64 + d2];
            s2 += bufA[g2][d+2] * Wk[(d+2) * 64 + d2];
            s3 += bufA[g2][d+3] * Wk[(d+3) * 64 + d2];
        }
        bufB[g2][d2] = (s0 + s1) + (s2 + s3);
    }
    __syncthreads();
    float tv[64];
    if (tid < 64) {
        int g2 = tid;
        float q[64];
        #pragma unroll
        for (int d2 = 0; d2 < 64; d2++) {
            float s0 = 0, s1 = 0, s2 = 0, s3 = 0;
            #pragma unroll
            for (int d = 0; d < 64; d += 4) {
                s0 += bufA[g2][d]   * Wq[(d)   * 64 + d2];
                s1 += bufA[g2][d+1] * Wq[(d+1) * 64 + d2];
                s2 += bufA[g2][d+2] * Wq[(d+2) * 64 + d2];
                s3 += bufA[g2][d+3] * Wq[(d+3) * 64 + d2];
            }
            q[d2] = (s0 + s1) + (s2 + s3);
        }
        float p[64];
        float mx = -1e30f;
        #pragma unroll
        for (int j = 0; j < 64; j++) {
            float s0 = 0, s1 = 0, s2 = 0, s3 = 0;
            #pragma unroll
            for (int d = 0; d < 64; d += 4) {
                s0 += q[d]   * bufB[j][d];
                s1 += q[d+1] * bufB[j][d+1];
                s2 += q[d+2] * bufB[j][d+2];
                s3 += q[d+3] * bufB[j][d+3];
            }
            float s = ((s0 + s1) + (s2 + s3)) * 0.125f;
            p[j] = s;
            mx = fmaxf(mx, s);
        }
        float sum = 0.f;
        #pragma unroll
        for (int j = 0; j < 64; j++) { p[j] = __expf(p[j] - mx); sum += p[j]; }
        float rs = 1.0f / sum;
        #pragma unroll
        for (int e = 0; e < 64; e++) {
            float s0 = 0, s1 = 0, s2 = 0, s3 = 0;
            #pragma unroll
            for (int j = 0; j < 64; j += 4) {
                s0 += p[j]   * bufA[j][e];
                s1 += p[j+1] * bufA[j+1][e];
                s2 += p[j+2] * bufA[j+2][e];
                s3 += p[j+3] * bufA[j+3][e];
            }
            tv[e] = ((s0 + s1) + (s2 + s3)) * rs;
        }
    }
    __syncthreads();
    if (tid < 64) {
        #pragma unroll
        for (int e = 0; e < 64; e++) bufB[tid][e] = tv[e];
    }
    __syncthreads();
    #pragma unroll
    for (int it = 0; it < 16; it++) {
        int idx = tid + it * 256;
        int g2 = idx >> 6, d2 = idx & 63;
        float s0 = 0, s1 = 0, s2 = 0, s3 = 0;
        #pragma unroll
        for (int e = 0; e < 64; e += 4) {
            s0 += bufB[g2][e]   * Wv[(e)   * 64 + d2];
            s1 += bufB[g2][e+1] * Wv[(e+1) * 64 + d2];
            s2 += bufB[g2][e+2] * Wv[(e+2) * 64 + d2];
            s3 += bufB[g2][e+3] * Wv[(e+3) * 64 + d2];
        }
        g_os[bh * 4096 + idx] = (s0 + s1) + (s2 + s3);
    }
}

// ---------------- fold out_slice into W_out: W_eff^T fp16 pair [b][c][hg] ----------------
__global__ void k_weff(const float* __restrict__ Wout) {
    int blk = blockIdx.x;           // b*512 + row
    int b = blk >> 9;
    int row = blk & 511;            // k index: h*64+g
    int h = row >> 6;
    int tid = threadIdx.x;          // n index = c (256)
    __shared__ float osr[64];
    if (tid < 64) osr[tid] = g_os[(b*8 + h) * 4096 + (row & 63) * 64 + tid];
    __syncthreads();
    float s = 0.f;
    #pragma unroll 16
    for (int d = 0; d < 64; d++)
        s += osr[d] * Wout[(h*64 + d) * CC + tid];
    __half sh = __float2half_rn(s);
    size_t idx = (size_t)b * (CC*INNER) + (size_t)tid * INNER + row;
    g_weffT_hi[idx] = sh;
    g_weffT_lo[idx] = __float2half_rn(s - __half2float(sh));
}

// ---------------- output GEMM: y = w @ W_eff[b] + b_out (fp16 2-seg) ----------------
// block M128 x N128, K=512 x 2 segments (16 chunks). grid (2, 1024): ct fast-varying.
__global__ __launch_bounds__(256, 2) void k_out(const float* __restrict__ bout,
                                                float* __restrict__ y) {
    extern __shared__ char sm[];
    float* stage = (float*)sm;
    uint32_t sb = smem_u32(sm);
    int tid = threadIdx.x;
    int lane = tid & 31, w = tid >> 5;
    int wm = w & 1, wn = w >> 1;
    int tileM = blockIdx.y, ct = blockIdx.x;
    int row0 = tileM * 128;
    int b = tileM >> 8;

    float acc[4][4][4];
    #pragma unroll
    for (int a = 0; a < 4; a++)
        #pragma unroll
        for (int bb2 = 0; bb2 < 4; bb2++)
            #pragma unroll
            for (int d = 0; d < 4; d++) acc[a][bb2][d] = 0.f;

    auto issue = [&](int c) {
        int p = c % 3, seg = c >> 3, k0 = (c & 7) * 64;
        const __half* Bs = (seg == 1) ? g_weffT_lo : g_weffT_hi;
        #pragma unroll
        for (int i = 0; i < 4; i++) {
            int id = tid + i * 256, r = id >> 3, c8 = (id & 7) * 8;
            cpa16(sb + p*32768 + SWZ((uint32_t)(r*128 + c8*2)),
                  g_w_hi + (size_t)(row0 + r) * INNER + k0 + c8);
        }
        #pragma unroll
        for (int i = 0; i < 4; i++) {
            int id = tid + i * 256, r = id >> 3, c8 = (id & 7) * 8;
            cpa16(sb + p*32768 + 16384 + SWZ((uint32_t)(r*128 + c8*2)),
                  Bs + (size_t)b * (CC*INNER) + (size_t)(ct*128 + r) * INNER + k0 + c8);
        }
        CP_COMMIT();
    };

    issue(0); issue(1);
    for (int c = 0; c < 16; c++) {
        if (c + 1 < 16) CP_WAIT1(); else CP_WAIT0();
        __syncthreads();
        uint32_t ab = sb + (c % 3) * 32768;
        uint32_t bbs = ab + 16384;
        int rA = lane & 15;
        #pragma unroll
        for (int kk = 0; kk < 4; kk++) {
            uint32_t af[4][4], bf[2][4];
            int kc = kk * 16 + (lane >> 4) * 8;
            #pragma unroll
            for (int mi = 0; mi < 4; mi++)
                ldsm4(af[mi], ab + SWZ((uint32_t)((wm*64 + mi*16 + rA)*128 + kc*2)));
            #pragma unroll
            for (int s = 0; s < 2; s++)
                ldsm4(bf[s], bbs + SWZ((uint32_t)((wn*32 + s*16 + rA)*128 + kc*2)));
            #pragma unroll
            for (int mi = 0; mi < 4; mi++)
                #pragma unroll
                for (int nj = 0; nj < 4; nj++)
                    mma_f16(acc[mi][nj], af[mi][0], af[mi][1], af[mi][2], af[mi][3],
                            bf[nj>>1][nj&1], bf[nj>>1][(nj&1)+2]);
        }
        if (c + 2 < 16) issue(c + 2);
    }
    __syncthreads();

    #pragma unroll
    for (int mi = 0; mi < 4; mi++)
        #pragma unroll
        for (int nj = 0; nj < 4; nj++) {
            int row = wm*64 + mi*16 + (lane >> 2);
            int col = wn*32 + nj*8 + (lane & 3)*2;
            *(float2*)&stage[row*STG + col]     = make_float2(acc[mi][nj][0], acc[mi][nj][1]);
            *(float2*)&stage[(row+8)*STG + col] = make_float2(acc[mi][nj][2], acc[mi][nj][3]);
        }
    __syncthreads();
    #pragma unroll
    for (int i = 0; i < 16; i++) {
        int lin = tid + i * 256, r = lin >> 5, c4 = (lin & 31) * 4;
        float4 v = *(float4*)&stage[r*STG + c4];
        float4 bv = *(const float4*)&bout[ct*128 + c4];
        v.x += bv.x; v.y += bv.y; v.z += bv.z; v.w += bv.w;
        *(float4*)&y[(size_t)(row0 + r)*CC + ct*128 + c4] = v;
    }
}

// ---------------- launch ----------------
extern "C" void kernel_launch(void* const* d_in, const int* in_sizes, int n_in,
                              void* d_out, int out_size) {
    const float* x    = (const float*)d_in[0];
    const float* Wfx  = (const float*)d_in[1];
    const float* bfx  = (const float*)d_in[2];
    const float* Wx   = (const float*)d_in[3];
    const float* bx   = (const float*)d_in[4];
    const float* Wsl  = (const float*)d_in[5];
    const float* bsl  = (const float*)d_in[6];
    const float* temp = (const float*)d_in[7];
    const float* Wq   = (const float*)d_in[8];
    const float* Wk   = (const float*)d_in[9];
    const float* Wv   = (const float*)d_in[10];
    const float* Wout = (const float*)d_in[11];
    const float* bout = (const float*)d_in[12];
    float* y = (float*)d_out;

    cudaFuncSetAttribute(k_proj,  cudaFuncAttributeMaxDynamicSharedMemorySize, GSMEM);
    cudaFuncSetAttribute(k_poolg, cudaFuncAttributeMaxDynamicSharedMemorySize, PGSMEM);
    cudaFuncSetAttribute(k_out,   cudaFuncAttributeMaxDynamicSharedMemorySize, GSMEM);

    k_zero<<<2048, 256>>>();
    k_prep<<<CC, 512>>>(Wx, bx, Wsl, bsl);
    k_split<<<dim3(TOK/64, 4), 256>>>(x);
    k_proj<<<dim3(4, TOK/128), 256, GSMEM>>>(temp);
    k_poolg<<<dim3(32, 16, 2), 256, PGSMEM>>>();
    k_stat<<<32, 256>>>(Wfx, bfx, Wq, Wk, Wv);
    k_weff<<<2048, 256>>>(Wout);
    k_out<<<dim3(2, TOK/128), 256, GSMEM>>>(bout, y);
}

// round 14
// speedup vs baseline: 1.4867x; 1.0201x over previous
#include <cuda_runtime.h>
#include <cuda_fp16.h>
#include <cstdint>

#define BB 4
#define NTOK 32768
#define CC 256
#define HH 8
#define DD 64
#define GG 64
#define INNER 512
#define TOK (BB*NTOK)   // 131072

// ---------------- scratch (device globals; no runtime allocation) ----------------
__device__ __align__(16) __half g_x_hi[(size_t)TOK*CC];      // x fp16 hi [tok][c]
__device__ __align__(16) __half g_xT_hi[(size_t)BB*CC*NTOK]; // x^T hi [b][c][n]
__device__ __align__(16) __half g_xT_lo[(size_t)BB*CC*NTOK]; // x^T lo
__device__ __align__(16) __half g_w_hi[(size_t)TOK*INNER];   // slice weights fp16 [tok][hg]
__device__ __align__(16) __half g_wslT_hi[INNER*CC];         // (Wx@Wslice)^T hi
__device__ __align__(16) __half g_wslT_lo[INNER*CC];         // lo
__device__ float g_bsl[INNER];                    // folded slice bias
__device__ float g_P[BB*HH*GG*CC];                // pooled P[bh][g][c] (atomic accum)
__device__ float g_norm[BB*HH*GG];                // weight column sums
__device__ float g_os[BB*HH*GG*DD];               // out_slice
__device__ __align__(16) __half g_weffT_hi[BB*CC*INNER];     // W_eff^T hi [b][c][hg]
__device__ __align__(16) __half g_weffT_lo[BB*CC*INNER];     // lo

// ============================ helpers ============================
#define DINLINE __device__ __forceinline__

DINLINE uint32_t smem_u32(const void* p) {
    uint32_t a;
    asm("{ .reg .u64 t; cvta.to.shared.u64 t, %1; cvt.u32.u64 %0, t; }" : "=r"(a) : "l"(p));
    return a;
}
DINLINE void cpa16(uint32_t dst, const void* src) {
    asm volatile("cp.async.cg.shared.global [%0], [%1], 16;" :: "r"(dst), "l"(src));
}
#define CP_COMMIT() asm volatile("cp.async.commit_group;" ::: "memory")
#define CP_WAIT2()  asm volatile("cp.async.wait_group 2;" ::: "memory")
#define CP_WAIT1()  asm volatile("cp.async.wait_group 1;" ::: "memory")
#define CP_WAIT0()  asm volatile("cp.async.wait_group 0;" ::: "memory")

DINLINE void ldsm4(uint32_t* r, uint32_t addr) {
    asm volatile("ldmatrix.sync.aligned.m8n8.x4.shared.b16 {%0,%1,%2,%3}, [%4];"
        : "=r"(r[0]), "=r"(r[1]), "=r"(r[2]), "=r"(r[3]) : "r"(addr));
}
DINLINE void ldsm4t(uint32_t* r, uint32_t addr) {
    asm volatile("ldmatrix.sync.aligned.m8n8.x4.trans.shared.b16 {%0,%1,%2,%3}, [%4];"
        : "=r"(r[0]), "=r"(r[1]), "=r"(r[2]), "=r"(r[3]) : "r"(addr));
}
DINLINE void mma_f16(float* d, uint32_t a0, uint32_t a1, uint32_t a2, uint32_t a3,
                     uint32_t b0, uint32_t b1) {
    asm volatile("mma.sync.aligned.m16n8k16.row.col.f32.f16.f16.f32 "
        "{%0,%1,%2,%3}, {%4,%5,%6,%7}, {%8,%9}, {%0,%1,%2,%3};"
        : "+f"(d[0]), "+f"(d[1]), "+f"(d[2]), "+f"(d[3])
        : "r"(a0), "r"(a1), "r"(a2), "r"(a3), "r"(b0), "r"(b1));
}
DINLINE uint32_t pack_h2(float a, float b) {
    __half2 h = __floats2half2_rn(a, b);
    return *reinterpret_cast<uint32_t*>(&h);
}
#define SWZ(off) ((off) ^ (((off) >> 3) & 0x70))
#define STG 132        // stage row stride (floats)
#define GSMEM 98304    // 3 stages x (16KB A + 16KB B)
#define PGSMEM 98304   // 4 stages x (8KB A + 16KB B)

// ---------------- zero accumulators (must run every graph replay) ----------------
__global__ void k_zero() {
    int i = blockIdx.x * blockDim.x + threadIdx.x;
    if (i < BB*HH*GG*CC) g_P[i] = 0.f;
    if (i < BB*HH*GG)    g_norm[i] = 0.f;
}

// ---------------- split x into fp16 hi ([tok][c]) and hi/lo transposed ----------------
__global__ void k_split(const float* __restrict__ x) {
    __shared__ uint16_t shi[64][68], slo[64][68];
    int tid = threadIdx.x;
    size_t t0 = (size_t)blockIdx.x * 64;     // token tile
    int c0 = blockIdx.y * 64;                // c tile
    int r = tid >> 2, cq = (tid & 3) * 16;
    #pragma unroll
    for (int j = 0; j < 16; j += 4) {
        float4 v = *(const float4*)&x[(t0 + r) * CC + c0 + cq + j];
        __half hx = __float2half_rn(v.x), hy = __float2half_rn(v.y);
        __half hz = __float2half_rn(v.z), hw = __float2half_rn(v.w);
        uint2 uh, ul;
        uh.x = pack_h2(v.x, v.y);
        uh.y = pack_h2(v.z, v.w);
        ul.x = pack_h2(v.x - __half2float(hx), v.y - __half2float(hy));
        ul.y = pack_h2(v.z - __half2float(hz), v.w - __half2float(hw));
        *(uint2*)&g_x_hi[(t0 + r) * CC + c0 + cq + j] = uh;
        *(uint2*)&shi[r][cq + j] = uh;
        *(uint2*)&slo[r][cq + j] = ul;
    }
    __syncthreads();
    int c = tid >> 2, tq = (tid & 3) * 16;
    size_t b = t0 >> 15;                 // /NTOK
    size_t nloc = t0 & (NTOK - 1);
    size_t base = ((size_t)b * CC + c0 + c) * NTOK + nloc + tq;
    #pragma unroll
    for (int j = 0; j < 16; j += 2) {
        uint32_t hv = (uint32_t)shi[tq + j][c] | ((uint32_t)shi[tq + j + 1][c] << 16);
        uint32_t lv = (uint32_t)slo[tq + j][c] | ((uint32_t)slo[tq + j + 1][c] << 16);
        *(uint32_t*)&g_xT_hi[base + j] = hv;
        *(uint32_t*)&g_xT_lo[base + j] = lv;
    }
}

// ---------------- fold + transpose + fp16-split slice weight ----------------
__global__ void k_prep(const float* __restrict__ Wx, const float* __restrict__ bx,
                       const float* __restrict__ Wsl, const float* __restrict__ bsl) {
    int c = blockIdx.x;        // K index 0..255
    int o = threadIdx.x;       // N index 0..511
    int h = o >> 6, gg = o & 63;
    float s = 0.f;
    #pragma unroll 16
    for (int d = 0; d < 64; d++)
        s += Wx[c*INNER + h*64 + d] * Wsl[d*64 + gg];
    __half sh = __float2half_rn(s);
    g_wslT_hi[o*CC + c] = sh;
    g_wslT_lo[o*CC + c] = __float2half_rn(s - __half2float(sh));
    if (c == 0) {
        float t = 0.f;
        #pragma unroll 16
        for (int d = 0; d < 64; d++) t += bx[h*64 + d] * Wsl[d*64 + gg];
        g_bsl[o] = t + bsl[gg];
    }
}

// ---------------- slice-logits GEMM + softmax (mma.sync, fp16 2-seg) ----------------
// block M128 x N128, K=256 x 2 segments (8 chunks of 64): xhi*Bhi + xhi*Blo.
// grid (4, 1024).
__global__ __launch_bounds__(256, 2) void k_proj(const float* __restrict__ temp) {
    extern __shared__ char sm[];
    float* stage = (float*)sm;
    uint32_t sb = smem_u32(sm);
    int tid = threadIdx.x;
    int lane = tid & 31, w = tid >> 5;
    int wm = w & 1, wn = w >> 1;
    int tileM = blockIdx.y, y2 = blockIdx.x;
    int row0 = tileM * 128;
    int b = tileM >> 8;

    float acc[4][4][4];
    #pragma unroll
    for (int a = 0; a < 4; a++)
        #pragma unroll
        for (int b2 = 0; b2 < 4; b2++)
            #pragma unroll
            for (int d = 0; d < 4; d++) acc[a][b2][d] = 0.f;

    auto issue = [&](int c) {
        int p = c % 3, seg = c >> 2, k0 = (c & 3) * 64;
        const __half* Bs = (seg == 1) ? g_wslT_lo : g_wslT_hi;
        #pragma unroll
        for (int i = 0; i < 4; i++) {
            int id = tid + i * 256, r = id >> 3, c8 = (id & 7) * 8;
            cpa16(sb + p*32768 + SWZ((uint32_t)(r*128 + c8*2)),
                  g_x_hi + (size_t)(row0 + r) * CC + k0 + c8);
        }
        #pragma unroll
        for (int i = 0; i < 4; i++) {
            int id = tid + i * 256, r = id >> 3, c8 = (id & 7) * 8;
            cpa16(sb + p*32768 + 16384 + SWZ((uint32_t)(r*128 + c8*2)),
                  Bs + (size_t)(y2*128 + r) * CC + k0 + c8);
        }
        CP_COMMIT();
    };

    issue(0); issue(1);
    for (int c = 0; c < 8; c++) {
        if (c + 1 < 8) CP_WAIT1(); else CP_WAIT0();
        __syncthreads();
        uint32_t ab = sb + (c % 3) * 32768;
        uint32_t bb = ab + 16384;
        int rA = lane & 15;
        #pragma unroll
        for (int kk = 0; kk < 4; kk++) {
            uint32_t af[4][4], bf[2][4];
            int kc = kk * 16 + (lane >> 4) * 8;
            #pragma unroll
            for (int mi = 0; mi < 4; mi++)
                ldsm4(af[mi], ab + SWZ((uint32_t)((wm*64 + mi*16 + rA)*128 + kc*2)));
            #pragma unroll
            for (int s = 0; s < 2; s++)
                ldsm4(bf[s], bb + SWZ((uint32_t)((wn*32 + s*16 + rA)*128 + kc*2)));
            #pragma unroll
            for (int mi = 0; mi < 4; mi++)
                #pragma unroll
                for (int nj = 0; nj < 4; nj++)
                    mma_f16(acc[mi][nj], af[mi][0], af[mi][1], af[mi][2], af[mi][3],
                            bf[nj>>1][nj&1], bf[nj>>1][(nj&1)+2]);
        }
        if (c + 2 < 8) issue(c + 2);
    }
    __syncthreads();

    // frags -> stage
    #pragma unroll
    for (int mi = 0; mi < 4; mi++)
        #pragma unroll
        for (int nj = 0; nj < 4; nj++) {
            int row = wm*64 + mi*16 + (lane >> 2);
            int col = wn*32 + nj*8 + (lane & 3)*2;
            *(float2*)&stage[row*STG + col]     = make_float2(acc[mi][nj][0], acc[mi][nj][1]);
            *(float2*)&stage[(row+8)*STG + col] = make_float2(acc[mi][nj][2], acc[mi][nj][3]);
        }
    __syncthreads();

    // softmax over each head's 64 cols per row
    float rt0 = 1.0f / fminf(fmaxf(temp[y2*2 + 0], 0.1f), 5.0f);
    float rt1 = 1.0f / fminf(fmaxf(temp[y2*2 + 1], 0.1f), 5.0f);
    for (int gi = 0; gi < 32; gi++) {
        int G = w * 32 + gi;
        int r = G >> 1, hh = G & 1;
        float bb0 = g_bsl[y2*128 + hh*64 + lane];
        float bb1 = g_bsl[y2*128 + hh*64 + 32 + lane];
        float rt = hh ? rt1 : rt0;
        float v0 = (stage[r*STG + hh*64 + lane]      + bb0) * rt;
        float v1 = (stage[r*STG + hh*64 + 32 + lane] + bb1) * rt;
        float m = fmaxf(v0, v1);
        #pragma unroll
        for (int o = 16; o; o >>= 1) m = fmaxf(m, __shfl_xor_sync(0xFFFFFFFFu, m, o));
        float e0 = __expf(v0 - m), e1 = __expf(v1 - m);
        float s = e0 + e1;
        #pragma unroll
        for (int o = 16; o; o >>= 1) s += __shfl_xor_sync(0xFFFFFFFFu, s, o);
        float rs = 1.0f / s;
        stage[r*STG + hh*64 + lane]      = e0 * rs;
        stage[r*STG + hh*64 + 32 + lane] = e1 * rs;
    }
    __syncthreads();

    // (a) norm: column sums -> atomic
    if (tid < 128) {
        float s = 0.f;
        #pragma unroll 8
        for (int r = 0; r < 128; r++) s += stage[r*STG + tid];
        int head = tid >> 6, g = tid & 63;
        atomicAdd(&g_norm[(b*8 + y2*2 + head)*64 + g], s);
    }
    // (b) w fp16 [tok][hg]  (coalesced 8B chunks) — sole w output now
    #pragma unroll
    for (int i = 0; i < 16; i++) {
        int lin = tid + i * 256, r = lin >> 5, c4 = (lin & 31) * 4;
        float4 v = *(float4*)&stage[r*STG + c4];
        uint2 uh;
        uh.x = pack_h2(v.x, v.y);
        uh.y = pack_h2(v.z, v.w);
        *(uint2*)&g_w_hi[(size_t)(row0 + r)*INNER + y2*128 + c4] = uh;
    }
}

// ---------------- pooling GEMM: P[bh][g][c] = sum_n w[n,g]*x[n,c] ----------------
// block M64(g) x N128(c), grid (32 bh, 2 cb, 16 kc). 64 chunks (2 segs x 32).
// A = g_w_hi K-major via ldmatrix.trans (wT tensor eliminated).
__global__ __launch_bounds__(256, 2) void k_poolg() {
    extern __shared__ char sm[];
    uint32_t sb = smem_u32(sm);
    int tid = threadIdx.x;
    int lane = tid & 31, w = tid >> 5;
    int wm = w & 1, wn = w >> 1;
    int bh = blockIdx.x, cb = blockIdx.y, kc = blockIdx.z;
    int b = bh >> 3, h = bh & 7;
    size_t nbase = (size_t)kc * 2048;
    const __half* Aw  = g_w_hi + ((size_t)b * NTOK + nbase) * INNER + h * 64;
    const __half* Bhi = g_xT_hi + ((size_t)b * CC + cb * 128) * NTOK;
    const __half* Blo = g_xT_lo + ((size_t)b * CC + cb * 128) * NTOK;

    float acc[2][4][4];
    #pragma unroll
    for (int a = 0; a < 2; a++)
        #pragma unroll
        for (int b2 = 0; b2 < 4; b2++)
            #pragma unroll
            for (int d = 0; d < 4; d++) acc[a][b2][d] = 0.f;

    auto issue = [&](int c) {
        int p = c & 3, seg = c >> 5, k0 = (c & 31) * 64;
        const __half* Bs = (seg == 1) ? Blo : Bhi;
        // A tile: 64 k-rows (tokens) x 64 g-halves = 8KB, from g_w_hi rows
        #pragma unroll
        for (int i = 0; i < 2; i++) {
            int id = tid + i * 256, r = id >> 3, c8 = (id & 7) * 8;
            cpa16(sb + p*24576 + SWZ((uint32_t)(r*128 + c8*2)),
                  Aw + (size_t)(k0 + r) * INNER + c8);
        }
        #pragma unroll
        for (int i = 0; i < 4; i++) {
            int id = tid + i * 256, r = id >> 3, c8 = (id & 7) * 8;
            cpa16(sb + p*24576 + 8192 + SWZ((uint32_t)(r*128 + c8*2)),
                  Bs + (size_t)r * NTOK + nbase + k0 + c8);
        }
        CP_COMMIT();
    };

    issue(0); issue(1); issue(2);
    // trans-A lane address components
    int klo = (lane & 7) + ((lane >> 4) << 3);     // k-row within 16-chunk
    int mh  = ((lane >> 3) & 1) << 3;              // m col offset 0/8
    for (int c = 0; c < 64; c++) {
        if (c + 2 < 64) CP_WAIT2(); else if (c + 1 < 64) CP_WAIT1(); else CP_WAIT0();
        __syncthreads();
        uint32_t ab = sb + (c & 3) * 24576;
        uint32_t bb = ab + 8192;
        int rA = lane & 15;
        #pragma unroll
        for (int kk = 0; kk < 4; kk++) {
            uint32_t af[2][4], bf[2][4];
            int kc2 = kk * 16 + (lane >> 4) * 8;
            #pragma unroll
            for (int mi = 0; mi < 2; mi++) {
                int krow = kk * 16 + klo;
                int mcol = wm*32 + mi*16 + mh;
                ldsm4t(af[mi], ab + SWZ((uint32_t)(krow*128 + mcol*2)));
            }
            #pragma unroll
            for (int s = 0; s < 2; s++)
                ldsm4(bf[s], bb + SWZ((uint32_t)((wn*32 + s*16 + rA)*128 + kc2*2)));
            #pragma unroll
            for (int mi = 0; mi < 2; mi++)
                #pragma unroll
                for (int nj = 0; nj < 4; nj++)
                    mma_f16(acc[mi][nj], af[mi][0], af[mi][1], af[mi][2], af[mi][3],
                            bf[nj>>1][nj&1], bf[nj>>1][(nj&1)+2]);
        }
        if (c + 3 < 64) issue(c + 3);
    }

    #pragma unroll
    for (int mi = 0; mi < 2; mi++)
        #pragma unroll
        for (int nj = 0; nj < 4; nj++) {
            int row = wm*32 + mi*16 + (lane >> 2);
            int col = cb*128 + wn*32 + nj*8 + (lane & 3)*2;
            int base = bh*16384 + row*256 + col;
            atomicAdd(&g_P[base],            acc[mi][nj][0]);
            atomicAdd(&g_P[base + 1],        acc[mi][nj][1]);
            atomicAdd(&g_P[base + 8*256],    acc[mi][nj][2]);
            atomicAdd(&g_P[base + 8*256 + 1],acc[mi][nj][3]);
        }
}

// ---------------- fused: ST = P@Wfx + bfx*norm ; tiny attention -> g_os ----------------
__global__ void k_stat(const float* __restrict__ Wfx, const float* __restrict__ bfx,
                       const float* __restrict__ Wq, const float* __restrict__ Wk,
                       const float* __restrict__ Wv) {
    int bh = blockIdx.x;
    int h = bh & 7;
    int tid = threadIdx.x;
    __shared__ float bufA[64][65], bufB[64][65];
    __shared__ float nrmc[64];

    float acc[16];
    #pragma unroll
    for (int j = 0; j < 16; j++) acc[j] = 0.f;
    int g = tid >> 2, dq = tid & 3;
    for (int c0 = 0; c0 < 4; c0++) {
        #pragma unroll
        for (int i = 0; i < 16; i++) {
            int id = tid + i * 256;
            int r = id >> 6, cl = id & 63;
            bufA[r][cl] = Wfx[(c0*64 + r) * INNER + h*64 + cl];
            bufB[r][cl] = g_P[bh*16384 + r*256 + c0*64 + cl];
        }
        __syncthreads();
        for (int cl = 0; cl < 64; cl++) {
            float pv = bufB[g][cl];
            #pragma unroll
            for (int j = 0; j < 16; j++)
                acc[j] += pv * bufA[cl][dq*16 + j];
        }
        __syncthreads();
    }
    if (tid < 64) nrmc[tid] = g_norm[bh*64 + tid];
    __syncthreads();
    {
        float nrm = nrmc[g];
        float rdiv = 1.0f / (nrm + 1e-5f);
        #pragma unroll
        for (int j = 0; j < 16; j++) {
            int d = dq*16 + j;
            bufA[g][d] = (acc[j] + bfx[h*64 + d] * nrm) * rdiv;
        }
    }
    __syncthreads();

    #pragma unroll
    for (int it = 0; it < 16; it++) {
        int idx = tid + it * 256;
        int g2 = idx >> 6, d2 = idx & 63;
        float s0 = 0, s1 = 0, s2 = 0, s3 = 0;
        #pragma unroll
        for (int d = 0; d < 64; d += 4) {
            s0 += bufA[g2][d]   * Wk[(d)   * 64 + d2];
            s1 += bufA[g2][d+1] * Wk[(d+1) * 64 + d2];
            s2 += bufA[g2][d+2] * Wk[(d+2) * 64 + d2];
            s3 += bufA[g2][d+3] * Wk[(d+3) * 64 + d2];
        }
        bufB[g2][d2] = (s0 + s1) + (s2 + s3);
    }
    __syncthreads();
    float tv[64];
    if (tid < 64) {
        int g2 = tid;
        float q[64];
        #pragma unroll
        for (int d2 = 0; d2 < 64; d2++) {
            float s0 = 0, s1 = 0, s2 = 0, s3 = 0;
            #pragma unroll
            for (int d = 0; d < 64; d += 4) {
                s0 += bufA[g2][d]   * Wq[(d)   * 64 + d2];
                s1 += bufA[g2][d+1] * Wq[(d+1) * 64 + d2];
                s2 += bufA[g2][d+2] * Wq[(d+2) * 64 + d2];
                s3 += bufA[g2][d+3] * Wq[(d+3) * 64 + d2];
            }
            q[d2] = (s0 + s1) + (s2 + s3);
        }
        float p[64];
        float mx = -1e30f;
        #pragma unroll
        for (int j = 0; j < 64; j++) {
            float s0 = 0, s1 = 0, s2 = 0, s3 = 0;
            #pragma unroll
            for (int d = 0; d < 64; d += 4) {
                s0 += q[d]   * bufB[j][d];
                s1 += q[d+1] * bufB[j][d+1];
                s2 += q[d+2] * bufB[j][d+2];
                s3 += q[d+3] * bufB[j][d+3];
            }
            float s = ((s0 + s1) + (s2 + s3)) * 0.125f;
            p[j] = s;
            mx = fmaxf(mx, s);
        }
        float sum = 0.f;
        #pragma unroll
        for (int j = 0; j < 64; j++) { p[j] = __expf(p[j] - mx); sum += p[j]; }
        float rs = 1.0f / sum;
        #pragma unroll
        for (int e = 0; e < 64; e++) {
            float s0 = 0, s1 = 0, s2 = 0, s3 = 0;
            #pragma unroll
            for (int j = 0; j < 64; j += 4) {
                s0 += p[j]   * bufA[j][e];
                s1 += p[j+1] * bufA[j+1][e];
                s2 += p[j+2] * bufA[j+2][e];
                s3 += p[j+3] * bufA[j+3][e];
            }
            tv[e] = ((s0 + s1) + (s2 + s3)) * rs;
        }
    }
    __syncthreads();
    if (tid < 64) {
        #pragma unroll
        for (int e = 0; e < 64; e++) bufB[tid][e] = tv[e];
    }
    __syncthreads();
    #pragma unroll
    for (int it = 0; it < 16; it++) {
        int idx = tid + it * 256;
        int g2 = idx >> 6, d2 = idx & 63;
        float s0 = 0, s1 = 0, s2 = 0, s3 = 0;
        #pragma unroll
        for (int e = 0; e < 64; e += 4) {
            s0 += bufB[g2][e]   * Wv[(e)   * 64 + d2];
            s1 += bufB[g2][e+1] * Wv[(e+1) * 64 + d2];
            s2 += bufB[g2][e+2] * Wv[(e+2) * 64 + d2];
            s3 += bufB[g2][e+3] * Wv[(e+3) * 64 + d2];
        }
        g_os[bh * 4096 + idx] = (s0 + s1) + (s2 + s3);
    }
}

// ---------------- fold out_slice into W_out: W_eff^T fp16 pair [b][c][hg] ----------------
__global__ void k_weff(const float* __restrict__ Wout) {
    int blk = blockIdx.x;           // b*512 + row
    int b = blk >> 9;
    int row = blk & 511;            // k index: h*64+g
    int h = row >> 6;
    int tid = threadIdx.x;          // n index = c (256)
    __shared__ float osr[64];
    if (tid < 64) osr[tid] = g_os[(b*8 + h) * 4096 + (row & 63) * 64 + tid];
    __syncthreads();
    float s = 0.f;
    #pragma unroll 16
    for (int d = 0; d < 64; d++)
        s += osr[d] * Wout[(h*64 + d) * CC + tid];
    __half sh = __float2half_rn(s);
    size_t idx = (size_t)b * (CC*INNER) + (size_t)tid * INNER + row;
    g_weffT_hi[idx] = sh;
    g_weffT_lo[idx] = __float2half_rn(s - __half2float(sh));
}

// ---------------- output GEMM: y = w @ W_eff[b] + b_out (fp16 2-seg) ----------------
// block M128 x N128, K=512 x 2 segments (16 chunks). grid (2, 1024): ct fast-varying.
__global__ __launch_bounds__(256, 2) void k_out(const float* __restrict__ bout,
                                                float* __restrict__ y) {
    extern __shared__ char sm[];
    float* stage = (float*)sm;
    uint32_t sb = smem_u32(sm);
    int tid = threadIdx.x;
    int lane = tid & 31, w = tid >> 5;
    int wm = w & 1, wn = w >> 1;
    int tileM = blockIdx.y, ct = blockIdx.x;
    int row0 = tileM * 128;
    int b = tileM >> 8;

    float acc[4][4][4];
    #pragma unroll
    for (int a = 0; a < 4; a++)
        #pragma unroll
        for (int bb2 = 0; bb2 < 4; bb2++)
            #pragma unroll
            for (int d = 0; d < 4; d++) acc[a][bb2][d] = 0.f;

    auto issue = [&](int c) {
        int p = c % 3, seg = c >> 3, k0 = (c & 7) * 64;
        const __half* Bs = (seg == 1) ? g_weffT_lo : g_weffT_hi;
        #pragma unroll
        for (int i = 0; i < 4; i++) {
            int id = tid + i * 256, r = id >> 3, c8 = (id & 7) * 8;
            cpa16(sb + p*32768 + SWZ((uint32_t)(r*128 + c8*2)),
                  g_w_hi + (size_t)(row0 + r) * INNER + k0 + c8);
        }
        #pragma unroll
        for (int i = 0; i < 4; i++) {
            int id = tid + i * 256, r = id >> 3, c8 = (id & 7) * 8;
            cpa16(sb + p*32768 + 16384 + SWZ((uint32_t)(r*128 + c8*2)),
                  Bs + (size_t)b * (CC*INNER) + (size_t)(ct*128 + r) * INNER + k0 + c8);
        }
        CP_COMMIT();
    };

    issue(0); issue(1);
    for (int c = 0; c < 16; c++) {
        if (c + 1 < 16) CP_WAIT1(); else CP_WAIT0();
        __syncthreads();
        uint32_t ab = sb + (c % 3) * 32768;
        uint32_t bbs = ab + 16384;
        int rA = lane & 15;
        #pragma unroll
        for (int kk = 0; kk < 4; kk++) {
            uint32_t af[4][4], bf[2][4];
            int kc = kk * 16 + (lane >> 4) * 8;
            #pragma unroll
            for (int mi = 0; mi < 4; mi++)
                ldsm4(af[mi], ab + SWZ((uint32_t)((wm*64 + mi*16 + rA)*128 + kc*2)));
            #pragma unroll
            for (int s = 0; s < 2; s++)
                ldsm4(bf[s], bbs + SWZ((uint32_t)((wn*32 + s*16 + rA)*128 + kc*2)));
            #pragma unroll
            for (int mi = 0; mi < 4; mi++)
                #pragma unroll
                for (int nj = 0; nj < 4; nj++)
                    mma_f16(acc[mi][nj], af[mi][0], af[mi][1], af[mi][2], af[mi][3],
                            bf[nj>>1][nj&1], bf[nj>>1][(nj&1)+2]);
        }
        if (c + 2 < 16) issue(c + 2);
    }
    __syncthreads();

    #pragma unroll
    for (int mi = 0; mi < 4; mi++)
        #pragma unroll
        for (int nj = 0; nj < 4; nj++) {
            int row = wm*64 + mi*16 + (lane >> 2);
            int col = wn*32 + nj*8 + (lane & 3)*2;
            *(float2*)&stage[row*STG + col]     = make_float2(acc[mi][nj][0], acc[mi][nj][1]);
            *(float2*)&stage[(row+8)*STG + col] = make_float2(acc[mi][nj][2], acc[mi][nj][3]);
        }
    __syncthreads();
    #pragma unroll
    for (int i = 0; i < 16; i++) {
        int lin = tid + i * 256, r = lin >> 5, c4 = (lin & 31) * 4;
        float4 v = *(float4*)&stage[r*STG + c4];
        float4 bv = *(const float4*)&bout[ct*128 + c4];
        v.x += bv.x; v.y += bv.y; v.z += bv.z; v.w += bv.w;
        *(float4*)&y[(size_t)(row0 + r)*CC + ct*128 + c4] = v;
    }
}

// ---------------- launch ----------------
extern "C" void kernel_launch(void* const* d_in, const int* in_sizes, int n_in,
                              void* d_out, int out_size) {
    const float* x    = (const float*)d_in[0];
    const float* Wfx  = (const float*)d_in[1];
    const float* bfx  = (const float*)d_in[2];
    const float* Wx   = (const float*)d_in[3];
    const float* bx   = (const float*)d_in[4];
    const float* Wsl  = (const float*)d_in[5];
    const float* bsl  = (const float*)d_in[6];
    const float* temp = (const float*)d_in[7];
    const float* Wq   = (const float*)d_in[8];
    const float* Wk   = (const float*)d_in[9];
    const float* Wv   = (const float*)d_in[10];
    const float* Wout = (const float*)d_in[11];
    const float* bout = (const float*)d_in[12];
    float* y = (float*)d_out;

    cudaFuncSetAttribute(k_proj,  cudaFuncAttributeMaxDynamicSharedMemorySize, GSMEM);
    cudaFuncSetAttribute(k_poolg, cudaFuncAttributeMaxDynamicSharedMemorySize, PGSMEM);
    cudaFuncSetAttribute(k_out,   cudaFuncAttributeMaxDynamicSharedMemorySize, GSMEM);

    k_zero<<<2048, 256>>>();
    k_prep<<<CC, 512>>>(Wx, bx, Wsl, bsl);
    k_split<<<dim3(TOK/64, 4), 256>>>(x);
    k_proj<<<dim3(4, TOK/128), 256, GSMEM>>>(temp);
    k_poolg<<<dim3(32, 2, 16), 256, PGSMEM>>>();
    k_stat<<<32, 256>>>(Wfx, bfx, Wq, Wk, Wv);
    k_weff<<<2048, 256>>>(Wout);
    k_out<<<dim3(2, TOK/128), 256, GSMEM>>>(bout, y);
}